// round 2
// baseline (speedup 1.0000x reference)
#include <cuda_runtime.h>
#include <cuda_bf16.h>
#include <math.h>

// ---------------------------------------------------------------------------
// DecoderLayer: B=2, S=2048, E=2048, NH=16, NKV=4, HD=128, FF=5632
// Round 0: correct fp32 baseline. Tiled SGEMM (64x64x16) + flash attention.
// ---------------------------------------------------------------------------

#define B_    2
#define S_    2048
#define E_    2048
#define NH_   16
#define NKV_  4
#define HD_   128
#define FF_   5632
#define T_    (B_ * S_)            // 4096 tokens
#define QKV_N ((NH_ + 2 * NKV_) * HD_)  // 3072

// scratch (device globals; allocation-free)
__device__ float g_hnorm[(size_t)T_ * E_];
__device__ float g_qkv  [(size_t)T_ * QKV_N];
__device__ float g_q    [(size_t)B_ * NH_  * S_ * HD_];
__device__ float g_kbuf [(size_t)B_ * NKV_ * S_ * HD_];
__device__ float g_vbuf [(size_t)B_ * NKV_ * S_ * HD_];
__device__ float g_attn [(size_t)T_ * E_];
__device__ float g_h    [(size_t)T_ * E_];
__device__ float g_ffh  [(size_t)T_ * FF_];

// ---------------------------------------------------------------------------
// RMSNorm: one block per row of 2048
// ---------------------------------------------------------------------------
__global__ void __launch_bounds__(256) rmsnorm_k(const float* __restrict__ x,
                                                 const float* __restrict__ w,
                                                 float* __restrict__ o) {
    size_t base = (size_t)blockIdx.x * E_;
    int tid = threadIdx.x;
    float4 v0 = *(const float4*)(x + base + tid * 4);
    float4 v1 = *(const float4*)(x + base + 1024 + tid * 4);
    float ss = v0.x*v0.x + v0.y*v0.y + v0.z*v0.z + v0.w*v0.w
             + v1.x*v1.x + v1.y*v1.y + v1.z*v1.z + v1.w*v1.w;
    #pragma unroll
    for (int off = 16; off; off >>= 1) ss += __shfl_xor_sync(0xffffffffu, ss, off);
    __shared__ float ws[8];
    if ((tid & 31) == 0) ws[tid >> 5] = ss;
    __syncthreads();
    float tot = ws[0] + ws[1] + ws[2] + ws[3] + ws[4] + ws[5] + ws[6] + ws[7];
    float sc = rsqrtf(tot * (1.0f / E_) + 1e-5f);
    float4 w0 = *(const float4*)(w + tid * 4);
    float4 w1w = *(const float4*)(w + 1024 + tid * 4);
    float4 r0 = make_float4(v0.x*sc*w0.x,  v0.y*sc*w0.y,  v0.z*sc*w0.z,  v0.w*sc*w0.w);
    float4 r1 = make_float4(v1.x*sc*w1w.x, v1.y*sc*w1w.y, v1.z*sc*w1w.z, v1.w*sc*w1w.w);
    *(float4*)(o + base + tid * 4)        = r0;
    *(float4*)(o + base + 1024 + tid * 4) = r1;
}

// ---------------------------------------------------------------------------
// GEMM: C[M,N] = A[M,K] * B[N,K]^T  (both K-major), tile 64x64x16, 256 thr.
// MODE 0: C = A·B^T
// MODE 1: C = R + A·B^T          (residual)
// MODE 2: C = silu(A·B^T) * (A·B2^T)
// ---------------------------------------------------------------------------
#define SSTR 68   // padded smem row stride (floats), 272B = 16B aligned

template <int MODE>
__global__ void __launch_bounds__(256) gemm_k(const float* __restrict__ A,
                                              const float* __restrict__ Bm,
                                              const float* __restrict__ B2,
                                              const float* __restrict__ R,
                                              float* __restrict__ C,
                                              int M, int N, int K) {
    __shared__ float As [16 * SSTR];
    __shared__ float Bs [16 * SSTR];
    __shared__ float B2s[16 * SSTR];

    int tid = threadIdx.x;
    int tx = tid & 15, ty = tid >> 4;
    int m0 = blockIdx.y * 64, n0 = blockIdx.x * 64;

    int lr = tid >> 2;          // 0..63 row within tile
    int lk = (tid & 3) * 4;     // 0,4,8,12 k offset

    const float* Ap  = A  + (size_t)(m0 + lr) * K + lk;
    const float* Bp  = Bm + (size_t)(n0 + lr) * K + lk;
    const float* B2p = (MODE == 2) ? (B2 + (size_t)(n0 + lr) * K + lk) : nullptr;

    float acc[4][4];
    float acc2[4][4];
    #pragma unroll
    for (int i = 0; i < 4; i++)
        #pragma unroll
        for (int j = 0; j < 4; j++) { acc[i][j] = 0.f; acc2[i][j] = 0.f; }

    for (int k0 = 0; k0 < K; k0 += 16) {
        float4 a = *(const float4*)(Ap + k0);
        float4 b = *(const float4*)(Bp + k0);
        As[(lk + 0) * SSTR + lr] = a.x;
        As[(lk + 1) * SSTR + lr] = a.y;
        As[(lk + 2) * SSTR + lr] = a.z;
        As[(lk + 3) * SSTR + lr] = a.w;
        Bs[(lk + 0) * SSTR + lr] = b.x;
        Bs[(lk + 1) * SSTR + lr] = b.y;
        Bs[(lk + 2) * SSTR + lr] = b.z;
        Bs[(lk + 3) * SSTR + lr] = b.w;
        if (MODE == 2) {
            float4 b2 = *(const float4*)(B2p + k0);
            B2s[(lk + 0) * SSTR + lr] = b2.x;
            B2s[(lk + 1) * SSTR + lr] = b2.y;
            B2s[(lk + 2) * SSTR + lr] = b2.z;
            B2s[(lk + 3) * SSTR + lr] = b2.w;
        }
        __syncthreads();
        #pragma unroll
        for (int kk = 0; kk < 16; kk++) {
            float4 av = *(const float4*)&As[kk * SSTR + ty * 4];
            float4 bv = *(const float4*)&Bs[kk * SSTR + tx * 4];
            const float aa[4] = {av.x, av.y, av.z, av.w};
            const float bb[4] = {bv.x, bv.y, bv.z, bv.w};
            #pragma unroll
            for (int i = 0; i < 4; i++)
                #pragma unroll
                for (int j = 0; j < 4; j++)
                    acc[i][j] = fmaf(aa[i], bb[j], acc[i][j]);
            if (MODE == 2) {
                float4 b2v = *(const float4*)&B2s[kk * SSTR + tx * 4];
                const float b2b[4] = {b2v.x, b2v.y, b2v.z, b2v.w};
                #pragma unroll
                for (int i = 0; i < 4; i++)
                    #pragma unroll
                    for (int j = 0; j < 4; j++)
                        acc2[i][j] = fmaf(aa[i], b2b[j], acc2[i][j]);
            }
        }
        __syncthreads();
    }

    #pragma unroll
    for (int i = 0; i < 4; i++) {
        size_t ridx = (size_t)(m0 + ty * 4 + i) * N + n0 + tx * 4;
        float4 res = make_float4(0.f, 0.f, 0.f, 0.f);
        if (MODE == 1) res = *(const float4*)(R + ridx);
        float vv[4];
        const float rr[4] = {res.x, res.y, res.z, res.w};
        #pragma unroll
        for (int j = 0; j < 4; j++) {
            float v = acc[i][j];
            if (MODE == 1) v += rr[j];
            if (MODE == 2) {
                float s = v;
                v = (s / (1.0f + __expf(-s))) * acc2[i][j];
            }
            vv[j] = v;
        }
        *(float4*)(C + ridx) = make_float4(vv[0], vv[1], vv[2], vv[3]);
    }
}

// ---------------------------------------------------------------------------
// RoPE + QKV split into (b, head, s, d) layouts. One block per token.
// ---------------------------------------------------------------------------
__global__ void __launch_bounds__(256) rope_split_k(const float* __restrict__ qkv,
                                                    const float* __restrict__ fc,
                                                    float* __restrict__ q,
                                                    float* __restrict__ k,
                                                    float* __restrict__ v) {
    int t = blockIdx.x;
    int b = t >> 11;      // /2048
    int s = t & 2047;
    const float* row = qkv + (size_t)t * QKV_N;
    const float* f = fc + (size_t)s * HD_;   // (64, 2) pairs
    // Q: 16 heads * 64 pairs
    for (int idx = threadIdx.x; idx < NH_ * 64; idx += 256) {
        int h = idx >> 6, i = idx & 63;
        float x0 = row[h * HD_ + 2 * i];
        float x1 = row[h * HD_ + 2 * i + 1];
        float cs = f[2 * i], sn = f[2 * i + 1];
        size_t o = ((size_t)(b * NH_ + h) * S_ + s) * HD_ + 2 * i;
        q[o]     = x0 * cs - x1 * sn;
        q[o + 1] = x1 * cs + x0 * sn;
    }
    // K: 4 heads * 64 pairs
    for (int idx = threadIdx.x; idx < NKV_ * 64; idx += 256) {
        int h = idx >> 6, i = idx & 63;
        float x0 = row[NH_ * HD_ + h * HD_ + 2 * i];
        float x1 = row[NH_ * HD_ + h * HD_ + 2 * i + 1];
        float cs = f[2 * i], sn = f[2 * i + 1];
        size_t o = ((size_t)(b * NKV_ + h) * S_ + s) * HD_ + 2 * i;
        k[o]     = x0 * cs - x1 * sn;
        k[o + 1] = x1 * cs + x0 * sn;
    }
    // V: straight copy
    for (int idx = threadIdx.x; idx < NKV_ * HD_; idx += 256) {
        int h = idx >> 7, d = idx & 127;
        v[((size_t)(b * NKV_ + h) * S_ + s) * HD_ + d] =
            row[(NH_ + NKV_) * HD_ + idx];
    }
}

// ---------------------------------------------------------------------------
// Flash attention, causal. Block = (64 q rows) x (one head, one batch).
// 256 threads: thread (r = tid/4, c = tid%4); online softmax; K/V share smem.
// ---------------------------------------------------------------------------
#define QSTR 132                       // padded row stride (floats); 528B, 16B aligned
#define PSTR 65
#define ATTN_SMEM ((2 * 64 * QSTR + 64 * PSTR) * 4)

__global__ void __launch_bounds__(256) attn_k(const float* __restrict__ Q,
                                              const float* __restrict__ Kt,
                                              const float* __restrict__ V,
                                              float* __restrict__ O) {
    extern __shared__ float sm[];
    float* Qs  = sm;                    // 64 x QSTR
    float* KVs = sm + 64 * QSTR;        // 64 x QSTR (K then V)
    float* Ps  = sm + 2 * 64 * QSTR;    // 64 x PSTR

    int tid = threadIdx.x;
    int qt = blockIdx.x, hh = blockIdx.y, b = blockIdx.z;
    int q0 = qt * 64;
    const float* Qp = Q  + (size_t)(b * NH_  + hh)        * S_ * HD_;
    const float* Kp = Kt + (size_t)(b * NKV_ + (hh >> 2)) * S_ * HD_;
    const float* Vp = V  + (size_t)(b * NKV_ + (hh >> 2)) * S_ * HD_;

    int r = tid >> 2, c = tid & 3;
    int qi = q0 + r;

    // load Q tile
    for (int idx = tid; idx < 64 * 32; idx += 256) {
        int row = idx >> 5, d4 = idx & 31;
        *(float4*)&Qs[row * QSTR + d4 * 4] =
            *(const float4*)(Qp + (size_t)(q0 + row) * HD_ + d4 * 4);
    }

    float o[32];
    #pragma unroll
    for (int d = 0; d < 32; d++) o[d] = 0.f;
    float m = -1e30f, l = 0.f;
    const float scale = 0.022097086912079608f;  // 1/sqrt(2048) (ref scales by sqrt(EMBED))

    for (int kt = 0; kt <= qt; kt++) {
        int k0 = kt * 64;
        // load K tile
        for (int idx = tid; idx < 64 * 32; idx += 256) {
            int row = idx >> 5, d4 = idx & 31;
            *(float4*)&KVs[row * QSTR + d4 * 4] =
                *(const float4*)(Kp + (size_t)(k0 + row) * HD_ + d4 * 4);
        }
        __syncthreads();

        // scores: 16 columns per thread
        float acc[16];
        #pragma unroll
        for (int jj = 0; jj < 16; jj++) acc[jj] = 0.f;
        #pragma unroll 4
        for (int d4 = 0; d4 < 32; d4++) {
            float4 qv = *(const float4*)&Qs[r * QSTR + d4 * 4];
            #pragma unroll
            for (int jj = 0; jj < 16; jj++) {
                float4 kv = *(const float4*)&KVs[(c * 16 + jj) * QSTR + d4 * 4];
                acc[jj] = fmaf(qv.x, kv.x, acc[jj]);
                acc[jj] = fmaf(qv.y, kv.y, acc[jj]);
                acc[jj] = fmaf(qv.z, kv.z, acc[jj]);
                acc[jj] = fmaf(qv.w, kv.w, acc[jj]);
            }
        }

        float mt = -1e30f;
        #pragma unroll
        for (int jj = 0; jj < 16; jj++) {
            float s = acc[jj] * scale;
            if (k0 + c * 16 + jj > qi) s = -1e30f;   // causal mask
            acc[jj] = s;
            mt = fmaxf(mt, s);
        }
        mt = fmaxf(mt, __shfl_xor_sync(0xffffffffu, mt, 1));
        mt = fmaxf(mt, __shfl_xor_sync(0xffffffffu, mt, 2));
        float mnew = fmaxf(m, mt);
        float fac = __expf(m - mnew);
        float ls = 0.f;
        #pragma unroll
        for (int jj = 0; jj < 16; jj++) {
            float p = __expf(acc[jj] - mnew);
            ls += p;
            Ps[r * PSTR + c * 16 + jj] = p;
        }
        ls += __shfl_xor_sync(0xffffffffu, ls, 1);
        ls += __shfl_xor_sync(0xffffffffu, ls, 2);
        l = l * fac + ls;
        m = mnew;
        #pragma unroll
        for (int d = 0; d < 32; d++) o[d] *= fac;
        __syncthreads();   // K reads + Ps writes done

        // load V tile into same buffer
        for (int idx = tid; idx < 64 * 32; idx += 256) {
            int row = idx >> 5, d4 = idx & 31;
            *(float4*)&KVs[row * QSTR + d4 * 4] =
                *(const float4*)(Vp + (size_t)(k0 + row) * HD_ + d4 * 4);
        }
        __syncthreads();

        // O += P * V   (thread owns cols c*32 .. c*32+31)
        #pragma unroll 4
        for (int j = 0; j < 64; j++) {
            float p = Ps[r * PSTR + j];
            #pragma unroll
            for (int d4 = 0; d4 < 8; d4++) {
                float4 vv = *(const float4*)&KVs[j * QSTR + c * 32 + d4 * 4];
                o[d4 * 4 + 0] = fmaf(p, vv.x, o[d4 * 4 + 0]);
                o[d4 * 4 + 1] = fmaf(p, vv.y, o[d4 * 4 + 1]);
                o[d4 * 4 + 2] = fmaf(p, vv.z, o[d4 * 4 + 2]);
                o[d4 * 4 + 3] = fmaf(p, vv.w, o[d4 * 4 + 3]);
            }
        }
        __syncthreads();   // V reads done before next K overwrite
    }

    // write out: (b, s, h, d) token-major
    float inv = 1.0f / l;
    float* Op = O + (((size_t)b * S_ + qi) * NH_ + hh) * HD_ + c * 32;
    #pragma unroll
    for (int d4 = 0; d4 < 8; d4++) {
        *(float4*)(Op + d4 * 4) = make_float4(o[d4 * 4 + 0] * inv, o[d4 * 4 + 1] * inv,
                                              o[d4 * 4 + 2] * inv, o[d4 * 4 + 3] * inv);
    }
}

// ---------------------------------------------------------------------------
// launch
// ---------------------------------------------------------------------------
extern "C" void kernel_launch(void* const* d_in, const int* in_sizes, int n_in,
                              void* d_out, int out_size) {
    const float* x     = (const float*)d_in[0];
    // d_in[1]: attention_mask (pure causal tril; handled analytically)
    const float* freqs = (const float*)d_in[2];
    // d_in[3]: input_pos (arange; unused)
    const float* w_qkv = (const float*)d_in[4];
    const float* w_fc  = (const float*)d_in[5];
    const float* w1    = (const float*)d_in[6];
    const float* w2    = (const float*)d_in[7];
    const float* w3    = (const float*)d_in[8];
    const float* anw   = (const float*)d_in[9];
    const float* fnw   = (const float*)d_in[10];
    float* out = (float*)d_out;

    float *hnorm, *qkv, *q, *k, *v, *attn, *h, *ffh;
    cudaGetSymbolAddress((void**)&hnorm, g_hnorm);
    cudaGetSymbolAddress((void**)&qkv,   g_qkv);
    cudaGetSymbolAddress((void**)&q,     g_q);
    cudaGetSymbolAddress((void**)&k,     g_kbuf);
    cudaGetSymbolAddress((void**)&v,     g_vbuf);
    cudaGetSymbolAddress((void**)&attn,  g_attn);
    cudaGetSymbolAddress((void**)&h,     g_h);
    cudaGetSymbolAddress((void**)&ffh,   g_ffh);

    cudaFuncSetAttribute(attn_k, cudaFuncAttributeMaxDynamicSharedMemorySize, ATTN_SMEM);

    // 1. h_norm = rmsnorm(x) * attn_norm_w
    rmsnorm_k<<<T_, 256>>>(x, anw, hnorm);
    // 2. qkv = h_norm @ w_qkv^T
    gemm_k<0><<<dim3(QKV_N / 64, T_ / 64), 256>>>(hnorm, w_qkv, nullptr, nullptr, qkv,
                                                  T_, QKV_N, E_);
    // 3. RoPE + split
    rope_split_k<<<T_, 256>>>(qkv, freqs, q, k, v);
    // 4. causal flash attention
    attn_k<<<dim3(S_ / 64, NH_, B_), 256, ATTN_SMEM>>>(q, k, v, attn);
    // 5. h = x + attn @ w_fc^T
    gemm_k<1><<<dim3(E_ / 64, T_ / 64), 256>>>(attn, w_fc, nullptr, x, h,
                                               T_, E_, E_);
    // 6. g = rmsnorm(h) * ff_norm_w
    rmsnorm_k<<<T_, 256>>>(h, fnw, hnorm);
    // 7. ffh = silu(g @ w1^T) * (g @ w2^T)
    gemm_k<2><<<dim3(FF_ / 64, T_ / 64), 256>>>(hnorm, w1, w2, nullptr, ffh,
                                                T_, FF_, E_);
    // 8. out = h + ffh @ w3^T
    gemm_k<1><<<dim3(E_ / 64, T_ / 64), 256>>>(ffh, w3, nullptr, h, out,
                                               T_, E_, FF_);
}

// round 4
// speedup vs baseline: 1.4217x; 1.4217x over previous
#include <cuda_runtime.h>
#include <cuda_bf16.h>
#include <math.h>
#include <stdint.h>

// ---------------------------------------------------------------------------
// DecoderLayer: B=2, S=2048, E=2048, NH=16, NKV=4, HD=128, FF=5632
// Round 3: GEMMs on mma.sync tf32 (baseline PTX — compute_103-safe; tcgen05
// is sm_103a-feature-gated and unavailable in this toolchain path).
// cp.async double-buffered smem pipeline. Attention: fp32 CUDA-core flash.
// ---------------------------------------------------------------------------

#define B_    2
#define S_    2048
#define E_    2048
#define NH_   16
#define NKV_  4
#define HD_   128
#define FF_   5632
#define T_    (B_ * S_)
#define QKV_N ((NH_ + 2 * NKV_) * HD_)  // 3072

// scratch (device globals; allocation-free)
__device__ float g_hnorm[(size_t)T_ * E_];
__device__ float g_qkv  [(size_t)T_ * QKV_N];
__device__ float g_q    [(size_t)B_ * NH_  * S_ * HD_];
__device__ float g_kbuf [(size_t)B_ * NKV_ * S_ * HD_];
__device__ float g_vbuf [(size_t)B_ * NKV_ * S_ * HD_];
__device__ float g_attn [(size_t)T_ * E_];
__device__ float g_h    [(size_t)T_ * E_];
__device__ float g_ffh  [(size_t)T_ * FF_];
// tf32-rounded weights
__device__ float g_wqkv_r[(size_t)QKV_N * E_];
__device__ float g_wfc_r [(size_t)E_ * E_];
__device__ float g_w1_r  [(size_t)FF_ * E_];
__device__ float g_w2_r  [(size_t)FF_ * E_];
__device__ float g_w3_r  [(size_t)E_ * FF_];

// ---------------------------------------------------------------------------
__device__ __forceinline__ uint32_t smem_u32(const void* p) {
    uint32_t a;
    asm("{ .reg .u64 t; cvta.to.shared.u64 t, %1; cvt.u32.u64 %0, t; }"
        : "=r"(a) : "l"(p));
    return a;
}

__device__ __forceinline__ float tf32r(float x) {
    uint32_t u;
    asm("cvt.rna.tf32.f32 %0, %1;" : "=r"(u) : "f"(x));
    return __uint_as_float(u);
}

#define CP_COMMIT() asm volatile("cp.async.commit_group;" ::: "memory")
#define CP_WAIT_0() asm volatile("cp.async.wait_group 0;" ::: "memory")

__device__ __forceinline__ void mma_tf32(float* c, const uint32_t* a,
                                         const uint32_t* b) {
    asm volatile(
        "mma.sync.aligned.m16n8k8.row.col.f32.tf32.tf32.f32 "
        "{%0,%1,%2,%3}, {%4,%5,%6,%7}, {%8,%9}, {%0,%1,%2,%3};"
        : "+f"(c[0]), "+f"(c[1]), "+f"(c[2]), "+f"(c[3])
        : "r"(a[0]), "r"(a[1]), "r"(a[2]), "r"(a[3]), "r"(b[0]), "r"(b[1]));
}

// ---------------------------------------------------------------------------
// weight round-to-nearest-tf32 pre-pass
// ---------------------------------------------------------------------------
__global__ void __launch_bounds__(256) round_tf32_k(const float* __restrict__ s,
                                                    float* __restrict__ d, int n4) {
    int i = blockIdx.x * 256 + threadIdx.x;
    if (i < n4) {
        float4 v = ((const float4*)s)[i];
        v.x = tf32r(v.x); v.y = tf32r(v.y); v.z = tf32r(v.z); v.w = tf32r(v.w);
        ((float4*)d)[i] = v;
    }
}

// ---------------------------------------------------------------------------
// RMSNorm (output rounded to tf32: feeds GEMM-A only)
// ---------------------------------------------------------------------------
__global__ void __launch_bounds__(256) rmsnorm_k(const float* __restrict__ x,
                                                 const float* __restrict__ w,
                                                 float* __restrict__ o) {
    size_t base = (size_t)blockIdx.x * E_;
    int tid = threadIdx.x;
    float4 v0 = *(const float4*)(x + base + tid * 4);
    float4 v1 = *(const float4*)(x + base + 1024 + tid * 4);
    float ss = v0.x*v0.x + v0.y*v0.y + v0.z*v0.z + v0.w*v0.w
             + v1.x*v1.x + v1.y*v1.y + v1.z*v1.z + v1.w*v1.w;
    #pragma unroll
    for (int off = 16; off; off >>= 1) ss += __shfl_xor_sync(0xffffffffu, ss, off);
    __shared__ float ws[8];
    if ((tid & 31) == 0) ws[tid >> 5] = ss;
    __syncthreads();
    float tot = ws[0] + ws[1] + ws[2] + ws[3] + ws[4] + ws[5] + ws[6] + ws[7];
    float sc = rsqrtf(tot * (1.0f / E_) + 1e-5f);
    float4 w0 = *(const float4*)(w + tid * 4);
    float4 w1w = *(const float4*)(w + 1024 + tid * 4);
    float4 r0 = make_float4(tf32r(v0.x*sc*w0.x),  tf32r(v0.y*sc*w0.y),
                            tf32r(v0.z*sc*w0.z),  tf32r(v0.w*sc*w0.w));
    float4 r1 = make_float4(tf32r(v1.x*sc*w1w.x), tf32r(v1.y*sc*w1w.y),
                            tf32r(v1.z*sc*w1w.z), tf32r(v1.w*sc*w1w.w));
    *(float4*)(o + base + tid * 4)        = r0;
    *(float4*)(o + base + 1024 + tid * 4) = r1;
}

// ---------------------------------------------------------------------------
// mma.sync tf32 GEMM: C[M,N] = A[M,K] * B[N,K]^T, tile 128 x BN, BK=32.
// MODE 0: C = A·B^T                     (BN = 128)
// MODE 1: C = R + A·B^T                 (BN = 128)
// MODE 2: C = tf32r(silu(A·B^T)*(A·B2^T))  (BN = 64, B rows 64..127 = B2)
// 256 threads = 8 warps (4 M x 2 N). Double-buffered cp.async.
// ---------------------------------------------------------------------------
#define ASTR 36          // padded row stride in floats (conflict-free frags)
#define STAGEF (128 * ASTR * 2)    // floats per stage (A block + B block)
#define GEMM_SMEM (2 * STAGEF * 4)

template <int MODE>
__global__ void __launch_bounds__(256) tgemm_k(const float* __restrict__ A,
                                               const float* __restrict__ Bm,
                                               const float* __restrict__ B2,
                                               const float* __restrict__ R,
                                               float* __restrict__ C,
                                               int M, int N, int K) {
    extern __shared__ float sm[];
    constexpr int BN = (MODE == 2) ? 64 : 128;
    constexpr int NT = (MODE == 2) ? 4 : 8;       // n-tiles per warp (per B matrix)

    const int tid = threadIdx.x;
    const int m0 = blockIdx.y * 128, n0 = blockIdx.x * BN;

    float* As[2] = { sm,              sm + STAGEF };
    float* Bs[2] = { sm + 128 * ASTR, sm + STAGEF + 128 * ASTR };
    uint32_t asu[2] = { smem_u32(As[0]), smem_u32(As[1]) };
    uint32_t bsu[2] = { smem_u32(Bs[0]), smem_u32(Bs[1]) };

    // loader mapping: 2 threads per row, 16 floats each
    const int lrow = tid >> 1, lkh = (tid & 1) * 16;
    const float* Agp = A + (size_t)(m0 + lrow) * K + lkh;
    const float* Bgp;
    if (MODE == 2)
        Bgp = ((lrow < 64) ? (Bm + (size_t)(n0 + lrow) * K)
                           : (B2 + (size_t)(n0 + lrow - 64) * K)) + lkh;
    else
        Bgp = Bm + (size_t)(n0 + lrow) * K + lkh;
    const uint32_t sAoff = (uint32_t)(lrow * ASTR + lkh) * 4;
    const uint32_t sBoff = sAoff;

    auto load_chunk = [&](int s, int c) {
        const float* ag = Agp + c * 32;
        const float* bg = Bgp + c * 32;
        uint32_t da = asu[s] + sAoff;
        uint32_t db = bsu[s] + sBoff;
        #pragma unroll
        for (int i = 0; i < 4; i++) {
            asm volatile("cp.async.cg.shared.global [%0], [%1], 16;"
                         :: "r"(da + i * 16), "l"(ag + i * 4) : "memory");
            asm volatile("cp.async.cg.shared.global [%0], [%1], 16;"
                         :: "r"(db + i * 16), "l"(bg + i * 4) : "memory");
        }
        CP_COMMIT();
    };

    const int wid = tid >> 5, lane = tid & 31;
    const int gid = lane >> 2, tg = lane & 3;
    const int wm = wid >> 1, wn = wid & 1;

    float c1[2][NT][4];
    float c2[(MODE == 2) ? 2 : 1][(MODE == 2) ? NT : 1][4];
    #pragma unroll
    for (int mt = 0; mt < 2; mt++)
        #pragma unroll
        for (int nt = 0; nt < NT; nt++)
            #pragma unroll
            for (int q = 0; q < 4; q++) {
                c1[mt][nt][q] = 0.f;
                if (MODE == 2) c2[mt][nt][q] = 0.f;
            }

    const int NC = K >> 5;
    load_chunk(0, 0);

    for (int c = 0; c < NC; c++) {
        CP_WAIT_0();
        __syncthreads();
        if (c + 1 < NC) load_chunk((c + 1) & 1, c + 1);

        const float* Ab = As[c & 1];
        const float* Bb = Bs[c & 1];
        #pragma unroll
        for (int ks = 0; ks < 4; ks++) {
            uint32_t af[2][4];
            #pragma unroll
            for (int mt = 0; mt < 2; mt++) {
                int r0 = (wm * 32 + mt * 16 + gid) * ASTR + ks * 8 + tg;
                af[mt][0] = __float_as_uint(Ab[r0]);
                af[mt][1] = __float_as_uint(Ab[r0 + 8 * ASTR]);
                af[mt][2] = __float_as_uint(Ab[r0 + 4]);
                af[mt][3] = __float_as_uint(Ab[r0 + 8 * ASTR + 4]);
            }
            uint32_t bf[NT][2];
            #pragma unroll
            for (int nt = 0; nt < NT; nt++) {
                int r0 = (wn * (NT * 8) + nt * 8 + gid) * ASTR + ks * 8 + tg;
                bf[nt][0] = __float_as_uint(Bb[r0]);
                bf[nt][1] = __float_as_uint(Bb[r0 + 4]);
            }
            #pragma unroll
            for (int mt = 0; mt < 2; mt++)
                #pragma unroll
                for (int nt = 0; nt < NT; nt++)
                    mma_tf32(c1[mt][nt], af[mt], bf[nt]);
            if (MODE == 2) {
                uint32_t bf2[NT][2];
                #pragma unroll
                for (int nt = 0; nt < NT; nt++) {
                    int r0 = (64 + wn * 32 + nt * 8 + gid) * ASTR + ks * 8 + tg;
                    bf2[nt][0] = __float_as_uint(Bb[r0]);
                    bf2[nt][1] = __float_as_uint(Bb[r0 + 4]);
                }
                #pragma unroll
                for (int mt = 0; mt < 2; mt++)
                    #pragma unroll
                    for (int nt = 0; nt < NT; nt++)
                        mma_tf32(c2[mt][nt], af[mt], bf2[nt]);
            }
        }
    }

    // epilogue
    #pragma unroll
    for (int mt = 0; mt < 2; mt++) {
        #pragma unroll
        for (int half = 0; half < 2; half++) {
            size_t row = (size_t)(m0 + wm * 32 + mt * 16 + gid + half * 8);
            #pragma unroll
            for (int nt = 0; nt < NT; nt++) {
                int col = n0 + wn * (NT * 8) + nt * 8 + tg * 2;
                float v0 = c1[mt][nt][half * 2 + 0];
                float v1 = c1[mt][nt][half * 2 + 1];
                if (MODE == 1) {
                    float2 res = *(const float2*)(R + row * N + col);
                    v0 += res.x; v1 += res.y;
                } else if (MODE == 2) {
                    float u0 = c2[mt][nt][half * 2 + 0];
                    float u1 = c2[mt][nt][half * 2 + 1];
                    v0 = tf32r((v0 / (1.0f + __expf(-v0))) * u0);
                    v1 = tf32r((v1 / (1.0f + __expf(-v1))) * u1);
                }
                *(float2*)(C + row * N + col) = make_float2(v0, v1);
            }
        }
    }
}

// ---------------------------------------------------------------------------
// RoPE + QKV split
// ---------------------------------------------------------------------------
__global__ void __launch_bounds__(256) rope_split_k(const float* __restrict__ qkv,
                                                    const float* __restrict__ fc,
                                                    float* __restrict__ q,
                                                    float* __restrict__ k,
                                                    float* __restrict__ v) {
    int t = blockIdx.x;
    int b = t >> 11;
    int s = t & 2047;
    const float* row = qkv + (size_t)t * QKV_N;
    const float* f = fc + (size_t)s * HD_;
    for (int idx = threadIdx.x; idx < NH_ * 64; idx += 256) {
        int h = idx >> 6, i = idx & 63;
        float x0 = row[h * HD_ + 2 * i];
        float x1 = row[h * HD_ + 2 * i + 1];
        float cs = f[2 * i], sn = f[2 * i + 1];
        size_t o = ((size_t)(b * NH_ + h) * S_ + s) * HD_ + 2 * i;
        q[o]     = x0 * cs - x1 * sn;
        q[o + 1] = x1 * cs + x0 * sn;
    }
    for (int idx = threadIdx.x; idx < NKV_ * 64; idx += 256) {
        int h = idx >> 6, i = idx & 63;
        float x0 = row[NH_ * HD_ + h * HD_ + 2 * i];
        float x1 = row[NH_ * HD_ + h * HD_ + 2 * i + 1];
        float cs = f[2 * i], sn = f[2 * i + 1];
        size_t o = ((size_t)(b * NKV_ + h) * S_ + s) * HD_ + 2 * i;
        k[o]     = x0 * cs - x1 * sn;
        k[o + 1] = x1 * cs + x0 * sn;
    }
    for (int idx = threadIdx.x; idx < NKV_ * HD_; idx += 256) {
        int h = idx >> 7, d = idx & 127;
        v[((size_t)(b * NKV_ + h) * S_ + s) * HD_ + d] =
            row[(NH_ + NKV_) * HD_ + idx];
    }
}

// ---------------------------------------------------------------------------
// Flash attention, fp32 (output rounded to tf32: feeds GEMM-A)
// ---------------------------------------------------------------------------
#define QSTR 132
#define PSTR 65
#define ATTN_SMEM ((2 * 64 * QSTR + 64 * PSTR) * 4)

__global__ void __launch_bounds__(256) attn_k(const float* __restrict__ Q,
                                              const float* __restrict__ Kt,
                                              const float* __restrict__ V,
                                              float* __restrict__ O) {
    extern __shared__ float smf[];
    float* Qs  = smf;
    float* KVs = smf + 64 * QSTR;
    float* Ps  = smf + 2 * 64 * QSTR;

    int tid = threadIdx.x;
    int qt = blockIdx.x, hh = blockIdx.y, b = blockIdx.z;
    int q0 = qt * 64;
    const float* Qp = Q  + (size_t)(b * NH_  + hh)        * S_ * HD_;
    const float* Kp = Kt + (size_t)(b * NKV_ + (hh >> 2)) * S_ * HD_;
    const float* Vp = V  + (size_t)(b * NKV_ + (hh >> 2)) * S_ * HD_;

    int r = tid >> 2, c = tid & 3;
    int qi = q0 + r;

    for (int idx = tid; idx < 64 * 32; idx += 256) {
        int row = idx >> 5, d4 = idx & 31;
        *(float4*)&Qs[row * QSTR + d4 * 4] =
            *(const float4*)(Qp + (size_t)(q0 + row) * HD_ + d4 * 4);
    }

    float o[32];
    #pragma unroll
    for (int d = 0; d < 32; d++) o[d] = 0.f;
    float m = -1e30f, l = 0.f;
    const float scale = 0.022097086912079608f;

    for (int kt = 0; kt <= qt; kt++) {
        int k0 = kt * 64;
        for (int idx = tid; idx < 64 * 32; idx += 256) {
            int row = idx >> 5, d4 = idx & 31;
            *(float4*)&KVs[row * QSTR + d4 * 4] =
                *(const float4*)(Kp + (size_t)(k0 + row) * HD_ + d4 * 4);
        }
        __syncthreads();

        float acc[16];
        #pragma unroll
        for (int jj = 0; jj < 16; jj++) acc[jj] = 0.f;
        #pragma unroll 4
        for (int d4 = 0; d4 < 32; d4++) {
            float4 qv = *(const float4*)&Qs[r * QSTR + d4 * 4];
            #pragma unroll
            for (int jj = 0; jj < 16; jj++) {
                float4 kv = *(const float4*)&KVs[(c * 16 + jj) * QSTR + d4 * 4];
                acc[jj] = fmaf(qv.x, kv.x, acc[jj]);
                acc[jj] = fmaf(qv.y, kv.y, acc[jj]);
                acc[jj] = fmaf(qv.z, kv.z, acc[jj]);
                acc[jj] = fmaf(qv.w, kv.w, acc[jj]);
            }
        }

        float mt = -1e30f;
        #pragma unroll
        for (int jj = 0; jj < 16; jj++) {
            float s = acc[jj] * scale;
            if (k0 + c * 16 + jj > qi) s = -1e30f;
            acc[jj] = s;
            mt = fmaxf(mt, s);
        }
        mt = fmaxf(mt, __shfl_xor_sync(0xffffffffu, mt, 1));
        mt = fmaxf(mt, __shfl_xor_sync(0xffffffffu, mt, 2));
        float mnew = fmaxf(m, mt);
        float fac = __expf(m - mnew);
        float ls = 0.f;
        #pragma unroll
        for (int jj = 0; jj < 16; jj++) {
            float p = __expf(acc[jj] - mnew);
            ls += p;
            Ps[r * PSTR + c * 16 + jj] = p;
        }
        ls += __shfl_xor_sync(0xffffffffu, ls, 1);
        ls += __shfl_xor_sync(0xffffffffu, ls, 2);
        l = l * fac + ls;
        m = mnew;
        #pragma unroll
        for (int d = 0; d < 32; d++) o[d] *= fac;
        __syncthreads();

        for (int idx = tid; idx < 64 * 32; idx += 256) {
            int row = idx >> 5, d4 = idx & 31;
            *(float4*)&KVs[row * QSTR + d4 * 4] =
                *(const float4*)(Vp + (size_t)(k0 + row) * HD_ + d4 * 4);
        }
        __syncthreads();

        #pragma unroll 4
        for (int j = 0; j < 64; j++) {
            float p = Ps[r * PSTR + j];
            #pragma unroll
            for (int d4 = 0; d4 < 8; d4++) {
                float4 vv = *(const float4*)&KVs[j * QSTR + c * 32 + d4 * 4];
                o[d4 * 4 + 0] = fmaf(p, vv.x, o[d4 * 4 + 0]);
                o[d4 * 4 + 1] = fmaf(p, vv.y, o[d4 * 4 + 1]);
                o[d4 * 4 + 2] = fmaf(p, vv.z, o[d4 * 4 + 2]);
                o[d4 * 4 + 3] = fmaf(p, vv.w, o[d4 * 4 + 3]);
            }
        }
        __syncthreads();
    }

    float inv = 1.0f / l;
    float* Op = O + (((size_t)b * S_ + qi) * NH_ + hh) * HD_ + c * 32;
    #pragma unroll
    for (int d4 = 0; d4 < 8; d4++) {
        *(float4*)(Op + d4 * 4) = make_float4(tf32r(o[d4 * 4 + 0] * inv),
                                              tf32r(o[d4 * 4 + 1] * inv),
                                              tf32r(o[d4 * 4 + 2] * inv),
                                              tf32r(o[d4 * 4 + 3] * inv));
    }
}

// ---------------------------------------------------------------------------
// launch
// ---------------------------------------------------------------------------
extern "C" void kernel_launch(void* const* d_in, const int* in_sizes, int n_in,
                              void* d_out, int out_size) {
    const float* x     = (const float*)d_in[0];
    const float* freqs = (const float*)d_in[2];
    const float* w_qkv = (const float*)d_in[4];
    const float* w_fc  = (const float*)d_in[5];
    const float* w1    = (const float*)d_in[6];
    const float* w2    = (const float*)d_in[7];
    const float* w3    = (const float*)d_in[8];
    const float* anw   = (const float*)d_in[9];
    const float* fnw   = (const float*)d_in[10];
    float* out = (float*)d_out;

    float *hnorm, *qkv, *q, *k, *v, *attn, *h, *ffh;
    float *wqkv_r, *wfc_r, *w1_r, *w2_r, *w3_r;
    cudaGetSymbolAddress((void**)&hnorm, g_hnorm);
    cudaGetSymbolAddress((void**)&qkv,   g_qkv);
    cudaGetSymbolAddress((void**)&q,     g_q);
    cudaGetSymbolAddress((void**)&k,     g_kbuf);
    cudaGetSymbolAddress((void**)&v,     g_vbuf);
    cudaGetSymbolAddress((void**)&attn,  g_attn);
    cudaGetSymbolAddress((void**)&h,     g_h);
    cudaGetSymbolAddress((void**)&ffh,   g_ffh);
    cudaGetSymbolAddress((void**)&wqkv_r, g_wqkv_r);
    cudaGetSymbolAddress((void**)&wfc_r,  g_wfc_r);
    cudaGetSymbolAddress((void**)&w1_r,   g_w1_r);
    cudaGetSymbolAddress((void**)&w2_r,   g_w2_r);
    cudaGetSymbolAddress((void**)&w3_r,   g_w3_r);

    static bool attr_done = false;
    if (!attr_done) {
        cudaFuncSetAttribute(tgemm_k<0>, cudaFuncAttributeMaxDynamicSharedMemorySize, GEMM_SMEM);
        cudaFuncSetAttribute(tgemm_k<1>, cudaFuncAttributeMaxDynamicSharedMemorySize, GEMM_SMEM);
        cudaFuncSetAttribute(tgemm_k<2>, cudaFuncAttributeMaxDynamicSharedMemorySize, GEMM_SMEM);
        cudaFuncSetAttribute(attn_k, cudaFuncAttributeMaxDynamicSharedMemorySize, ATTN_SMEM);
        attr_done = true;
    }

    // 0. round weights to tf32 (RN: removes truncation bias in mma.sync tf32)
    auto rnd = [](const float* s, float* d, size_t n) {
        int n4 = (int)(n / 4);
        round_tf32_k<<<(n4 + 255) / 256, 256>>>(s, d, n4);
    };
    rnd(w_qkv, wqkv_r, (size_t)QKV_N * E_);
    rnd(w_fc,  wfc_r,  (size_t)E_ * E_);
    rnd(w1,    w1_r,   (size_t)FF_ * E_);
    rnd(w2,    w2_r,   (size_t)FF_ * E_);
    rnd(w3,    w3_r,   (size_t)E_ * FF_);

    // 1. h_norm = tf32(rmsnorm(x) * attn_norm_w)
    rmsnorm_k<<<T_, 256>>>(x, anw, hnorm);
    // 2. qkv = h_norm @ w_qkv^T
    tgemm_k<0><<<dim3(QKV_N / 128, T_ / 128), 256, GEMM_SMEM>>>(hnorm, wqkv_r, nullptr,
                                                                nullptr, qkv, T_, QKV_N, E_);
    // 3. RoPE + split
    rope_split_k<<<T_, 256>>>(qkv, freqs, q, k, v);
    // 4. causal flash attention (fp32)
    attn_k<<<dim3(S_ / 64, NH_, B_), 256, ATTN_SMEM>>>(q, k, v, attn);
    // 5. h = x + attn @ w_fc^T
    tgemm_k<1><<<dim3(E_ / 128, T_ / 128), 256, GEMM_SMEM>>>(attn, wfc_r, nullptr, x,
                                                             h, T_, E_, E_);
    // 6. g = tf32(rmsnorm(h) * ff_norm_w)
    rmsnorm_k<<<T_, 256>>>(h, fnw, hnorm);
    // 7. ffh = tf32( silu(g @ w1^T) * (g @ w2^T) )
    tgemm_k<2><<<dim3(FF_ / 64, T_ / 128), 256, GEMM_SMEM>>>(hnorm, w1_r, w2_r, nullptr,
                                                             ffh, T_, FF_, E_);
    // 8. out = h + ffh @ w3^T
    tgemm_k<1><<<dim3(E_ / 128, T_ / 128), 256, GEMM_SMEM>>>(ffh, w3_r, nullptr, h,
                                                             out, T_, E_, FF_);
}

// round 6
// speedup vs baseline: 1.5212x; 1.0700x over previous
#include <cuda_runtime.h>
#include <cuda_bf16.h>
#include <math.h>
#include <stdint.h>

// ---------------------------------------------------------------------------
// DecoderLayer: B=2, S=2048, E=2048, NH=16, NKV=4, HD=128, FF=5632
// Round 4: tf32 mma.sync GEMMs, XOR-swizzled smem (32KB/stage), 3-stage
// cp.async pipeline, 2 CTAs/SM. In-kernel B-fragment tf32 rounding (no
// weight pre-pass). Attention: fp32 CUDA-core flash.
// ---------------------------------------------------------------------------

#define B_    2
#define S_    2048
#define E_    2048
#define NH_   16
#define NKV_  4
#define HD_   128
#define FF_   5632
#define T_    (B_ * S_)
#define QKV_N ((NH_ + 2 * NKV_) * HD_)  // 3072

// scratch (device globals; allocation-free)
__device__ float g_hnorm[(size_t)T_ * E_];
__device__ float g_qkv  [(size_t)T_ * QKV_N];
__device__ float g_q    [(size_t)B_ * NH_  * S_ * HD_];
__device__ float g_kbuf [(size_t)B_ * NKV_ * S_ * HD_];
__device__ float g_vbuf [(size_t)B_ * NKV_ * S_ * HD_];
__device__ float g_attn [(size_t)T_ * E_];
__device__ float g_h    [(size_t)T_ * E_];
__device__ float g_ffh  [(size_t)T_ * FF_];

// ---------------------------------------------------------------------------
__device__ __forceinline__ uint32_t smem_u32(const void* p) {
    uint32_t a;
    asm("{ .reg .u64 t; cvta.to.shared.u64 t, %1; cvt.u32.u64 %0, t; }"
        : "=r"(a) : "l"(p));
    return a;
}

__device__ __forceinline__ float tf32r(float x) {
    uint32_t u;
    asm("cvt.rna.tf32.f32 %0, %1;" : "=r"(u) : "f"(x));
    return __uint_as_float(u);
}

__device__ __forceinline__ uint32_t tf32r_u(float x) {
    uint32_t u;
    asm("cvt.rna.tf32.f32 %0, %1;" : "=r"(u) : "f"(x));
    return u;
}

#define CP_COMMIT() asm volatile("cp.async.commit_group;" ::: "memory")
#define CP_WAIT_0() asm volatile("cp.async.wait_group 0;" ::: "memory")
#define CP_WAIT_1() asm volatile("cp.async.wait_group 1;" ::: "memory")

__device__ __forceinline__ void mma_tf32(float* c, const uint32_t* a,
                                         const uint32_t* b) {
    asm volatile(
        "mma.sync.aligned.m16n8k8.row.col.f32.tf32.tf32.f32 "
        "{%0,%1,%2,%3}, {%4,%5,%6,%7}, {%8,%9}, {%0,%1,%2,%3};"
        : "+f"(c[0]), "+f"(c[1]), "+f"(c[2]), "+f"(c[3])
        : "r"(a[0]), "r"(a[1]), "r"(a[2]), "r"(a[3]), "r"(b[0]), "r"(b[1]));
}

// ---------------------------------------------------------------------------
// RMSNorm (output rounded to tf32: feeds GEMM-A only)
// ---------------------------------------------------------------------------
__global__ void __launch_bounds__(256) rmsnorm_k(const float* __restrict__ x,
                                                 const float* __restrict__ w,
                                                 float* __restrict__ o) {
    size_t base = (size_t)blockIdx.x * E_;
    int tid = threadIdx.x;
    float4 v0 = *(const float4*)(x + base + tid * 4);
    float4 v1 = *(const float4*)(x + base + 1024 + tid * 4);
    float ss = v0.x*v0.x + v0.y*v0.y + v0.z*v0.z + v0.w*v0.w
             + v1.x*v1.x + v1.y*v1.y + v1.z*v1.z + v1.w*v1.w;
    #pragma unroll
    for (int off = 16; off; off >>= 1) ss += __shfl_xor_sync(0xffffffffu, ss, off);
    __shared__ float ws[8];
    if ((tid & 31) == 0) ws[tid >> 5] = ss;
    __syncthreads();
    float tot = ws[0] + ws[1] + ws[2] + ws[3] + ws[4] + ws[5] + ws[6] + ws[7];
    float sc = rsqrtf(tot * (1.0f / E_) + 1e-5f);
    float4 w0 = *(const float4*)(w + tid * 4);
    float4 w1w = *(const float4*)(w + 1024 + tid * 4);
    float4 r0 = make_float4(tf32r(v0.x*sc*w0.x),  tf32r(v0.y*sc*w0.y),
                            tf32r(v0.z*sc*w0.z),  tf32r(v0.w*sc*w0.w));
    float4 r1 = make_float4(tf32r(v1.x*sc*w1w.x), tf32r(v1.y*sc*w1w.y),
                            tf32r(v1.z*sc*w1w.z), tf32r(v1.w*sc*w1w.w));
    *(float4*)(o + base + tid * 4)        = r0;
    *(float4*)(o + base + 1024 + tid * 4) = r1;
}

// ---------------------------------------------------------------------------
// mma.sync tf32 GEMM: C[M,N] = A[M,K] * B[N,K]^T, tile 128 x BN, BK=32.
// MODE 0: C = A·B^T                        (BN = 128)
// MODE 1: C = R + A·B^T                    (BN = 128)
// MODE 2: C = tf32r(silu(A·B^T)*(A·B2^T))  (BN = 64; B rows 64..127 = B2)
// 256 threads = 8 warps (4 M x 2 N). 3-stage cp.async, XOR swizzle.
// B fragments rounded to tf32 (RNA) in-register after LDS.
// ---------------------------------------------------------------------------
#define STAGE_F 8192                 // floats per stage: (128 A + 128 B) x 32
#define NSTAGE 3
#define GEMM_SMEM (NSTAGE * STAGE_F * 4)   // 96 KB

// float index of element e (0..31) of row r within a 128-row block
__device__ __forceinline__ int fidx(int r, int g, int tg) {
    return r * 32 + (((g ^ (r & 7)) << 2) | tg);
}

template <int MODE>
__global__ void __launch_bounds__(256, 2) tgemm_k(const float* __restrict__ A,
                                                  const float* __restrict__ Bm,
                                                  const float* __restrict__ B2,
                                                  const float* __restrict__ R,
                                                  float* __restrict__ C,
                                                  int M, int N, int K) {
    extern __shared__ float sm[];
    constexpr int BN = (MODE == 2) ? 64 : 128;
    constexpr int NT = (MODE == 2) ? 4 : 8;   // n-tiles per warp (per B matrix)

    const int tid = threadIdx.x;
    const int m0 = blockIdx.y * 128, n0 = blockIdx.x * BN;

    // loader: 2 threads per row, 4 x 16B chunks each
    const int lrow = tid >> 1;
    const int cbase = (tid & 1) * 4;
    const float* Agp = A + (size_t)(m0 + lrow) * K + cbase * 4;
    const float* Bgp;
    if (MODE == 2)
        Bgp = ((lrow < 64) ? (Bm + (size_t)(n0 + lrow) * K)
                           : (B2 + (size_t)(n0 + lrow - 64) * K)) + cbase * 4;
    else
        Bgp = Bm + (size_t)(n0 + lrow) * K + cbase * 4;

    const uint32_t smb = smem_u32(sm);
    // swizzled dst byte offsets within a 128-row block
    uint32_t dsto[4];
    #pragma unroll
    for (int i = 0; i < 4; i++)
        dsto[i] = (uint32_t)(lrow * 128 + (((cbase + i) ^ (lrow & 7)) << 4));

    auto load_chunk = [&](int s, int c) {
        uint32_t ab = smb + s * (STAGE_F * 4);
        uint32_t bb = ab + 16384;
        const float* ag = Agp + c * 32;
        const float* bg = Bgp + c * 32;
        #pragma unroll
        for (int i = 0; i < 4; i++) {
            asm volatile("cp.async.cg.shared.global [%0], [%1], 16;"
                         :: "r"(ab + dsto[i]), "l"(ag + i * 4) : "memory");
            asm volatile("cp.async.cg.shared.global [%0], [%1], 16;"
                         :: "r"(bb + dsto[i]), "l"(bg + i * 4) : "memory");
        }
        CP_COMMIT();
    };

    const int wid = tid >> 5, lane = tid & 31;
    const int gid = lane >> 2, tg = lane & 3;
    const int wm = wid >> 1, wn = wid & 1;

    float c1[2][NT][4];
    float c2[(MODE == 2) ? 2 : 1][(MODE == 2) ? NT : 1][4];
    #pragma unroll
    for (int mt = 0; mt < 2; mt++)
        #pragma unroll
        for (int nt = 0; nt < NT; nt++)
            #pragma unroll
            for (int q = 0; q < 4; q++) {
                c1[mt][nt][q] = 0.f;
                if (MODE == 2) c2[mt][nt][q] = 0.f;
            }

    const int NC = K >> 5;
    load_chunk(0, 0);
    load_chunk(1, 1);

    int stage = 0, nstage = 2;
    for (int c = 0; c < NC; c++) {
        if (c + 1 < NC) CP_WAIT_1(); else CP_WAIT_0();
        __syncthreads();
        if (c + 2 < NC) {
            load_chunk(nstage, c + 2);
            nstage = (nstage == 2) ? 0 : nstage + 1;
        }

        const float* Ab = sm + stage * STAGE_F;
        const float* Bb = Ab + 4096;
        stage = (stage == 2) ? 0 : stage + 1;

        #pragma unroll
        for (int ks = 0; ks < 4; ks++) {
            const int g0 = 2 * ks, g1 = 2 * ks + 1;
            uint32_t af[2][4];
            #pragma unroll
            for (int mt = 0; mt < 2; mt++) {
                int ra = wm * 32 + mt * 16 + gid;
                af[mt][0] = __float_as_uint(Ab[fidx(ra,     g0, tg)]);
                af[mt][1] = __float_as_uint(Ab[fidx(ra + 8, g0, tg)]);
                af[mt][2] = __float_as_uint(Ab[fidx(ra,     g1, tg)]);
                af[mt][3] = __float_as_uint(Ab[fidx(ra + 8, g1, tg)]);
            }
            uint32_t bf[NT][2];
            #pragma unroll
            for (int nt = 0; nt < NT; nt++) {
                int rb = wn * (NT * 8) + nt * 8 + gid;
                bf[nt][0] = tf32r_u(Bb[fidx(rb, g0, tg)]);
                bf[nt][1] = tf32r_u(Bb[fidx(rb, g1, tg)]);
            }
            #pragma unroll
            for (int mt = 0; mt < 2; mt++)
                #pragma unroll
                for (int nt = 0; nt < NT; nt++)
                    mma_tf32(c1[mt][nt], af[mt], bf[nt]);
            if (MODE == 2) {
                uint32_t bf2[NT][2];
                #pragma unroll
                for (int nt = 0; nt < NT; nt++) {
                    int rb = 64 + wn * 32 + nt * 8 + gid;
                    bf2[nt][0] = tf32r_u(Bb[fidx(rb, g0, tg)]);
                    bf2[nt][1] = tf32r_u(Bb[fidx(rb, g1, tg)]);
                }
                #pragma unroll
                for (int mt = 0; mt < 2; mt++)
                    #pragma unroll
                    for (int nt = 0; nt < NT; nt++)
                        mma_tf32(c2[mt][nt], af[mt], bf2[nt]);
            }
        }
    }

    // epilogue
    #pragma unroll
    for (int mt = 0; mt < 2; mt++) {
        #pragma unroll
        for (int half = 0; half < 2; half++) {
            size_t row = (size_t)(m0 + wm * 32 + mt * 16 + gid + half * 8);
            #pragma unroll
            for (int nt = 0; nt < NT; nt++) {
                int col = n0 + wn * (NT * 8) + nt * 8 + tg * 2;
                float v0 = c1[mt][nt][half * 2 + 0];
                float v1 = c1[mt][nt][half * 2 + 1];
                if (MODE == 1) {
                    float2 res = *(const float2*)(R + row * N + col);
                    v0 += res.x; v1 += res.y;
                } else if (MODE == 2) {
                    float u0 = c2[mt][nt][half * 2 + 0];
                    float u1 = c2[mt][nt][half * 2 + 1];
                    v0 = tf32r((v0 / (1.0f + __expf(-v0))) * u0);
                    v1 = tf32r((v1 / (1.0f + __expf(-v1))) * u1);
                }
                *(float2*)(C + row * N + col) = make_float2(v0, v1);
            }
        }
    }
}

// ---------------------------------------------------------------------------
// RoPE + QKV split
// ---------------------------------------------------------------------------
__global__ void __launch_bounds__(256) rope_split_k(const float* __restrict__ qkv,
                                                    const float* __restrict__ fc,
                                                    float* __restrict__ q,
                                                    float* __restrict__ k,
                                                    float* __restrict__ v) {
    int t = blockIdx.x;
    int b = t >> 11;
    int s = t & 2047;
    const float* row = qkv + (size_t)t * QKV_N;
    const float* f = fc + (size_t)s * HD_;
    for (int idx = threadIdx.x; idx < NH_ * 64; idx += 256) {
        int h = idx >> 6, i = idx & 63;
        float x0 = row[h * HD_ + 2 * i];
        float x1 = row[h * HD_ + 2 * i + 1];
        float cs = f[2 * i], sn = f[2 * i + 1];
        size_t o = ((size_t)(b * NH_ + h) * S_ + s) * HD_ + 2 * i;
        q[o]     = x0 * cs - x1 * sn;
        q[o + 1] = x1 * cs + x0 * sn;
    }
    for (int idx = threadIdx.x; idx < NKV_ * 64; idx += 256) {
        int h = idx >> 6, i = idx & 63;
        float x0 = row[NH_ * HD_ + h * HD_ + 2 * i];
        float x1 = row[NH_ * HD_ + h * HD_ + 2 * i + 1];
        float cs = f[2 * i], sn = f[2 * i + 1];
        size_t o = ((size_t)(b * NKV_ + h) * S_ + s) * HD_ + 2 * i;
        k[o]     = x0 * cs - x1 * sn;
        k[o + 1] = x1 * cs + x0 * sn;
    }
    for (int idx = threadIdx.x; idx < NKV_ * HD_; idx += 256) {
        int h = idx >> 7, d = idx & 127;
        v[((size_t)(b * NKV_ + h) * S_ + s) * HD_ + d] =
            row[(NH_ + NKV_) * HD_ + idx];
    }
}

// ---------------------------------------------------------------------------
// Flash attention, fp32 (output rounded to tf32: feeds GEMM-A)
// ---------------------------------------------------------------------------
#define QSTR 132
#define PSTR 65
#define ATTN_SMEM ((2 * 64 * QSTR + 64 * PSTR) * 4)

__global__ void __launch_bounds__(256) attn_k(const float* __restrict__ Q,
                                              const float* __restrict__ Kt,
                                              const float* __restrict__ V,
                                              float* __restrict__ O) {
    extern __shared__ float smf[];
    float* Qs  = smf;
    float* KVs = smf + 64 * QSTR;
    float* Ps  = smf + 2 * 64 * QSTR;

    int tid = threadIdx.x;
    int qt = blockIdx.x, hh = blockIdx.y, b = blockIdx.z;
    int q0 = qt * 64;
    const float* Qp = Q  + (size_t)(b * NH_  + hh)        * S_ * HD_;
    const float* Kp = Kt + (size_t)(b * NKV_ + (hh >> 2)) * S_ * HD_;
    const float* Vp = V  + (size_t)(b * NKV_ + (hh >> 2)) * S_ * HD_;

    int r = tid >> 2, c = tid & 3;
    int qi = q0 + r;

    for (int idx = tid; idx < 64 * 32; idx += 256) {
        int row = idx >> 5, d4 = idx & 31;
        *(float4*)&Qs[row * QSTR + d4 * 4] =
            *(const float4*)(Qp + (size_t)(q0 + row) * HD_ + d4 * 4);
    }

    float o[32];
    #pragma unroll
    for (int d = 0; d < 32; d++) o[d] = 0.f;
    float m = -1e30f, l = 0.f;
    const float scale = 0.022097086912079608f;

    for (int kt = 0; kt <= qt; kt++) {
        int k0 = kt * 64;
        for (int idx = tid; idx < 64 * 32; idx += 256) {
            int row = idx >> 5, d4 = idx & 31;
            *(float4*)&KVs[row * QSTR + d4 * 4] =
                *(const float4*)(Kp + (size_t)(k0 + row) * HD_ + d4 * 4);
        }
        __syncthreads();

        float acc[16];
        #pragma unroll
        for (int jj = 0; jj < 16; jj++) acc[jj] = 0.f;
        #pragma unroll 4
        for (int d4 = 0; d4 < 32; d4++) {
            float4 qv = *(const float4*)&Qs[r * QSTR + d4 * 4];
            #pragma unroll
            for (int jj = 0; jj < 16; jj++) {
                float4 kv = *(const float4*)&KVs[(c * 16 + jj) * QSTR + d4 * 4];
                acc[jj] = fmaf(qv.x, kv.x, acc[jj]);
                acc[jj] = fmaf(qv.y, kv.y, acc[jj]);
                acc[jj] = fmaf(qv.z, kv.z, acc[jj]);
                acc[jj] = fmaf(qv.w, kv.w, acc[jj]);
            }
        }

        float mt = -1e30f;
        #pragma unroll
        for (int jj = 0; jj < 16; jj++) {
            float s = acc[jj] * scale;
            if (k0 + c * 16 + jj > qi) s = -1e30f;
            acc[jj] = s;
            mt = fmaxf(mt, s);
        }
        mt = fmaxf(mt, __shfl_xor_sync(0xffffffffu, mt, 1));
        mt = fmaxf(mt, __shfl_xor_sync(0xffffffffu, mt, 2));
        float mnew = fmaxf(m, mt);
        float fac = __expf(m - mnew);
        float ls = 0.f;
        #pragma unroll
        for (int jj = 0; jj < 16; jj++) {
            float p = __expf(acc[jj] - mnew);
            ls += p;
            Ps[r * PSTR + c * 16 + jj] = p;
        }
        ls += __shfl_xor_sync(0xffffffffu, ls, 1);
        ls += __shfl_xor_sync(0xffffffffu, ls, 2);
        l = l * fac + ls;
        m = mnew;
        #pragma unroll
        for (int d = 0; d < 32; d++) o[d] *= fac;
        __syncthreads();

        for (int idx = tid; idx < 64 * 32; idx += 256) {
            int row = idx >> 5, d4 = idx & 31;
            *(float4*)&KVs[row * QSTR + d4 * 4] =
                *(const float4*)(Vp + (size_t)(k0 + row) * HD_ + d4 * 4);
        }
        __syncthreads();

        #pragma unroll 4
        for (int j = 0; j < 64; j++) {
            float p = Ps[r * PSTR + j];
            #pragma unroll
            for (int d4 = 0; d4 < 8; d4++) {
                float4 vv = *(const float4*)&KVs[j * QSTR + c * 32 + d4 * 4];
                o[d4 * 4 + 0] = fmaf(p, vv.x, o[d4 * 4 + 0]);
                o[d4 * 4 + 1] = fmaf(p, vv.y, o[d4 * 4 + 1]);
                o[d4 * 4 + 2] = fmaf(p, vv.z, o[d4 * 4 + 2]);
                o[d4 * 4 + 3] = fmaf(p, vv.w, o[d4 * 4 + 3]);
            }
        }
        __syncthreads();
    }

    float inv = 1.0f / l;
    float* Op = O + (((size_t)b * S_ + qi) * NH_ + hh) * HD_ + c * 32;
    #pragma unroll
    for (int d4 = 0; d4 < 8; d4++) {
        *(float4*)(Op + d4 * 4) = make_float4(tf32r(o[d4 * 4 + 0] * inv),
                                              tf32r(o[d4 * 4 + 1] * inv),
                                              tf32r(o[d4 * 4 + 2] * inv),
                                              tf32r(o[d4 * 4 + 3] * inv));
    }
}

// ---------------------------------------------------------------------------
// launch
// ---------------------------------------------------------------------------
extern "C" void kernel_launch(void* const* d_in, const int* in_sizes, int n_in,
                              void* d_out, int out_size) {
    const float* x     = (const float*)d_in[0];
    const float* freqs = (const float*)d_in[2];
    const float* w_qkv = (const float*)d_in[4];
    const float* w_fc  = (const float*)d_in[5];
    const float* w1    = (const float*)d_in[6];
    const float* w2    = (const float*)d_in[7];
    const float* w3    = (const float*)d_in[8];
    const float* anw   = (const float*)d_in[9];
    const float* fnw   = (const float*)d_in[10];
    float* out = (float*)d_out;

    float *hnorm, *qkv, *q, *k, *v, *attn, *h, *ffh;
    cudaGetSymbolAddress((void**)&hnorm, g_hnorm);
    cudaGetSymbolAddress((void**)&qkv,   g_qkv);
    cudaGetSymbolAddress((void**)&q,     g_q);
    cudaGetSymbolAddress((void**)&k,     g_kbuf);
    cudaGetSymbolAddress((void**)&v,     g_vbuf);
    cudaGetSymbolAddress((void**)&attn,  g_attn);
    cudaGetSymbolAddress((void**)&h,     g_h);
    cudaGetSymbolAddress((void**)&ffh,   g_ffh);

    static bool attr_done = false;
    if (!attr_done) {
        cudaFuncSetAttribute(tgemm_k<0>, cudaFuncAttributeMaxDynamicSharedMemorySize, GEMM_SMEM);
        cudaFuncSetAttribute(tgemm_k<1>, cudaFuncAttributeMaxDynamicSharedMemorySize, GEMM_SMEM);
        cudaFuncSetAttribute(tgemm_k<2>, cudaFuncAttributeMaxDynamicSharedMemorySize, GEMM_SMEM);
        cudaFuncSetAttribute(attn_k, cudaFuncAttributeMaxDynamicSharedMemorySize, ATTN_SMEM);
        attr_done = true;
    }

    // 1. h_norm = tf32(rmsnorm(x) * attn_norm_w)
    rmsnorm_k<<<T_, 256>>>(x, anw, hnorm);
    // 2. qkv = h_norm @ w_qkv^T
    tgemm_k<0><<<dim3(QKV_N / 128, T_ / 128), 256, GEMM_SMEM>>>(hnorm, w_qkv, nullptr,
                                                                nullptr, qkv, T_, QKV_N, E_);
    // 3. RoPE + split
    rope_split_k<<<T_, 256>>>(qkv, freqs, q, k, v);
    // 4. causal flash attention (fp32)
    attn_k<<<dim3(S_ / 64, NH_, B_), 256, ATTN_SMEM>>>(q, k, v, attn);
    // 5. h = x + attn @ w_fc^T
    tgemm_k<1><<<dim3(E_ / 128, T_ / 128), 256, GEMM_SMEM>>>(attn, w_fc, nullptr, x,
                                                             h, T_, E_, E_);
    // 6. g = tf32(rmsnorm(h) * ff_norm_w)
    rmsnorm_k<<<T_, 256>>>(h, fnw, hnorm);
    // 7. ffh = tf32( silu(g @ w1^T) * (g @ w2^T) )
    tgemm_k<2><<<dim3(FF_ / 64, T_ / 128), 256, GEMM_SMEM>>>(hnorm, w1, w2, nullptr,
                                                             ffh, T_, FF_, E_);
    // 8. out = h + ffh @ w3^T
    tgemm_k<1><<<dim3(E_ / 128, T_ / 128), 256, GEMM_SMEM>>>(ffh, w3, nullptr, h,
                                                             out, T_, E_, FF_);
}

// round 7
// speedup vs baseline: 1.5340x; 1.0084x over previous
#include <cuda_runtime.h>
#include <cuda_bf16.h>
#include <math.h>
#include <stdint.h>

// ---------------------------------------------------------------------------
// DecoderLayer: B=2, S=2048, E=2048, NH=16, NKV=4, HD=128, FF=5632
// Round 4: tf32 mma.sync GEMMs, XOR-swizzled smem (32KB/stage), 3-stage
// cp.async pipeline, 2 CTAs/SM. In-kernel B-fragment tf32 rounding (no
// weight pre-pass). Attention: fp32 CUDA-core flash.
// ---------------------------------------------------------------------------

#define B_    2
#define S_    2048
#define E_    2048
#define NH_   16
#define NKV_  4
#define HD_   128
#define FF_   5632
#define T_    (B_ * S_)
#define QKV_N ((NH_ + 2 * NKV_) * HD_)  // 3072

// scratch (device globals; allocation-free)
__device__ float g_hnorm[(size_t)T_ * E_];
__device__ float g_qkv  [(size_t)T_ * QKV_N];
__device__ float g_q    [(size_t)B_ * NH_  * S_ * HD_];
__device__ float g_kbuf [(size_t)B_ * NKV_ * S_ * HD_];
__device__ float g_vbuf [(size_t)B_ * NKV_ * S_ * HD_];
__device__ float g_attn [(size_t)T_ * E_];
__device__ float g_h    [(size_t)T_ * E_];
__device__ float g_ffh  [(size_t)T_ * FF_];

// ---------------------------------------------------------------------------
__device__ __forceinline__ uint32_t smem_u32(const void* p) {
    uint32_t a;
    asm("{ .reg .u64 t; cvta.to.shared.u64 t, %1; cvt.u32.u64 %0, t; }"
        : "=r"(a) : "l"(p));
    return a;
}

__device__ __forceinline__ float tf32r(float x) {
    uint32_t u;
    asm("cvt.rna.tf32.f32 %0, %1;" : "=r"(u) : "f"(x));
    return __uint_as_float(u);
}

__device__ __forceinline__ uint32_t tf32r_u(float x) {
    uint32_t u;
    asm("cvt.rna.tf32.f32 %0, %1;" : "=r"(u) : "f"(x));
    return u;
}

#define CP_COMMIT() asm volatile("cp.async.commit_group;" ::: "memory")
#define CP_WAIT_0() asm volatile("cp.async.wait_group 0;" ::: "memory")
#define CP_WAIT_1() asm volatile("cp.async.wait_group 1;" ::: "memory")

__device__ __forceinline__ void mma_tf32(float* c, const uint32_t* a,
                                         const uint32_t* b) {
    asm volatile(
        "mma.sync.aligned.m16n8k8.row.col.f32.tf32.tf32.f32 "
        "{%0,%1,%2,%3}, {%4,%5,%6,%7}, {%8,%9}, {%0,%1,%2,%3};"
        : "+f"(c[0]), "+f"(c[1]), "+f"(c[2]), "+f"(c[3])
        : "r"(a[0]), "r"(a[1]), "r"(a[2]), "r"(a[3]), "r"(b[0]), "r"(b[1]));
}

// ---------------------------------------------------------------------------
// RMSNorm (output rounded to tf32: feeds GEMM-A only)
// ---------------------------------------------------------------------------
__global__ void __launch_bounds__(256) rmsnorm_k(const float* __restrict__ x,
                                                 const float* __restrict__ w,
                                                 float* __restrict__ o) {
    size_t base = (size_t)blockIdx.x * E_;
    int tid = threadIdx.x;
    float4 v0 = *(const float4*)(x + base + tid * 4);
    float4 v1 = *(const float4*)(x + base + 1024 + tid * 4);
    float ss = v0.x*v0.x + v0.y*v0.y + v0.z*v0.z + v0.w*v0.w
             + v1.x*v1.x + v1.y*v1.y + v1.z*v1.z + v1.w*v1.w;
    #pragma unroll
    for (int off = 16; off; off >>= 1) ss += __shfl_xor_sync(0xffffffffu, ss, off);
    __shared__ float ws[8];
    if ((tid & 31) == 0) ws[tid >> 5] = ss;
    __syncthreads();
    float tot = ws[0] + ws[1] + ws[2] + ws[3] + ws[4] + ws[5] + ws[6] + ws[7];
    float sc = rsqrtf(tot * (1.0f / E_) + 1e-5f);
    float4 w0 = *(const float4*)(w + tid * 4);
    float4 w1w = *(const float4*)(w + 1024 + tid * 4);
    float4 r0 = make_float4(tf32r(v0.x*sc*w0.x),  tf32r(v0.y*sc*w0.y),
                            tf32r(v0.z*sc*w0.z),  tf32r(v0.w*sc*w0.w));
    float4 r1 = make_float4(tf32r(v1.x*sc*w1w.x), tf32r(v1.y*sc*w1w.y),
                            tf32r(v1.z*sc*w1w.z), tf32r(v1.w*sc*w1w.w));
    *(float4*)(o + base + tid * 4)        = r0;
    *(float4*)(o + base + 1024 + tid * 4) = r1;
}

// ---------------------------------------------------------------------------
// mma.sync tf32 GEMM: C[M,N] = A[M,K] * B[N,K]^T, tile 128 x BN, BK=32.
// MODE 0: C = A·B^T                        (BN = 128)
// MODE 1: C = R + A·B^T                    (BN = 128)
// MODE 2: C = tf32r(silu(A·B^T)*(A·B2^T))  (BN = 64; B rows 64..127 = B2)
// 256 threads = 8 warps (4 M x 2 N). 3-stage cp.async, XOR swizzle.
// B fragments rounded to tf32 (RNA) in-register after LDS.
// ---------------------------------------------------------------------------
#define STAGE_F 8192                 // floats per stage: (128 A + 128 B) x 32
#define NSTAGE 3
#define GEMM_SMEM (NSTAGE * STAGE_F * 4)   // 96 KB

// float index of element e (0..31) of row r within a 128-row block
__device__ __forceinline__ int fidx(int r, int g, int tg) {
    return r * 32 + (((g ^ (r & 7)) << 2) | tg);
}

template <int MODE>
__global__ void __launch_bounds__(256, 2) tgemm_k(const float* __restrict__ A,
                                                  const float* __restrict__ Bm,
                                                  const float* __restrict__ B2,
                                                  const float* __restrict__ R,
                                                  float* __restrict__ C,
                                                  int M, int N, int K) {
    extern __shared__ float sm[];
    constexpr int BN = (MODE == 2) ? 64 : 128;
    constexpr int NT = (MODE == 2) ? 4 : 8;   // n-tiles per warp (per B matrix)

    const int tid = threadIdx.x;
    const int m0 = blockIdx.y * 128, n0 = blockIdx.x * BN;

    // loader: 2 threads per row, 4 x 16B chunks each
    const int lrow = tid >> 1;
    const int cbase = (tid & 1) * 4;
    const float* Agp = A + (size_t)(m0 + lrow) * K + cbase * 4;
    const float* Bgp;
    if (MODE == 2)
        Bgp = ((lrow < 64) ? (Bm + (size_t)(n0 + lrow) * K)
                           : (B2 + (size_t)(n0 + lrow - 64) * K)) + cbase * 4;
    else
        Bgp = Bm + (size_t)(n0 + lrow) * K + cbase * 4;

    const uint32_t smb = smem_u32(sm);
    // swizzled dst byte offsets within a 128-row block
    uint32_t dsto[4];
    #pragma unroll
    for (int i = 0; i < 4; i++)
        dsto[i] = (uint32_t)(lrow * 128 + (((cbase + i) ^ (lrow & 7)) << 4));

    auto load_chunk = [&](int s, int c) {
        uint32_t ab = smb + s * (STAGE_F * 4);
        uint32_t bb = ab + 16384;
        const float* ag = Agp + c * 32;
        const float* bg = Bgp + c * 32;
        #pragma unroll
        for (int i = 0; i < 4; i++) {
            asm volatile("cp.async.cg.shared.global [%0], [%1], 16;"
                         :: "r"(ab + dsto[i]), "l"(ag + i * 4) : "memory");
            asm volatile("cp.async.cg.shared.global [%0], [%1], 16;"
                         :: "r"(bb + dsto[i]), "l"(bg + i * 4) : "memory");
        }
        CP_COMMIT();
    };

    const int wid = tid >> 5, lane = tid & 31;
    const int gid = lane >> 2, tg = lane & 3;
    const int wm = wid >> 1, wn = wid & 1;

    float c1[2][NT][4];
    float c2[(MODE == 2) ? 2 : 1][(MODE == 2) ? NT : 1][4];
    #pragma unroll
    for (int mt = 0; mt < 2; mt++)
        #pragma unroll
        for (int nt = 0; nt < NT; nt++)
            #pragma unroll
            for (int q = 0; q < 4; q++) {
                c1[mt][nt][q] = 0.f;
                if (MODE == 2) c2[mt][nt][q] = 0.f;
            }

    const int NC = K >> 5;
    load_chunk(0, 0);
    load_chunk(1, 1);

    int stage = 0, nstage = 2;
    for (int c = 0; c < NC; c++) {
        if (c + 1 < NC) CP_WAIT_1(); else CP_WAIT_0();
        __syncthreads();
        if (c + 2 < NC) {
            load_chunk(nstage, c + 2);
            nstage = (nstage == 2) ? 0 : nstage + 1;
        }

        const float* Ab = sm + stage * STAGE_F;
        const float* Bb = Ab + 4096;
        stage = (stage == 2) ? 0 : stage + 1;

        #pragma unroll
        for (int ks = 0; ks < 4; ks++) {
            const int g0 = 2 * ks, g1 = 2 * ks + 1;
            uint32_t af[2][4];
            #pragma unroll
            for (int mt = 0; mt < 2; mt++) {
                int ra = wm * 32 + mt * 16 + gid;
                af[mt][0] = __float_as_uint(Ab[fidx(ra,     g0, tg)]);
                af[mt][1] = __float_as_uint(Ab[fidx(ra + 8, g0, tg)]);
                af[mt][2] = __float_as_uint(Ab[fidx(ra,     g1, tg)]);
                af[mt][3] = __float_as_uint(Ab[fidx(ra + 8, g1, tg)]);
            }
            uint32_t bf[NT][2];
            #pragma unroll
            for (int nt = 0; nt < NT; nt++) {
                int rb = wn * (NT * 8) + nt * 8 + gid;
                bf[nt][0] = tf32r_u(Bb[fidx(rb, g0, tg)]);
                bf[nt][1] = tf32r_u(Bb[fidx(rb, g1, tg)]);
            }
            #pragma unroll
            for (int mt = 0; mt < 2; mt++)
                #pragma unroll
                for (int nt = 0; nt < NT; nt++)
                    mma_tf32(c1[mt][nt], af[mt], bf[nt]);
            if (MODE == 2) {
                uint32_t bf2[NT][2];
                #pragma unroll
                for (int nt = 0; nt < NT; nt++) {
                    int rb = 64 + wn * 32 + nt * 8 + gid;
                    bf2[nt][0] = tf32r_u(Bb[fidx(rb, g0, tg)]);
                    bf2[nt][1] = tf32r_u(Bb[fidx(rb, g1, tg)]);
                }
                #pragma unroll
                for (int mt = 0; mt < 2; mt++)
                    #pragma unroll
                    for (int nt = 0; nt < NT; nt++)
                        mma_tf32(c2[mt][nt], af[mt], bf2[nt]);
            }
        }
    }

    // epilogue
    #pragma unroll
    for (int mt = 0; mt < 2; mt++) {
        #pragma unroll
        for (int half = 0; half < 2; half++) {
            size_t row = (size_t)(m0 + wm * 32 + mt * 16 + gid + half * 8);
            #pragma unroll
            for (int nt = 0; nt < NT; nt++) {
                int col = n0 + wn * (NT * 8) + nt * 8 + tg * 2;
                float v0 = c1[mt][nt][half * 2 + 0];
                float v1 = c1[mt][nt][half * 2 + 1];
                if (MODE == 1) {
                    float2 res = *(const float2*)(R + row * N + col);
                    v0 += res.x; v1 += res.y;
                } else if (MODE == 2) {
                    float u0 = c2[mt][nt][half * 2 + 0];
                    float u1 = c2[mt][nt][half * 2 + 1];
                    v0 = tf32r((v0 / (1.0f + __expf(-v0))) * u0);
                    v1 = tf32r((v1 / (1.0f + __expf(-v1))) * u1);
                }
                *(float2*)(C + row * N + col) = make_float2(v0, v1);
            }
        }
    }
}

// ---------------------------------------------------------------------------
// RoPE + QKV split
// ---------------------------------------------------------------------------
__global__ void __launch_bounds__(256) rope_split_k(const float* __restrict__ qkv,
                                                    const float* __restrict__ fc,
                                                    float* __restrict__ q,
                                                    float* __restrict__ k,
                                                    float* __restrict__ v) {
    int t = blockIdx.x;
    int b = t >> 11;
    int s = t & 2047;
    const float* row = qkv + (size_t)t * QKV_N;
    const float* f = fc + (size_t)s * HD_;
    for (int idx = threadIdx.x; idx < NH_ * 64; idx += 256) {
        int h = idx >> 6, i = idx & 63;
        float x0 = row[h * HD_ + 2 * i];
        float x1 = row[h * HD_ + 2 * i + 1];
        float cs = f[2 * i], sn = f[2 * i + 1];
        size_t o = ((size_t)(b * NH_ + h) * S_ + s) * HD_ + 2 * i;
        q[o]     = x0 * cs - x1 * sn;
        q[o + 1] = x1 * cs + x0 * sn;
    }
    for (int idx = threadIdx.x; idx < NKV_ * 64; idx += 256) {
        int h = idx >> 6, i = idx & 63;
        float x0 = row[NH_ * HD_ + h * HD_ + 2 * i];
        float x1 = row[NH_ * HD_ + h * HD_ + 2 * i + 1];
        float cs = f[2 * i], sn = f[2 * i + 1];
        size_t o = ((size_t)(b * NKV_ + h) * S_ + s) * HD_ + 2 * i;
        k[o]     = x0 * cs - x1 * sn;
        k[o + 1] = x1 * cs + x0 * sn;
    }
    for (int idx = threadIdx.x; idx < NKV_ * HD_; idx += 256) {
        int h = idx >> 7, d = idx & 127;
        v[((size_t)(b * NKV_ + h) * S_ + s) * HD_ + d] =
            row[(NH_ + NKV_) * HD_ + idx];
    }
}

// ---------------------------------------------------------------------------
// Flash attention, fp32 (output rounded to tf32: feeds GEMM-A)
// ---------------------------------------------------------------------------
#define QSTR 132
#define PSTR 65
#define ATTN_SMEM ((2 * 64 * QSTR + 64 * PSTR) * 4)

__global__ void __launch_bounds__(256) attn_k(const float* __restrict__ Q,
                                              const float* __restrict__ Kt,
                                              const float* __restrict__ V,
                                              float* __restrict__ O) {
    extern __shared__ float smf[];
    float* Qs  = smf;
    float* KVs = smf + 64 * QSTR;
    float* Ps  = smf + 2 * 64 * QSTR;

    int tid = threadIdx.x;
    int qt = blockIdx.x, hh = blockIdx.y, b = blockIdx.z;
    int q0 = qt * 64;
    const float* Qp = Q  + (size_t)(b * NH_  + hh)        * S_ * HD_;
    const float* Kp = Kt + (size_t)(b * NKV_ + (hh >> 2)) * S_ * HD_;
    const float* Vp = V  + (size_t)(b * NKV_ + (hh >> 2)) * S_ * HD_;

    int r = tid >> 2, c = tid & 3;
    int qi = q0 + r;

    for (int idx = tid; idx < 64 * 32; idx += 256) {
        int row = idx >> 5, d4 = idx & 31;
        *(float4*)&Qs[row * QSTR + d4 * 4] =
            *(const float4*)(Qp + (size_t)(q0 + row) * HD_ + d4 * 4);
    }

    float o[32];
    #pragma unroll
    for (int d = 0; d < 32; d++) o[d] = 0.f;
    float m = -1e30f, l = 0.f;
    const float scale = 0.022097086912079608f;

    for (int kt = 0; kt <= qt; kt++) {
        int k0 = kt * 64;
        for (int idx = tid; idx < 64 * 32; idx += 256) {
            int row = idx >> 5, d4 = idx & 31;
            *(float4*)&KVs[row * QSTR + d4 * 4] =
                *(const float4*)(Kp + (size_t)(k0 + row) * HD_ + d4 * 4);
        }
        __syncthreads();

        float acc[16];
        #pragma unroll
        for (int jj = 0; jj < 16; jj++) acc[jj] = 0.f;
        #pragma unroll 4
        for (int d4 = 0; d4 < 32; d4++) {
            float4 qv = *(const float4*)&Qs[r * QSTR + d4 * 4];
            #pragma unroll
            for (int jj = 0; jj < 16; jj++) {
                float4 kv = *(const float4*)&KVs[(c * 16 + jj) * QSTR + d4 * 4];
                acc[jj] = fmaf(qv.x, kv.x, acc[jj]);
                acc[jj] = fmaf(qv.y, kv.y, acc[jj]);
                acc[jj] = fmaf(qv.z, kv.z, acc[jj]);
                acc[jj] = fmaf(qv.w, kv.w, acc[jj]);
            }
        }

        float mt = -1e30f;
        #pragma unroll
        for (int jj = 0; jj < 16; jj++) {
            float s = acc[jj] * scale;
            if (k0 + c * 16 + jj > qi) s = -1e30f;
            acc[jj] = s;
            mt = fmaxf(mt, s);
        }
        mt = fmaxf(mt, __shfl_xor_sync(0xffffffffu, mt, 1));
        mt = fmaxf(mt, __shfl_xor_sync(0xffffffffu, mt, 2));
        float mnew = fmaxf(m, mt);
        float fac = __expf(m - mnew);
        float ls = 0.f;
        #pragma unroll
        for (int jj = 0; jj < 16; jj++) {
            float p = __expf(acc[jj] - mnew);
            ls += p;
            Ps[r * PSTR + c * 16 + jj] = p;
        }
        ls += __shfl_xor_sync(0xffffffffu, ls, 1);
        ls += __shfl_xor_sync(0xffffffffu, ls, 2);
        l = l * fac + ls;
        m = mnew;
        #pragma unroll
        for (int d = 0; d < 32; d++) o[d] *= fac;
        __syncthreads();

        for (int idx = tid; idx < 64 * 32; idx += 256) {
            int row = idx >> 5, d4 = idx & 31;
            *(float4*)&KVs[row * QSTR + d4 * 4] =
                *(const float4*)(Vp + (size_t)(k0 + row) * HD_ + d4 * 4);
        }
        __syncthreads();

        #pragma unroll 4
        for (int j = 0; j < 64; j++) {
            float p = Ps[r * PSTR + j];
            #pragma unroll
            for (int d4 = 0; d4 < 8; d4++) {
                float4 vv = *(const float4*)&KVs[j * QSTR + c * 32 + d4 * 4];
                o[d4 * 4 + 0] = fmaf(p, vv.x, o[d4 * 4 + 0]);
                o[d4 * 4 + 1] = fmaf(p, vv.y, o[d4 * 4 + 1]);
                o[d4 * 4 + 2] = fmaf(p, vv.z, o[d4 * 4 + 2]);
                o[d4 * 4 + 3] = fmaf(p, vv.w, o[d4 * 4 + 3]);
            }
        }
        __syncthreads();
    }

    float inv = 1.0f / l;
    float* Op = O + (((size_t)b * S_ + qi) * NH_ + hh) * HD_ + c * 32;
    #pragma unroll
    for (int d4 = 0; d4 < 8; d4++) {
        *(float4*)(Op + d4 * 4) = make_float4(tf32r(o[d4 * 4 + 0] * inv),
                                              tf32r(o[d4 * 4 + 1] * inv),
                                              tf32r(o[d4 * 4 + 2] * inv),
                                              tf32r(o[d4 * 4 + 3] * inv));
    }
}

// ---------------------------------------------------------------------------
// launch
// ---------------------------------------------------------------------------
extern "C" void kernel_launch(void* const* d_in, const int* in_sizes, int n_in,
                              void* d_out, int out_size) {
    const float* x     = (const float*)d_in[0];
    const float* freqs = (const float*)d_in[2];
    const float* w_qkv = (const float*)d_in[4];
    const float* w_fc  = (const float*)d_in[5];
    const float* w1    = (const float*)d_in[6];
    const float* w2    = (const float*)d_in[7];
    const float* w3    = (const float*)d_in[8];
    const float* anw   = (const float*)d_in[9];
    const float* fnw   = (const float*)d_in[10];
    float* out = (float*)d_out;

    float *hnorm, *qkv, *q, *k, *v, *attn, *h, *ffh;
    cudaGetSymbolAddress((void**)&hnorm, g_hnorm);
    cudaGetSymbolAddress((void**)&qkv,   g_qkv);
    cudaGetSymbolAddress((void**)&q,     g_q);
    cudaGetSymbolAddress((void**)&k,     g_kbuf);
    cudaGetSymbolAddress((void**)&v,     g_vbuf);
    cudaGetSymbolAddress((void**)&attn,  g_attn);
    cudaGetSymbolAddress((void**)&h,     g_h);
    cudaGetSymbolAddress((void**)&ffh,   g_ffh);

    static bool attr_done = false;
    if (!attr_done) {
        cudaFuncSetAttribute(tgemm_k<0>, cudaFuncAttributeMaxDynamicSharedMemorySize, GEMM_SMEM);
        cudaFuncSetAttribute(tgemm_k<1>, cudaFuncAttributeMaxDynamicSharedMemorySize, GEMM_SMEM);
        cudaFuncSetAttribute(tgemm_k<2>, cudaFuncAttributeMaxDynamicSharedMemorySize, GEMM_SMEM);
        cudaFuncSetAttribute(attn_k, cudaFuncAttributeMaxDynamicSharedMemorySize, ATTN_SMEM);
        attr_done = true;
    }

    // 1. h_norm = tf32(rmsnorm(x) * attn_norm_w)
    rmsnorm_k<<<T_, 256>>>(x, anw, hnorm);
    // 2. qkv = h_norm @ w_qkv^T
    tgemm_k<0><<<dim3(QKV_N / 128, T_ / 128), 256, GEMM_SMEM>>>(hnorm, w_qkv, nullptr,
                                                                nullptr, qkv, T_, QKV_N, E_);
    // 3. RoPE + split
    rope_split_k<<<T_, 256>>>(qkv, freqs, q, k, v);
    // 4. causal flash attention (fp32)
    attn_k<<<dim3(S_ / 64, NH_, B_), 256, ATTN_SMEM>>>(q, k, v, attn);
    // 5. h = x + attn @ w_fc^T
    tgemm_k<1><<<dim3(E_ / 128, T_ / 128), 256, GEMM_SMEM>>>(attn, w_fc, nullptr, x,
                                                             h, T_, E_, E_);
    // 6. g = tf32(rmsnorm(h) * ff_norm_w)
    rmsnorm_k<<<T_, 256>>>(h, fnw, hnorm);
    // 7. ffh = tf32( silu(g @ w1^T) * (g @ w2^T) )
    tgemm_k<2><<<dim3(FF_ / 64, T_ / 128), 256, GEMM_SMEM>>>(hnorm, w1, w2, nullptr,
                                                             ffh, T_, FF_, E_);
    // 8. out = h + ffh @ w3^T
    tgemm_k<1><<<dim3(E_ / 128, T_ / 128), 256, GEMM_SMEM>>>(ffh, w3, nullptr, h,
                                                             out, T_, E_, FF_);
}

// round 8
// speedup vs baseline: 1.7553x; 1.1443x over previous
#include <cuda_runtime.h>
#include <cuda_fp16.h>
#include <math.h>
#include <stdint.h>

// ---------------------------------------------------------------------------
// DecoderLayer: B=2, S=2048, E=2048, NH=16, NKV=4, HD=128, FF=5632
// Round 7: GEMMs on fp16 mma.sync m16n8k16 (same 11-bit significand as tf32,
// 2x flop/instr, half smem traffic). BK=64, 3-stage cp.async, XOR swizzle.
// Attention stays fp32 CUDA-core flash (known good), now emitting half.
// ---------------------------------------------------------------------------

#define B_    2
#define S_    2048
#define E_    2048
#define NH_   16
#define NKV_  4
#define HD_   128
#define FF_   5632
#define T_    (B_ * S_)
#define QKV_N ((NH_ + 2 * NKV_) * HD_)  // 3072

// scratch (device globals; allocation-free)
__device__ float  g_qkv  [(size_t)T_ * QKV_N];
__device__ float  g_h    [(size_t)T_ * E_];
__device__ float  g_q    [(size_t)B_ * NH_  * S_ * HD_];
__device__ float  g_kbuf [(size_t)B_ * NKV_ * S_ * HD_];
__device__ float  g_vbuf [(size_t)B_ * NKV_ * S_ * HD_];
__device__ __half g_hnorm[(size_t)T_ * E_];
__device__ __half g_attnh[(size_t)T_ * E_];
__device__ __half g_ffh  [(size_t)T_ * FF_];
__device__ __half g_wqkvh[(size_t)QKV_N * E_];
__device__ __half g_wfch [(size_t)E_ * E_];
__device__ __half g_w1h  [(size_t)FF_ * E_];
__device__ __half g_w2h  [(size_t)FF_ * E_];
__device__ __half g_w3h  [(size_t)E_ * FF_];

// ---------------------------------------------------------------------------
__device__ __forceinline__ uint32_t smem_u32(const void* p) {
    uint32_t a;
    asm("{ .reg .u64 t; cvta.to.shared.u64 t, %1; cvt.u32.u64 %0, t; }"
        : "=r"(a) : "l"(p));
    return a;
}
__device__ __forceinline__ uint32_t lds32(uint32_t addr) {
    uint32_t v;
    asm volatile("ld.shared.b32 %0, [%1];" : "=r"(v) : "r"(addr));
    return v;
}
__device__ __forceinline__ uint32_t packh2(float a, float b) {
    __half2 h = __floats2half2_rn(a, b);
    return *reinterpret_cast<uint32_t*>(&h);
}
#define CP_COMMIT() asm volatile("cp.async.commit_group;" ::: "memory")
#define CP_WAIT_0() asm volatile("cp.async.wait_group 0;" ::: "memory")
#define CP_WAIT_1() asm volatile("cp.async.wait_group 1;" ::: "memory")

__device__ __forceinline__ void mma_f16(float* c, const uint32_t* a,
                                        uint32_t b0, uint32_t b1) {
    asm volatile(
        "mma.sync.aligned.m16n8k16.row.col.f32.f16.f16.f32 "
        "{%0,%1,%2,%3}, {%4,%5,%6,%7}, {%8,%9}, {%0,%1,%2,%3};"
        : "+f"(c[0]), "+f"(c[1]), "+f"(c[2]), "+f"(c[3])
        : "r"(a[0]), "r"(a[1]), "r"(a[2]), "r"(a[3]), "r"(b0), "r"(b1));
}

// ---------------------------------------------------------------------------
// fp32 -> fp16 weight conversion
// ---------------------------------------------------------------------------
__global__ void __launch_bounds__(256) cvt_half_k(const float* __restrict__ s,
                                                  __half* __restrict__ d, int n4) {
    int i = blockIdx.x * 256 + threadIdx.x;
    if (i < n4) {
        float4 v = ((const float4*)s)[i];
        uint2 o;
        o.x = packh2(v.x, v.y);
        o.y = packh2(v.z, v.w);
        ((uint2*)d)[i] = o;
    }
}

// ---------------------------------------------------------------------------
// RMSNorm: fp32 in, fp16 out
// ---------------------------------------------------------------------------
__global__ void __launch_bounds__(256) rmsnorm_k(const float* __restrict__ x,
                                                 const float* __restrict__ w,
                                                 __half* __restrict__ o) {
    size_t base = (size_t)blockIdx.x * E_;
    int tid = threadIdx.x;
    float4 v0 = *(const float4*)(x + base + tid * 8);
    float4 v1 = *(const float4*)(x + base + tid * 8 + 4);
    float ss = v0.x*v0.x + v0.y*v0.y + v0.z*v0.z + v0.w*v0.w
             + v1.x*v1.x + v1.y*v1.y + v1.z*v1.z + v1.w*v1.w;
    #pragma unroll
    for (int off = 16; off; off >>= 1) ss += __shfl_xor_sync(0xffffffffu, ss, off);
    __shared__ float ws[8];
    if ((tid & 31) == 0) ws[tid >> 5] = ss;
    __syncthreads();
    float tot = ws[0] + ws[1] + ws[2] + ws[3] + ws[4] + ws[5] + ws[6] + ws[7];
    float sc = rsqrtf(tot * (1.0f / E_) + 1e-5f);
    float4 w0 = *(const float4*)(w + tid * 8);
    float4 w1w = *(const float4*)(w + tid * 8 + 4);
    uint4 r;
    r.x = packh2(v0.x*sc*w0.x,  v0.y*sc*w0.y);
    r.y = packh2(v0.z*sc*w0.z,  v0.w*sc*w0.w);
    r.z = packh2(v1.x*sc*w1w.x, v1.y*sc*w1w.y);
    r.w = packh2(v1.z*sc*w1w.z, v1.w*sc*w1w.w);
    *(uint4*)(o + base + tid * 8) = r;
}

// ---------------------------------------------------------------------------
// fp16 GEMM: C[M,N] = A[M,K] * B[N,K]^T, tile 128 x BN, BK=64, 3-stage.
// MODE 0: C(f32) = A·B^T                  (BN = 128)
// MODE 1: C(f32) = R + A·B^T              (BN = 128)
// MODE 2: C(f16) = silu(A·B^T)*(A·B2^T)   (BN = 64; B rows 64..127 = B2)
// 256 threads = 8 warps (4 M x 2 N). Rows: 64 halves = 128 B, XOR-swizzled
// at 16B-chunk granularity.
// ---------------------------------------------------------------------------
#define GBLK 16384                     // bytes per 128-row half block
#define GSTAGE (2 * GBLK)              // A block + B block = 32768
#define GEMM_SMEM (3 * GSTAGE)         // 98304

__device__ __forceinline__ uint32_t coff(int r, int ch, int tg) {
    return (uint32_t)(r * 128 + ((ch ^ (r & 7)) << 4) + tg * 4);
}

template <int MODE>
__global__ void __launch_bounds__(256, 2) tgemm_k(const __half* __restrict__ A,
                                                  const __half* __restrict__ Bm,
                                                  const __half* __restrict__ B2,
                                                  const float* __restrict__ R,
                                                  void* __restrict__ Cout,
                                                  int M, int N, int K) {
    extern __shared__ char sm[];
    constexpr int BN = (MODE == 2) ? 64 : 128;
    constexpr int NT = (MODE == 2) ? 4 : 8;

    const int tid = threadIdx.x;
    const int m0 = blockIdx.y * 128, n0 = blockIdx.x * BN;

    // loader: 2 threads/row, 4 x 16B chunks each (row = 64 halves)
    const int lrow = tid >> 1;
    const int ci0 = (tid & 1) * 4;
    const __half* Ag = A + (size_t)(m0 + lrow) * K + ci0 * 8;
    const __half* Bg;
    if (MODE == 2)
        Bg = ((lrow < 64) ? (Bm + (size_t)(n0 + lrow) * K)
                          : (B2 + (size_t)(n0 + lrow - 64) * K)) + ci0 * 8;
    else
        Bg = Bm + (size_t)(n0 + lrow) * K + ci0 * 8;

    const uint32_t smb = smem_u32(sm);
    uint32_t dsto[4];
    #pragma unroll
    for (int i = 0; i < 4; i++)
        dsto[i] = (uint32_t)(lrow * 128 + (((ci0 + i) ^ (lrow & 7)) << 4));

    auto load_chunk = [&](int st, int c) {
        const __half* a = Ag + c * 64;
        const __half* b = Bg + c * 64;
        uint32_t ab = smb + st * GSTAGE;
        uint32_t bb = ab + GBLK;
        #pragma unroll
        for (int i = 0; i < 4; i++) {
            asm volatile("cp.async.cg.shared.global [%0], [%1], 16;"
                         :: "r"(ab + dsto[i]), "l"(a + i * 8) : "memory");
            asm volatile("cp.async.cg.shared.global [%0], [%1], 16;"
                         :: "r"(bb + dsto[i]), "l"(b + i * 8) : "memory");
        }
        CP_COMMIT();
    };

    const int wid = tid >> 5, lane = tid & 31;
    const int gid = lane >> 2, tg = lane & 3;
    const int wm = wid >> 1, wn = wid & 1;

    float c1[2][NT][4];
    float c2[(MODE == 2) ? 2 : 1][(MODE == 2) ? NT : 1][4];
    #pragma unroll
    for (int mt = 0; mt < 2; mt++)
        #pragma unroll
        for (int nt = 0; nt < NT; nt++)
            #pragma unroll
            for (int q = 0; q < 4; q++) {
                c1[mt][nt][q] = 0.f;
                if (MODE == 2) c2[mt][nt][q] = 0.f;
            }

    const int NC = K >> 6;
    load_chunk(0, 0);
    load_chunk(1, 1);

    for (int c = 0; c < NC; c++) {
        if (c + 1 < NC) CP_WAIT_1(); else CP_WAIT_0();
        __syncthreads();
        if (c + 2 < NC) load_chunk((c + 2) % 3, c + 2);

        const uint32_t ab = smb + (c % 3) * GSTAGE;
        const uint32_t bb = ab + GBLK;
        #pragma unroll
        for (int ks = 0; ks < 4; ks++) {
            uint32_t af[2][4];
            #pragma unroll
            for (int mt = 0; mt < 2; mt++) {
                int ra = wm * 32 + mt * 16 + gid;
                af[mt][0] = lds32(ab + coff(ra,     2 * ks,     tg));
                af[mt][1] = lds32(ab + coff(ra + 8, 2 * ks,     tg));
                af[mt][2] = lds32(ab + coff(ra,     2 * ks + 1, tg));
                af[mt][3] = lds32(ab + coff(ra + 8, 2 * ks + 1, tg));
            }
            uint32_t bf[NT][2];
            #pragma unroll
            for (int nt = 0; nt < NT; nt++) {
                int rb = wn * (NT * 8) + nt * 8 + gid;
                bf[nt][0] = lds32(bb + coff(rb, 2 * ks,     tg));
                bf[nt][1] = lds32(bb + coff(rb, 2 * ks + 1, tg));
            }
            #pragma unroll
            for (int mt = 0; mt < 2; mt++)
                #pragma unroll
                for (int nt = 0; nt < NT; nt++)
                    mma_f16(c1[mt][nt], af[mt], bf[nt][0], bf[nt][1]);
            if (MODE == 2) {
                uint32_t bf2[NT][2];
                #pragma unroll
                for (int nt = 0; nt < NT; nt++) {
                    int rb = 64 + wn * 32 + nt * 8 + gid;
                    bf2[nt][0] = lds32(bb + coff(rb, 2 * ks,     tg));
                    bf2[nt][1] = lds32(bb + coff(rb, 2 * ks + 1, tg));
                }
                #pragma unroll
                for (int mt = 0; mt < 2; mt++)
                    #pragma unroll
                    for (int nt = 0; nt < NT; nt++)
                        mma_f16(c2[mt][nt], af[mt], bf2[nt][0], bf2[nt][1]);
            }
        }
    }

    // epilogue
    #pragma unroll
    for (int mt = 0; mt < 2; mt++) {
        #pragma unroll
        for (int half = 0; half < 2; half++) {
            size_t row = (size_t)(m0 + wm * 32 + mt * 16 + gid + half * 8);
            #pragma unroll
            for (int nt = 0; nt < NT; nt++) {
                int col = n0 + wn * (NT * 8) + nt * 8 + tg * 2;
                float v0 = c1[mt][nt][half * 2 + 0];
                float v1 = c1[mt][nt][half * 2 + 1];
                if (MODE == 2) {
                    float u0 = c2[mt][nt][half * 2 + 0];
                    float u1 = c2[mt][nt][half * 2 + 1];
                    v0 = (v0 / (1.0f + __expf(-v0))) * u0;
                    v1 = (v1 / (1.0f + __expf(-v1))) * u1;
                    *(uint32_t*)((__half*)Cout + row * N + col) = packh2(v0, v1);
                } else {
                    if (MODE == 1) {
                        float2 res = *(const float2*)(R + row * N + col);
                        v0 += res.x; v1 += res.y;
                    }
                    *(float2*)((float*)Cout + row * N + col) = make_float2(v0, v1);
                }
            }
        }
    }
}

// ---------------------------------------------------------------------------
// RoPE + QKV split (fp32 out; attention stays fp32)
// ---------------------------------------------------------------------------
__global__ void __launch_bounds__(256) rope_split_k(const float* __restrict__ qkv,
                                                    const float* __restrict__ fc,
                                                    float* __restrict__ q,
                                                    float* __restrict__ k,
                                                    float* __restrict__ v) {
    int t = blockIdx.x;
    int b = t >> 11;
    int s = t & 2047;
    const float* row = qkv + (size_t)t * QKV_N;
    const float* f = fc + (size_t)s * HD_;
    for (int idx = threadIdx.x; idx < NH_ * 64; idx += 256) {
        int h = idx >> 6, i = idx & 63;
        float x0 = row[h * HD_ + 2 * i];
        float x1 = row[h * HD_ + 2 * i + 1];
        float cs = f[2 * i], sn = f[2 * i + 1];
        size_t o = ((size_t)(b * NH_ + h) * S_ + s) * HD_ + 2 * i;
        q[o]     = x0 * cs - x1 * sn;
        q[o + 1] = x1 * cs + x0 * sn;
    }
    for (int idx = threadIdx.x; idx < NKV_ * 64; idx += 256) {
        int h = idx >> 6, i = idx & 63;
        float x0 = row[NH_ * HD_ + h * HD_ + 2 * i];
        float x1 = row[NH_ * HD_ + h * HD_ + 2 * i + 1];
        float cs = f[2 * i], sn = f[2 * i + 1];
        size_t o = ((size_t)(b * NKV_ + h) * S_ + s) * HD_ + 2 * i;
        k[o]     = x0 * cs - x1 * sn;
        k[o + 1] = x1 * cs + x0 * sn;
    }
    for (int idx = threadIdx.x; idx < NKV_ * HD_; idx += 256) {
        int h = idx >> 7, d = idx & 127;
        v[((size_t)(b * NKV_ + h) * S_ + s) * HD_ + d] =
            row[(NH_ + NKV_) * HD_ + idx];
    }
}

// ---------------------------------------------------------------------------
// Flash attention, fp32 compute, fp16 output (feeds GEMM-A)
// ---------------------------------------------------------------------------
#define QSTR 132
#define PSTR 65
#define ATTN_SMEM ((2 * 64 * QSTR + 64 * PSTR) * 4)

__global__ void __launch_bounds__(256) attn_k(const float* __restrict__ Q,
                                              const float* __restrict__ Kt,
                                              const float* __restrict__ V,
                                              __half* __restrict__ O) {
    extern __shared__ float smf[];
    float* Qs  = smf;
    float* KVs = smf + 64 * QSTR;
    float* Ps  = smf + 2 * 64 * QSTR;

    int tid = threadIdx.x;
    int qt = blockIdx.x, hh = blockIdx.y, b = blockIdx.z;
    int q0 = qt * 64;
    const float* Qp = Q  + (size_t)(b * NH_  + hh)        * S_ * HD_;
    const float* Kp = Kt + (size_t)(b * NKV_ + (hh >> 2)) * S_ * HD_;
    const float* Vp = V  + (size_t)(b * NKV_ + (hh >> 2)) * S_ * HD_;

    int r = tid >> 2, c = tid & 3;
    int qi = q0 + r;

    for (int idx = tid; idx < 64 * 32; idx += 256) {
        int row = idx >> 5, d4 = idx & 31;
        *(float4*)&Qs[row * QSTR + d4 * 4] =
            *(const float4*)(Qp + (size_t)(q0 + row) * HD_ + d4 * 4);
    }

    float o[32];
    #pragma unroll
    for (int d = 0; d < 32; d++) o[d] = 0.f;
    float m = -1e30f, l = 0.f;
    const float scale = 0.022097086912079608f;  // 1/sqrt(2048)

    for (int kt = 0; kt <= qt; kt++) {
        int k0 = kt * 64;
        for (int idx = tid; idx < 64 * 32; idx += 256) {
            int row = idx >> 5, d4 = idx & 31;
            *(float4*)&KVs[row * QSTR + d4 * 4] =
                *(const float4*)(Kp + (size_t)(k0 + row) * HD_ + d4 * 4);
        }
        __syncthreads();

        float acc[16];
        #pragma unroll
        for (int jj = 0; jj < 16; jj++) acc[jj] = 0.f;
        #pragma unroll 4
        for (int d4 = 0; d4 < 32; d4++) {
            float4 qv = *(const float4*)&Qs[r * QSTR + d4 * 4];
            #pragma unroll
            for (int jj = 0; jj < 16; jj++) {
                float4 kv = *(const float4*)&KVs[(c * 16 + jj) * QSTR + d4 * 4];
                acc[jj] = fmaf(qv.x, kv.x, acc[jj]);
                acc[jj] = fmaf(qv.y, kv.y, acc[jj]);
                acc[jj] = fmaf(qv.z, kv.z, acc[jj]);
                acc[jj] = fmaf(qv.w, kv.w, acc[jj]);
            }
        }

        float mt = -1e30f;
        #pragma unroll
        for (int jj = 0; jj < 16; jj++) {
            float s = acc[jj] * scale;
            if (k0 + c * 16 + jj > qi) s = -1e30f;
            acc[jj] = s;
            mt = fmaxf(mt, s);
        }
        mt = fmaxf(mt, __shfl_xor_sync(0xffffffffu, mt, 1));
        mt = fmaxf(mt, __shfl_xor_sync(0xffffffffu, mt, 2));
        float mnew = fmaxf(m, mt);
        float fac = __expf(m - mnew);
        float ls = 0.f;
        #pragma unroll
        for (int jj = 0; jj < 16; jj++) {
            float p = __expf(acc[jj] - mnew);
            ls += p;
            Ps[r * PSTR + c * 16 + jj] = p;
        }
        ls += __shfl_xor_sync(0xffffffffu, ls, 1);
        ls += __shfl_xor_sync(0xffffffffu, ls, 2);
        l = l * fac + ls;
        m = mnew;
        #pragma unroll
        for (int d = 0; d < 32; d++) o[d] *= fac;
        __syncthreads();

        for (int idx = tid; idx < 64 * 32; idx += 256) {
            int row = idx >> 5, d4 = idx & 31;
            *(float4*)&KVs[row * QSTR + d4 * 4] =
                *(const float4*)(Vp + (size_t)(k0 + row) * HD_ + d4 * 4);
        }
        __syncthreads();

        #pragma unroll 4
        for (int j = 0; j < 64; j++) {
            float p = Ps[r * PSTR + j];
            #pragma unroll
            for (int d4 = 0; d4 < 8; d4++) {
                float4 vv = *(const float4*)&KVs[j * QSTR + c * 32 + d4 * 4];
                o[d4 * 4 + 0] = fmaf(p, vv.x, o[d4 * 4 + 0]);
                o[d4 * 4 + 1] = fmaf(p, vv.y, o[d4 * 4 + 1]);
                o[d4 * 4 + 2] = fmaf(p, vv.z, o[d4 * 4 + 2]);
                o[d4 * 4 + 3] = fmaf(p, vv.w, o[d4 * 4 + 3]);
            }
        }
        __syncthreads();
    }

    float inv = 1.0f / l;
    __half* Op = O + (((size_t)b * S_ + qi) * NH_ + hh) * HD_ + c * 32;
    #pragma unroll
    for (int d4 = 0; d4 < 8; d4++) {
        uint2 pk;
        pk.x = packh2(o[d4 * 4 + 0] * inv, o[d4 * 4 + 1] * inv);
        pk.y = packh2(o[d4 * 4 + 2] * inv, o[d4 * 4 + 3] * inv);
        *(uint2*)(Op + d4 * 4) = pk;
    }
}

// ---------------------------------------------------------------------------
// launch
// ---------------------------------------------------------------------------
extern "C" void kernel_launch(void* const* d_in, const int* in_sizes, int n_in,
                              void* d_out, int out_size) {
    const float* x     = (const float*)d_in[0];
    const float* freqs = (const float*)d_in[2];
    const float* w_qkv = (const float*)d_in[4];
    const float* w_fc  = (const float*)d_in[5];
    const float* w1    = (const float*)d_in[6];
    const float* w2    = (const float*)d_in[7];
    const float* w3    = (const float*)d_in[8];
    const float* anw   = (const float*)d_in[9];
    const float* fnw   = (const float*)d_in[10];
    float* out = (float*)d_out;

    float *qkv, *q, *k, *v, *h;
    __half *hnorm, *attnh, *ffh, *wqkvh, *wfch, *w1h, *w2h, *w3h;
    cudaGetSymbolAddress((void**)&qkv,   g_qkv);
    cudaGetSymbolAddress((void**)&q,     g_q);
    cudaGetSymbolAddress((void**)&k,     g_kbuf);
    cudaGetSymbolAddress((void**)&v,     g_vbuf);
    cudaGetSymbolAddress((void**)&h,     g_h);
    cudaGetSymbolAddress((void**)&hnorm, g_hnorm);
    cudaGetSymbolAddress((void**)&attnh, g_attnh);
    cudaGetSymbolAddress((void**)&ffh,   g_ffh);
    cudaGetSymbolAddress((void**)&wqkvh, g_wqkvh);
    cudaGetSymbolAddress((void**)&wfch,  g_wfch);
    cudaGetSymbolAddress((void**)&w1h,   g_w1h);
    cudaGetSymbolAddress((void**)&w2h,   g_w2h);
    cudaGetSymbolAddress((void**)&w3h,   g_w3h);

    static bool attr_done = false;
    if (!attr_done) {
        cudaFuncSetAttribute(tgemm_k<0>, cudaFuncAttributeMaxDynamicSharedMemorySize, GEMM_SMEM);
        cudaFuncSetAttribute(tgemm_k<1>, cudaFuncAttributeMaxDynamicSharedMemorySize, GEMM_SMEM);
        cudaFuncSetAttribute(tgemm_k<2>, cudaFuncAttributeMaxDynamicSharedMemorySize, GEMM_SMEM);
        cudaFuncSetAttribute(attn_k, cudaFuncAttributeMaxDynamicSharedMemorySize, ATTN_SMEM);
        attr_done = true;
    }

    // 0. weights -> fp16
    auto cvt = [](const float* s, __half* d, size_t n) {
        int n4 = (int)(n / 4);
        cvt_half_k<<<(n4 + 255) / 256, 256>>>(s, d, n4);
    };
    cvt(w_qkv, wqkvh, (size_t)QKV_N * E_);
    cvt(w_fc,  wfch,  (size_t)E_ * E_);
    cvt(w1,    w1h,   (size_t)FF_ * E_);
    cvt(w2,    w2h,   (size_t)FF_ * E_);
    cvt(w3,    w3h,   (size_t)E_ * FF_);

    // 1. h_norm = half(rmsnorm(x) * attn_norm_w)
    rmsnorm_k<<<T_, 256>>>(x, anw, hnorm);
    // 2. qkv(f32) = h_norm @ w_qkv^T
    tgemm_k<0><<<dim3(QKV_N / 128, T_ / 128), 256, GEMM_SMEM>>>(hnorm, wqkvh, nullptr,
                                                                nullptr, qkv, T_, QKV_N, E_);
    // 3. RoPE + split (fp32)
    rope_split_k<<<T_, 256>>>(qkv, freqs, q, k, v);
    // 4. causal flash attention (fp32 -> half out)
    attn_k<<<dim3(S_ / 64, NH_, B_), 256, ATTN_SMEM>>>(q, k, v, attnh);
    // 5. h(f32) = x + attnh @ w_fc^T
    tgemm_k<1><<<dim3(E_ / 128, T_ / 128), 256, GEMM_SMEM>>>(attnh, wfch, nullptr, x,
                                                             h, T_, E_, E_);
    // 6. g = half(rmsnorm(h) * ff_norm_w)
    rmsnorm_k<<<T_, 256>>>(h, fnw, hnorm);
    // 7. ffh(f16) = silu(g @ w1^T) * (g @ w2^T)
    tgemm_k<2><<<dim3(FF_ / 64, T_ / 128), 256, GEMM_SMEM>>>(hnorm, w1h, w2h, nullptr,
                                                             ffh, T_, FF_, E_);
    // 8. out(f32) = h + ffh @ w3^T
    tgemm_k<1><<<dim3(E_ / 128, T_ / 128), 256, GEMM_SMEM>>>(ffh, w3h, nullptr, h,
                                                             out, T_, E_, FF_);
}

// round 9
// speedup vs baseline: 11.9125x; 6.7864x over previous
#include <cuda_runtime.h>
#include <cuda_fp16.h>
#include <math.h>
#include <stdint.h>

// ---------------------------------------------------------------------------
// DecoderLayer: B=2, S=2048, E=2048, NH=16, NKV=4, HD=128, FF=5632
// Round 8: fp16 mma GEMMs (as R7) + flash attention on fp16 mma.sync with
// in-register P->A fragment conversion, 3-stage cp.async K/V^T tiles.
// ---------------------------------------------------------------------------

#define B_    2
#define S_    2048
#define E_    2048
#define NH_   16
#define NKV_  4
#define HD_   128
#define FF_   5632
#define T_    (B_ * S_)
#define QKV_N ((NH_ + 2 * NKV_) * HD_)  // 3072

// scratch (device globals; allocation-free)
__device__ float  g_qkv  [(size_t)T_ * QKV_N];
__device__ float  g_h    [(size_t)T_ * E_];
__device__ __half g_hnorm[(size_t)T_ * E_];
__device__ __half g_qh   [(size_t)B_ * NH_  * S_ * HD_];
__device__ __half g_kh   [(size_t)B_ * NKV_ * S_ * HD_];
__device__ __half g_vth  [(size_t)B_ * NKV_ * HD_ * S_];  // [b][h][d][s]
__device__ __half g_attnh[(size_t)T_ * E_];
__device__ __half g_ffh  [(size_t)T_ * FF_];
__device__ __half g_wqkvh[(size_t)QKV_N * E_];
__device__ __half g_wfch [(size_t)E_ * E_];
__device__ __half g_w1h  [(size_t)FF_ * E_];
__device__ __half g_w2h  [(size_t)FF_ * E_];
__device__ __half g_w3h  [(size_t)E_ * FF_];

// ---------------------------------------------------------------------------
__device__ __forceinline__ uint32_t smem_u32(const void* p) {
    uint32_t a;
    asm("{ .reg .u64 t; cvta.to.shared.u64 t, %1; cvt.u32.u64 %0, t; }"
        : "=r"(a) : "l"(p));
    return a;
}
__device__ __forceinline__ uint32_t lds32(uint32_t addr) {
    uint32_t v;
    asm volatile("ld.shared.b32 %0, [%1];" : "=r"(v) : "r"(addr));
    return v;
}
__device__ __forceinline__ uint32_t packh2(float a, float b) {
    __half2 h = __floats2half2_rn(a, b);
    return *reinterpret_cast<uint32_t*>(&h);
}
#define CP_COMMIT() asm volatile("cp.async.commit_group;" ::: "memory")
#define CP_WAIT_0() asm volatile("cp.async.wait_group 0;" ::: "memory")
#define CP_WAIT_1() asm volatile("cp.async.wait_group 1;" ::: "memory")

__device__ __forceinline__ void mma_f16(float* c, const uint32_t* a,
                                        uint32_t b0, uint32_t b1) {
    asm volatile(
        "mma.sync.aligned.m16n8k16.row.col.f32.f16.f16.f32 "
        "{%0,%1,%2,%3}, {%4,%5,%6,%7}, {%8,%9}, {%0,%1,%2,%3};"
        : "+f"(c[0]), "+f"(c[1]), "+f"(c[2]), "+f"(c[3])
        : "r"(a[0]), "r"(a[1]), "r"(a[2]), "r"(a[3]), "r"(b0), "r"(b1));
}

// XOR swizzle: byte offset of 16B chunk ch (+ tg*4) in 64-half row r
__device__ __forceinline__ uint32_t coff(int r, int ch, int tg) {
    return (uint32_t)(r * 128 + ((ch ^ (r & 7)) << 4) + tg * 4);
}

// ---------------------------------------------------------------------------
// fp32 -> fp16 weight conversion
// ---------------------------------------------------------------------------
__global__ void __launch_bounds__(256) cvt_half_k(const float* __restrict__ s,
                                                  __half* __restrict__ d, int n4) {
    int i = blockIdx.x * 256 + threadIdx.x;
    if (i < n4) {
        float4 v = ((const float4*)s)[i];
        uint2 o;
        o.x = packh2(v.x, v.y);
        o.y = packh2(v.z, v.w);
        ((uint2*)d)[i] = o;
    }
}

// ---------------------------------------------------------------------------
// RMSNorm: fp32 in, fp16 out
// ---------------------------------------------------------------------------
__global__ void __launch_bounds__(256) rmsnorm_k(const float* __restrict__ x,
                                                 const float* __restrict__ w,
                                                 __half* __restrict__ o) {
    size_t base = (size_t)blockIdx.x * E_;
    int tid = threadIdx.x;
    float4 v0 = *(const float4*)(x + base + tid * 8);
    float4 v1 = *(const float4*)(x + base + tid * 8 + 4);
    float ss = v0.x*v0.x + v0.y*v0.y + v0.z*v0.z + v0.w*v0.w
             + v1.x*v1.x + v1.y*v1.y + v1.z*v1.z + v1.w*v1.w;
    #pragma unroll
    for (int off = 16; off; off >>= 1) ss += __shfl_xor_sync(0xffffffffu, ss, off);
    __shared__ float ws[8];
    if ((tid & 31) == 0) ws[tid >> 5] = ss;
    __syncthreads();
    float tot = ws[0] + ws[1] + ws[2] + ws[3] + ws[4] + ws[5] + ws[6] + ws[7];
    float sc = rsqrtf(tot * (1.0f / E_) + 1e-5f);
    float4 w0 = *(const float4*)(w + tid * 8);
    float4 w1w = *(const float4*)(w + tid * 8 + 4);
    uint4 r;
    r.x = packh2(v0.x*sc*w0.x,  v0.y*sc*w0.y);
    r.y = packh2(v0.z*sc*w0.z,  v0.w*sc*w0.w);
    r.z = packh2(v1.x*sc*w1w.x, v1.y*sc*w1w.y);
    r.w = packh2(v1.z*sc*w1w.z, v1.w*sc*w1w.w);
    *(uint4*)(o + base + tid * 8) = r;
}

// ---------------------------------------------------------------------------
// fp16 GEMM (unchanged from R7): C[M,N] = A[M,K]*B[N,K]^T, 128xBN, BK=64.
// ---------------------------------------------------------------------------
#define GBLK 16384
#define GSTAGE (2 * GBLK)
#define GEMM_SMEM (3 * GSTAGE)

template <int MODE>
__global__ void __launch_bounds__(256, 2) tgemm_k(const __half* __restrict__ A,
                                                  const __half* __restrict__ Bm,
                                                  const __half* __restrict__ B2,
                                                  const float* __restrict__ R,
                                                  void* __restrict__ Cout,
                                                  int M, int N, int K) {
    extern __shared__ char sm[];
    constexpr int BN = (MODE == 2) ? 64 : 128;
    constexpr int NT = (MODE == 2) ? 4 : 8;

    const int tid = threadIdx.x;
    const int m0 = blockIdx.y * 128, n0 = blockIdx.x * BN;

    const int lrow = tid >> 1;
    const int ci0 = (tid & 1) * 4;
    const __half* Ag = A + (size_t)(m0 + lrow) * K + ci0 * 8;
    const __half* Bg;
    if (MODE == 2)
        Bg = ((lrow < 64) ? (Bm + (size_t)(n0 + lrow) * K)
                          : (B2 + (size_t)(n0 + lrow - 64) * K)) + ci0 * 8;
    else
        Bg = Bm + (size_t)(n0 + lrow) * K + ci0 * 8;

    const uint32_t smb = smem_u32(sm);
    uint32_t dsto[4];
    #pragma unroll
    for (int i = 0; i < 4; i++)
        dsto[i] = (uint32_t)(lrow * 128 + (((ci0 + i) ^ (lrow & 7)) << 4));

    auto load_chunk = [&](int st, int c) {
        const __half* a = Ag + c * 64;
        const __half* b = Bg + c * 64;
        uint32_t ab = smb + st * GSTAGE;
        uint32_t bb = ab + GBLK;
        #pragma unroll
        for (int i = 0; i < 4; i++) {
            asm volatile("cp.async.cg.shared.global [%0], [%1], 16;"
                         :: "r"(ab + dsto[i]), "l"(a + i * 8) : "memory");
            asm volatile("cp.async.cg.shared.global [%0], [%1], 16;"
                         :: "r"(bb + dsto[i]), "l"(b + i * 8) : "memory");
        }
        CP_COMMIT();
    };

    const int wid = tid >> 5, lane = tid & 31;
    const int gid = lane >> 2, tg = lane & 3;
    const int wm = wid >> 1, wn = wid & 1;

    float c1[2][NT][4];
    float c2[(MODE == 2) ? 2 : 1][(MODE == 2) ? NT : 1][4];
    #pragma unroll
    for (int mt = 0; mt < 2; mt++)
        #pragma unroll
        for (int nt = 0; nt < NT; nt++)
            #pragma unroll
            for (int q = 0; q < 4; q++) {
                c1[mt][nt][q] = 0.f;
                if (MODE == 2) c2[mt][nt][q] = 0.f;
            }

    const int NC = K >> 6;
    load_chunk(0, 0);
    load_chunk(1, 1);

    for (int c = 0; c < NC; c++) {
        if (c + 1 < NC) CP_WAIT_1(); else CP_WAIT_0();
        __syncthreads();
        if (c + 2 < NC) load_chunk((c + 2) % 3, c + 2);

        const uint32_t ab = smb + (c % 3) * GSTAGE;
        const uint32_t bb = ab + GBLK;
        #pragma unroll
        for (int ks = 0; ks < 4; ks++) {
            uint32_t af[2][4];
            #pragma unroll
            for (int mt = 0; mt < 2; mt++) {
                int ra = wm * 32 + mt * 16 + gid;
                af[mt][0] = lds32(ab + coff(ra,     2 * ks,     tg));
                af[mt][1] = lds32(ab + coff(ra + 8, 2 * ks,     tg));
                af[mt][2] = lds32(ab + coff(ra,     2 * ks + 1, tg));
                af[mt][3] = lds32(ab + coff(ra + 8, 2 * ks + 1, tg));
            }
            uint32_t bf[NT][2];
            #pragma unroll
            for (int nt = 0; nt < NT; nt++) {
                int rb = wn * (NT * 8) + nt * 8 + gid;
                bf[nt][0] = lds32(bb + coff(rb, 2 * ks,     tg));
                bf[nt][1] = lds32(bb + coff(rb, 2 * ks + 1, tg));
            }
            #pragma unroll
            for (int mt = 0; mt < 2; mt++)
                #pragma unroll
                for (int nt = 0; nt < NT; nt++)
                    mma_f16(c1[mt][nt], af[mt], bf[nt][0], bf[nt][1]);
            if (MODE == 2) {
                uint32_t bf2[NT][2];
                #pragma unroll
                for (int nt = 0; nt < NT; nt++) {
                    int rb = 64 + wn * 32 + nt * 8 + gid;
                    bf2[nt][0] = lds32(bb + coff(rb, 2 * ks,     tg));
                    bf2[nt][1] = lds32(bb + coff(rb, 2 * ks + 1, tg));
                }
                #pragma unroll
                for (int mt = 0; mt < 2; mt++)
                    #pragma unroll
                    for (int nt = 0; nt < NT; nt++)
                        mma_f16(c2[mt][nt], af[mt], bf2[nt][0], bf2[nt][1]);
            }
        }
    }

    #pragma unroll
    for (int mt = 0; mt < 2; mt++) {
        #pragma unroll
        for (int half = 0; half < 2; half++) {
            size_t row = (size_t)(m0 + wm * 32 + mt * 16 + gid + half * 8);
            #pragma unroll
            for (int nt = 0; nt < NT; nt++) {
                int col = n0 + wn * (NT * 8) + nt * 8 + tg * 2;
                float v0 = c1[mt][nt][half * 2 + 0];
                float v1 = c1[mt][nt][half * 2 + 1];
                if (MODE == 2) {
                    float u0 = c2[mt][nt][half * 2 + 0];
                    float u1 = c2[mt][nt][half * 2 + 1];
                    v0 = (v0 / (1.0f + __expf(-v0))) * u0;
                    v1 = (v1 / (1.0f + __expf(-v1))) * u1;
                    *(uint32_t*)((__half*)Cout + row * N + col) = packh2(v0, v1);
                } else {
                    if (MODE == 1) {
                        float2 res = *(const float2*)(R + row * N + col);
                        v0 += res.x; v1 += res.y;
                    }
                    *(float2*)((float*)Cout + row * N + col) = make_float2(v0, v1);
                }
            }
        }
    }
}

// ---------------------------------------------------------------------------
// RoPE + split: q half pre-scaled by 1/sqrt(2048), k half. (V via vtrans_k.)
// ---------------------------------------------------------------------------
__global__ void __launch_bounds__(256) rope_split_k(const float* __restrict__ qkv,
                                                    const float* __restrict__ fc,
                                                    __half* __restrict__ q,
                                                    __half* __restrict__ k) {
    int t = blockIdx.x;
    int b = t >> 11;
    int s = t & 2047;
    const float* row = qkv + (size_t)t * QKV_N;
    const float* f = fc + (size_t)s * HD_;
    const float sc = 0.022097086912079608f;  // 1/sqrt(2048)
    for (int idx = threadIdx.x; idx < NH_ * 64; idx += 256) {
        int h = idx >> 6, i = idx & 63;
        float x0 = row[h * HD_ + 2 * i];
        float x1 = row[h * HD_ + 2 * i + 1];
        float cs = f[2 * i], sn = f[2 * i + 1];
        size_t o = ((size_t)(b * NH_ + h) * S_ + s) * HD_ + 2 * i;
        *(uint32_t*)(q + o) = packh2((x0 * cs - x1 * sn) * sc,
                                     (x1 * cs + x0 * sn) * sc);
    }
    for (int idx = threadIdx.x; idx < NKV_ * 64; idx += 256) {
        int h = idx >> 6, i = idx & 63;
        float x0 = row[NH_ * HD_ + h * HD_ + 2 * i];
        float x1 = row[NH_ * HD_ + h * HD_ + 2 * i + 1];
        float cs = f[2 * i], sn = f[2 * i + 1];
        size_t o = ((size_t)(b * NKV_ + h) * S_ + s) * HD_ + 2 * i;
        *(uint32_t*)(k + o) = packh2(x0 * cs - x1 * sn, x1 * cs + x0 * sn);
    }
}

// ---------------------------------------------------------------------------
// V transpose: qkv f32 [t][...] -> vt half [b][h][d][s], 32x32 smem tiles.
// ---------------------------------------------------------------------------
__global__ void __launch_bounds__(256) vtrans_k(const float* __restrict__ qkv,
                                                __half* __restrict__ vt) {
    __shared__ float tsm[32][33];
    int bh = blockIdx.z, b = bh >> 2, h = bh & 3;
    int s0 = blockIdx.x * 32, d0 = blockIdx.y * 32;
    int tx = threadIdx.x & 31, ty = threadIdx.x >> 5;  // 32 x 8
    #pragma unroll
    for (int i = 0; i < 4; i++) {
        int s = s0 + ty + i * 8;
        tsm[ty + i * 8][tx] =
            qkv[((size_t)(b * S_ + s)) * QKV_N + (NH_ + NKV_) * HD_ + h * HD_ + d0 + tx];
    }
    __syncthreads();
    #pragma unroll
    for (int i = 0; i < 4; i++) {
        int d = d0 + ty + i * 8;
        vt[((size_t)(b * NKV_ + h) * HD_ + d) * S_ + s0 + tx] =
            __float2half(tsm[tx][ty + i * 8]);
    }
}

// ---------------------------------------------------------------------------
// Flash attention on fp16 mma. BM=128 (8 warps x 16 rows), BN=64 kv.
// K smem: [2 d-blocks][64 kv][64 halves]; V^T smem: [128 d][64 kv halves].
// 3-stage cp.async. P converts in-register to PV A-fragments.
// ---------------------------------------------------------------------------
#define AT_BLK 16384
#define AT_STAGE (2 * AT_BLK)
#define ATT_SMEM (3 * AT_STAGE)   // 98304

__global__ void __launch_bounds__(256, 1) attn_k(const __half* __restrict__ Q,
                                                 const __half* __restrict__ K,
                                                 const __half* __restrict__ Vt,
                                                 __half* __restrict__ O) {
    extern __shared__ char smc[];
    const uint32_t smb = smem_u32(smc);
    const int tid = threadIdx.x;
    const int wq = tid >> 5, lane = tid & 31;
    const int gid = lane >> 2, tg = lane & 3;
    const int qt = blockIdx.x, hh = blockIdx.y, b = blockIdx.z;
    const int q0 = qt * 128;

    const __half* Qp = Q  + (size_t)(b * NH_  + hh)        * S_ * HD_;
    const __half* Kp = K  + (size_t)(b * NKV_ + (hh >> 2)) * S_ * HD_;
    const __half* Vp = Vt + (size_t)(b * NKV_ + (hh >> 2)) * HD_ * S_;

    const int ra = q0 + wq * 16 + gid;   // rows ra, ra+8

    // resident Q A-fragments (pre-scaled)
    uint32_t qa[8][4];
    #pragma unroll
    for (int kc = 0; kc < 8; kc++) {
        const __half* p0 = Qp + (size_t)ra * HD_ + kc * 16 + 2 * tg;
        qa[kc][0] = *(const uint32_t*)(p0);
        qa[kc][1] = *(const uint32_t*)(p0 + 8 * HD_);
        qa[kc][2] = *(const uint32_t*)(p0 + 8);
        qa[kc][3] = *(const uint32_t*)(p0 + 8 * HD_ + 8);
    }

    // loaders: 128 rows x 64 halves for K (block layout) and V^T
    const int lrow = tid >> 1;
    const int ci0 = (tid & 1) * 4;
    uint32_t dsto[4];
    #pragma unroll
    for (int i = 0; i < 4; i++)
        dsto[i] = (uint32_t)(lrow * 128 + (((ci0 + i) ^ (lrow & 7)) << 4));
    const __half* Kg = Kp + (size_t)(lrow & 63) * HD_ + (lrow >> 6) * 64 + ci0 * 8;
    const __half* Vg = Vp + (size_t)lrow * S_ + ci0 * 8;

    auto load_tile = [&](int st, int kt) {
        int k0 = kt * 64;
        uint32_t kb = smb + st * AT_STAGE;
        uint32_t vb = kb + AT_BLK;
        const __half* kg = Kg + (size_t)k0 * HD_;
        const __half* vg = Vg + k0;
        #pragma unroll
        for (int i = 0; i < 4; i++) {
            asm volatile("cp.async.cg.shared.global [%0], [%1], 16;"
                         :: "r"(kb + dsto[i]), "l"(kg + i * 8) : "memory");
            asm volatile("cp.async.cg.shared.global [%0], [%1], 16;"
                         :: "r"(vb + dsto[i]), "l"(vg + i * 8) : "memory");
        }
        CP_COMMIT();
    };

    float o[16][4];
    #pragma unroll
    for (int dt = 0; dt < 16; dt++)
        #pragma unroll
        for (int q = 0; q < 4; q++) o[dt][q] = 0.f;
    float mA = -1e30f, mB = -1e30f, lA = 0.f, lB = 0.f;

    const int nkt = 2 * qt + 2;
    load_tile(0, 0);
    load_tile(1, 1);

    for (int kt = 0; kt < nkt; kt++) {
        if (kt + 1 < nkt) CP_WAIT_1(); else CP_WAIT_0();
        __syncthreads();
        if (kt + 2 < nkt) load_tile((kt + 2) % 3, kt + 2);

        const uint32_t kb = smb + (kt % 3) * AT_STAGE;
        const uint32_t vb = kb + AT_BLK;
        const int k0 = kt * 64;

        // scores S = Q K^T  (16 x 64 per warp)
        float s[8][4];
        #pragma unroll
        for (int nt = 0; nt < 8; nt++)
            #pragma unroll
            for (int q = 0; q < 4; q++) s[nt][q] = 0.f;
        #pragma unroll
        for (int kc = 0; kc < 8; kc++) {
            const int rbase = (kc >> 2) * 64;
            const int ch0 = 2 * (kc & 3);
            #pragma unroll
            for (int nt = 0; nt < 8; nt++) {
                int r = rbase + nt * 8 + gid;
                uint32_t b0 = lds32(kb + coff(r, ch0,     tg));
                uint32_t b1 = lds32(kb + coff(r, ch0 + 1, tg));
                mma_f16(s[nt], qa[kc], b0, b1);
            }
        }

        // causal mask + row max
        float mtA = -1e30f, mtB = -1e30f;
        #pragma unroll
        for (int nt = 0; nt < 8; nt++) {
            int c0 = k0 + nt * 8 + tg * 2, c1 = c0 + 1;
            if (c0 > ra)     s[nt][0] = -1e30f;
            if (c1 > ra)     s[nt][1] = -1e30f;
            if (c0 > ra + 8) s[nt][2] = -1e30f;
            if (c1 > ra + 8) s[nt][3] = -1e30f;
            mtA = fmaxf(mtA, fmaxf(s[nt][0], s[nt][1]));
            mtB = fmaxf(mtB, fmaxf(s[nt][2], s[nt][3]));
        }
        mtA = fmaxf(mtA, __shfl_xor_sync(0xffffffffu, mtA, 1));
        mtA = fmaxf(mtA, __shfl_xor_sync(0xffffffffu, mtA, 2));
        mtB = fmaxf(mtB, __shfl_xor_sync(0xffffffffu, mtB, 1));
        mtB = fmaxf(mtB, __shfl_xor_sync(0xffffffffu, mtB, 2));

        float mnA = fmaxf(mA, mtA), mnB = fmaxf(mB, mtB);
        float facA = __expf(mA - mnA), facB = __expf(mB - mnB);
        float lsA = 0.f, lsB = 0.f;
        #pragma unroll
        for (int nt = 0; nt < 8; nt++) {
            s[nt][0] = __expf(s[nt][0] - mnA);
            s[nt][1] = __expf(s[nt][1] - mnA);
            s[nt][2] = __expf(s[nt][2] - mnB);
            s[nt][3] = __expf(s[nt][3] - mnB);
            lsA += s[nt][0] + s[nt][1];
            lsB += s[nt][2] + s[nt][3];
        }
        lsA += __shfl_xor_sync(0xffffffffu, lsA, 1);
        lsA += __shfl_xor_sync(0xffffffffu, lsA, 2);
        lsB += __shfl_xor_sync(0xffffffffu, lsB, 1);
        lsB += __shfl_xor_sync(0xffffffffu, lsB, 2);
        lA = lA * facA + lsA;  mA = mnA;
        lB = lB * facB + lsB;  mB = mnB;

        #pragma unroll
        for (int dt = 0; dt < 16; dt++) {
            o[dt][0] *= facA; o[dt][1] *= facA;
            o[dt][2] *= facB; o[dt][3] *= facB;
        }

        // O += P V   (P A-fragments from score C-fragments, in-register)
        #pragma unroll
        for (int j = 0; j < 4; j++) {
            uint32_t aa[4];
            aa[0] = packh2(s[2 * j][0],     s[2 * j][1]);
            aa[1] = packh2(s[2 * j][2],     s[2 * j][3]);
            aa[2] = packh2(s[2 * j + 1][0], s[2 * j + 1][1]);
            aa[3] = packh2(s[2 * j + 1][2], s[2 * j + 1][3]);
            #pragma unroll
            for (int dt = 0; dt < 16; dt++) {
                int r = dt * 8 + gid;
                uint32_t b0 = lds32(vb + coff(r, 2 * j,     tg));
                uint32_t b1 = lds32(vb + coff(r, 2 * j + 1, tg));
                mma_f16(o[dt], aa, b0, b1);
            }
        }
        __syncthreads();
    }

    // write out: token-major [b][s][h][d], half
    float iA = 1.0f / lA, iB = 1.0f / lB;
    __half* OpA = O + (((size_t)b * S_ + ra)     * NH_ + hh) * HD_;
    __half* OpB = O + (((size_t)b * S_ + ra + 8) * NH_ + hh) * HD_;
    #pragma unroll
    for (int dt = 0; dt < 16; dt++) {
        int d = dt * 8 + tg * 2;
        *(uint32_t*)(OpA + d) = packh2(o[dt][0] * iA, o[dt][1] * iA);
        *(uint32_t*)(OpB + d) = packh2(o[dt][2] * iB, o[dt][3] * iB);
    }
}

// ---------------------------------------------------------------------------
// launch
// ---------------------------------------------------------------------------
extern "C" void kernel_launch(void* const* d_in, const int* in_sizes, int n_in,
                              void* d_out, int out_size) {
    const float* x     = (const float*)d_in[0];
    const float* freqs = (const float*)d_in[2];
    const float* w_qkv = (const float*)d_in[4];
    const float* w_fc  = (const float*)d_in[5];
    const float* w1    = (const float*)d_in[6];
    const float* w2    = (const float*)d_in[7];
    const float* w3    = (const float*)d_in[8];
    const float* anw   = (const float*)d_in[9];
    const float* fnw   = (const float*)d_in[10];
    float* out = (float*)d_out;

    float *qkv, *h;
    __half *hnorm, *qh, *kh, *vth, *attnh, *ffh, *wqkvh, *wfch, *w1h, *w2h, *w3h;
    cudaGetSymbolAddress((void**)&qkv,   g_qkv);
    cudaGetSymbolAddress((void**)&h,     g_h);
    cudaGetSymbolAddress((void**)&hnorm, g_hnorm);
    cudaGetSymbolAddress((void**)&qh,    g_qh);
    cudaGetSymbolAddress((void**)&kh,    g_kh);
    cudaGetSymbolAddress((void**)&vth,   g_vth);
    cudaGetSymbolAddress((void**)&attnh, g_attnh);
    cudaGetSymbolAddress((void**)&ffh,   g_ffh);
    cudaGetSymbolAddress((void**)&wqkvh, g_wqkvh);
    cudaGetSymbolAddress((void**)&wfch,  g_wfch);
    cudaGetSymbolAddress((void**)&w1h,   g_w1h);
    cudaGetSymbolAddress((void**)&w2h,   g_w2h);
    cudaGetSymbolAddress((void**)&w3h,   g_w3h);

    static bool attr_done = false;
    if (!attr_done) {
        cudaFuncSetAttribute(tgemm_k<0>, cudaFuncAttributeMaxDynamicSharedMemorySize, GEMM_SMEM);
        cudaFuncSetAttribute(tgemm_k<1>, cudaFuncAttributeMaxDynamicSharedMemorySize, GEMM_SMEM);
        cudaFuncSetAttribute(tgemm_k<2>, cudaFuncAttributeMaxDynamicSharedMemorySize, GEMM_SMEM);
        cudaFuncSetAttribute(attn_k, cudaFuncAttributeMaxDynamicSharedMemorySize, ATT_SMEM);
        attr_done = true;
    }

    // 0. weights -> fp16
    auto cvt = [](const float* s, __half* d, size_t n) {
        int n4 = (int)(n / 4);
        cvt_half_k<<<(n4 + 255) / 256, 256>>>(s, d, n4);
    };
    cvt(w_qkv, wqkvh, (size_t)QKV_N * E_);
    cvt(w_fc,  wfch,  (size_t)E_ * E_);
    cvt(w1,    w1h,   (size_t)FF_ * E_);
    cvt(w2,    w2h,   (size_t)FF_ * E_);
    cvt(w3,    w3h,   (size_t)E_ * FF_);

    // 1. h_norm = half(rmsnorm(x) * attn_norm_w)
    rmsnorm_k<<<T_, 256>>>(x, anw, hnorm);
    // 2. qkv(f32) = h_norm @ w_qkv^T
    tgemm_k<0><<<dim3(QKV_N / 128, T_ / 128), 256, GEMM_SMEM>>>(hnorm, wqkvh, nullptr,
                                                                nullptr, qkv, T_, QKV_N, E_);
    // 3. RoPE + split (half) and V transpose (half, [b][h][d][s])
    rope_split_k<<<T_, 256>>>(qkv, freqs, qh, kh);
    vtrans_k<<<dim3(S_ / 32, HD_ / 32, B_ * NKV_), 256>>>(qkv, vth);
    // 4. causal flash attention (fp16 mma, f32 softmax)
    attn_k<<<dim3(S_ / 128, NH_, B_), 256, ATT_SMEM>>>(qh, kh, vth, attnh);
    // 5. h(f32) = x + attnh @ w_fc^T
    tgemm_k<1><<<dim3(E_ / 128, T_ / 128), 256, GEMM_SMEM>>>(attnh, wfch, nullptr, x,
                                                             h, T_, E_, E_);
    // 6. g = half(rmsnorm(h) * ff_norm_w)
    rmsnorm_k<<<T_, 256>>>(h, fnw, hnorm);
    // 7. ffh(f16) = silu(g @ w1^T) * (g @ w2^T)
    tgemm_k<2><<<dim3(FF_ / 64, T_ / 128), 256, GEMM_SMEM>>>(hnorm, w1h, w2h, nullptr,
                                                             ffh, T_, FF_, E_);
    // 8. out(f32) = h + ffh @ w3^T
    tgemm_k<1><<<dim3(E_ / 128, T_ / 128), 256, GEMM_SMEM>>>(ffh, w3h, nullptr, h,
                                                             out, T_, E_, FF_);
}

// round 13
// speedup vs baseline: 13.7233x; 1.1520x over previous
#include <cuda_runtime.h>
#include <cuda_fp16.h>
#include <math.h>
#include <stdint.h>

// ---------------------------------------------------------------------------
// DecoderLayer: B=2, S=2048, E=2048, NH=16, NKV=4, HD=128, FF=5632
// Round 9: fp16 mma GEMMs with 256x128 CTA tile / 64x64 warp tile (intensity
// 21.3 -> 32 flop/smem-byte). Attention unchanged from R8 (fp16 mma flash).
// ---------------------------------------------------------------------------

#define B_    2
#define S_    2048
#define E_    2048
#define NH_   16
#define NKV_  4
#define HD_   128
#define FF_   5632
#define T_    (B_ * S_)
#define QKV_N ((NH_ + 2 * NKV_) * HD_)  // 3072

// scratch (device globals; allocation-free)
__device__ float  g_qkv  [(size_t)T_ * QKV_N];
__device__ float  g_h    [(size_t)T_ * E_];
__device__ __half g_hnorm[(size_t)T_ * E_];
__device__ __half g_qh   [(size_t)B_ * NH_  * S_ * HD_];
__device__ __half g_kh   [(size_t)B_ * NKV_ * S_ * HD_];
__device__ __half g_vth  [(size_t)B_ * NKV_ * HD_ * S_];  // [b][h][d][s]
__device__ __half g_attnh[(size_t)T_ * E_];
__device__ __half g_ffh  [(size_t)T_ * FF_];
__device__ __half g_wqkvh[(size_t)QKV_N * E_];
__device__ __half g_wfch [(size_t)E_ * E_];
__device__ __half g_w1h  [(size_t)FF_ * E_];
__device__ __half g_w2h  [(size_t)FF_ * E_];
__device__ __half g_w3h  [(size_t)E_ * FF_];

// ---------------------------------------------------------------------------
__device__ __forceinline__ uint32_t smem_u32(const void* p) {
    uint32_t a;
    asm("{ .reg .u64 t; cvta.to.shared.u64 t, %1; cvt.u32.u64 %0, t; }"
        : "=r"(a) : "l"(p));
    return a;
}
__device__ __forceinline__ uint32_t lds32(uint32_t addr) {
    uint32_t v;
    asm volatile("ld.shared.b32 %0, [%1];" : "=r"(v) : "r"(addr));
    return v;
}
__device__ __forceinline__ uint32_t packh2(float a, float b) {
    __half2 h = __floats2half2_rn(a, b);
    return *reinterpret_cast<uint32_t*>(&h);
}
__device__ __forceinline__ void cpa16(uint32_t dst, const void* src) {
    asm volatile("cp.async.cg.shared.global [%0], [%1], 16;"
                 :: "r"(dst), "l"(src) : "memory");
}
#define CP_COMMIT() asm volatile("cp.async.commit_group;" ::: "memory")
#define CP_WAIT_0() asm volatile("cp.async.wait_group 0;" ::: "memory")
#define CP_WAIT_1() asm volatile("cp.async.wait_group 1;" ::: "memory")

__device__ __forceinline__ void mma_f16(float* c, const uint32_t* a,
                                        uint32_t b0, uint32_t b1) {
    asm volatile(
        "mma.sync.aligned.m16n8k16.row.col.f32.f16.f16.f32 "
        "{%0,%1,%2,%3}, {%4,%5,%6,%7}, {%8,%9}, {%0,%1,%2,%3};"
        : "+f"(c[0]), "+f"(c[1]), "+f"(c[2]), "+f"(c[3])
        : "r"(a[0]), "r"(a[1]), "r"(a[2]), "r"(a[3]), "r"(b0), "r"(b1));
}

// XOR swizzle: byte offset of 16B chunk ch (+ tg*4) in 64-half row r
__device__ __forceinline__ uint32_t coff(int r, int ch, int tg) {
    return (uint32_t)(r * 128 + ((ch ^ (r & 7)) << 4) + tg * 4);
}

// ---------------------------------------------------------------------------
// fp32 -> fp16 weight conversion
// ---------------------------------------------------------------------------
__global__ void __launch_bounds__(256) cvt_half_k(const float* __restrict__ s,
                                                  __half* __restrict__ d, int n4) {
    int i = blockIdx.x * 256 + threadIdx.x;
    if (i < n4) {
        float4 v = ((const float4*)s)[i];
        uint2 o;
        o.x = packh2(v.x, v.y);
        o.y = packh2(v.z, v.w);
        ((uint2*)d)[i] = o;
    }
}

// ---------------------------------------------------------------------------
// RMSNorm: fp32 in, fp16 out
// ---------------------------------------------------------------------------
__global__ void __launch_bounds__(256) rmsnorm_k(const float* __restrict__ x,
                                                 const float* __restrict__ w,
                                                 __half* __restrict__ o) {
    size_t base = (size_t)blockIdx.x * E_;
    int tid = threadIdx.x;
    float4 v0 = *(const float4*)(x + base + tid * 8);
    float4 v1 = *(const float4*)(x + base + tid * 8 + 4);
    float ss = v0.x*v0.x + v0.y*v0.y + v0.z*v0.z + v0.w*v0.w
             + v1.x*v1.x + v1.y*v1.y + v1.z*v1.z + v1.w*v1.w;
    #pragma unroll
    for (int off = 16; off; off >>= 1) ss += __shfl_xor_sync(0xffffffffu, ss, off);
    __shared__ float ws[8];
    if ((tid & 31) == 0) ws[tid >> 5] = ss;
    __syncthreads();
    float tot = ws[0] + ws[1] + ws[2] + ws[3] + ws[4] + ws[5] + ws[6] + ws[7];
    float sc = rsqrtf(tot * (1.0f / E_) + 1e-5f);
    float4 w0 = *(const float4*)(w + tid * 8);
    float4 w1w = *(const float4*)(w + tid * 8 + 4);
    uint4 r;
    r.x = packh2(v0.x*sc*w0.x,  v0.y*sc*w0.y);
    r.y = packh2(v0.z*sc*w0.z,  v0.w*sc*w0.w);
    r.z = packh2(v1.x*sc*w1w.x, v1.y*sc*w1w.y);
    r.w = packh2(v1.z*sc*w1w.z, v1.w*sc*w1w.w);
    *(uint4*)(o + base + tid * 8) = r;
}

// ---------------------------------------------------------------------------
// fp16 GEMM: C[M,N] = A[M,K]*B[N,K]^T. CTA tile 256 x BN, BK=64, 3-stage.
// Warp tile 64x64 (MODE 0/1, BN=128) or 64x32 per B matrix (MODE 2, BN=64).
// MODE 0: C(f32) = A·B^T
// MODE 1: C(f32) = R + A·B^T
// MODE 2: C(f16) = silu(A·B^T)*(A·B2^T)   (smem B rows 64..127 = B2)
// 256 threads = 8 warps in 4(M) x 2(N) grid. XOR-swizzled smem rows (128B).
// Loader: 384 rows x 8 16B-chunks per chunk-stage = 12 cp.async per thread.
// ---------------------------------------------------------------------------
#define GSTAGE 49152                    // (256 A rows + 128 B rows) * 128B
#define GEMM_SMEM (3 * GSTAGE)          // 147456

template <int MODE>
__global__ void __launch_bounds__(256) tgemm_k(const __half* __restrict__ A,
                                               const __half* __restrict__ Bm,
                                               const __half* __restrict__ B2,
                                               const float* __restrict__ R,
                                               void* __restrict__ Cout,
                                               int M, int N, int K) {
    extern __shared__ char sm[];
    constexpr int BN = (MODE == 2) ? 64 : 128;
    constexpr int NT = (MODE == 2) ? 4 : 8;   // n-tiles per warp per B matrix

    const int tid = threadIdx.x;
    const int m0 = blockIdx.y * 256, n0 = blockIdx.x * BN;
    const uint32_t smb = smem_u32(sm);

    // loader tables: 12 x (smem offset, global ptr)
    uint32_t so[12];
    const __half* gp[12];
    #pragma unroll
    for (int j = 0; j < 12; j++) {
        int ci = tid + j * 256;
        int row = ci >> 3, ch = ci & 7;
        so[j] = (uint32_t)(row * 128 + ((ch ^ (row & 7)) << 4));
        if (row < 256) {
            gp[j] = A + (size_t)(m0 + row) * K + ch * 8;
        } else {
            int br = row - 256;
            if (MODE == 2)
                gp[j] = ((br < 64) ? (Bm + (size_t)(n0 + br) * K)
                                   : (B2 + (size_t)(n0 + br - 64) * K)) + ch * 8;
            else
                gp[j] = Bm + (size_t)(n0 + br) * K + ch * 8;
        }
    }

    auto load_chunk = [&](int st, int c) {
        uint32_t base = smb + st * GSTAGE;
        #pragma unroll
        for (int j = 0; j < 12; j++)
            cpa16(base + so[j], gp[j] + c * 64);
        CP_COMMIT();
    };

    const int wid = tid >> 5, lane = tid & 31;
    const int gid = lane >> 2, tg = lane & 3;
    const int wm = wid >> 1, wn = wid & 1;

    float c1[4][NT][4];
    float c2[(MODE == 2) ? 4 : 1][(MODE == 2) ? NT : 1][4];
    #pragma unroll
    for (int mt = 0; mt < 4; mt++)
        #pragma unroll
        for (int nt = 0; nt < NT; nt++)
            #pragma unroll
            for (int q = 0; q < 4; q++) {
                c1[mt][nt][q] = 0.f;
                if (MODE == 2) c2[mt][nt][q] = 0.f;
            }

    const int NC = K >> 6;
    load_chunk(0, 0);
    load_chunk(1, 1);

    for (int c = 0; c < NC; c++) {
        if (c + 1 < NC) CP_WAIT_1(); else CP_WAIT_0();
        __syncthreads();
        if (c + 2 < NC) load_chunk((c + 2) % 3, c + 2);

        const uint32_t ab = smb + (c % 3) * GSTAGE;
        const uint32_t bb = ab + 32768;
        #pragma unroll
        for (int ks = 0; ks < 4; ks++) {
            uint32_t af[4][4];
            #pragma unroll
            for (int mt = 0; mt < 4; mt++) {
                int ra = wm * 64 + mt * 16 + gid;
                af[mt][0] = lds32(ab + coff(ra,     2 * ks,     tg));
                af[mt][1] = lds32(ab + coff(ra + 8, 2 * ks,     tg));
                af[mt][2] = lds32(ab + coff(ra,     2 * ks + 1, tg));
                af[mt][3] = lds32(ab + coff(ra + 8, 2 * ks + 1, tg));
            }
            uint32_t bf[NT][2];
            #pragma unroll
            for (int nt = 0; nt < NT; nt++) {
                int rb = wn * (NT * 8) + nt * 8 + gid;
                bf[nt][0] = lds32(bb + coff(rb, 2 * ks,     tg));
                bf[nt][1] = lds32(bb + coff(rb, 2 * ks + 1, tg));
            }
            #pragma unroll
            for (int mt = 0; mt < 4; mt++)
                #pragma unroll
                for (int nt = 0; nt < NT; nt++)
                    mma_f16(c1[mt][nt], af[mt], bf[nt][0], bf[nt][1]);
            if (MODE == 2) {
                uint32_t bf2[NT][2];
                #pragma unroll
                for (int nt = 0; nt < NT; nt++) {
                    int rb = 64 + wn * 32 + nt * 8 + gid;
                    bf2[nt][0] = lds32(bb + coff(rb, 2 * ks,     tg));
                    bf2[nt][1] = lds32(bb + coff(rb, 2 * ks + 1, tg));
                }
                #pragma unroll
                for (int mt = 0; mt < 4; mt++)
                    #pragma unroll
                    for (int nt = 0; nt < NT; nt++)
                        mma_f16(c2[mt][nt], af[mt], bf2[nt][0], bf2[nt][1]);
            }
        }
    }

    // epilogue
    #pragma unroll
    for (int mt = 0; mt < 4; mt++) {
        #pragma unroll
        for (int half = 0; half < 2; half++) {
            size_t row = (size_t)(m0 + wm * 64 + mt * 16 + gid + half * 8);
            #pragma unroll
            for (int nt = 0; nt < NT; nt++) {
                int col = n0 + wn * (NT * 8) + nt * 8 + tg * 2;
                float v0 = c1[mt][nt][half * 2 + 0];
                float v1 = c1[mt][nt][half * 2 + 1];
                if (MODE == 2) {
                    float u0 = c2[mt][nt][half * 2 + 0];
                    float u1 = c2[mt][nt][half * 2 + 1];
                    v0 = (v0 / (1.0f + __expf(-v0))) * u0;
                    v1 = (v1 / (1.0f + __expf(-v1))) * u1;
                    *(uint32_t*)((__half*)Cout + row * N + col) = packh2(v0, v1);
                } else {
                    if (MODE == 1) {
                        float2 res = *(const float2*)(R + row * N + col);
                        v0 += res.x; v1 += res.y;
                    }
                    *(float2*)((float*)Cout + row * N + col) = make_float2(v0, v1);
                }
            }
        }
    }
}

// ---------------------------------------------------------------------------
// RoPE + split: q half pre-scaled by 1/sqrt(2048), k half. (V via vtrans_k.)
// ---------------------------------------------------------------------------
__global__ void __launch_bounds__(256) rope_split_k(const float* __restrict__ qkv,
                                                    const float* __restrict__ fc,
                                                    __half* __restrict__ q,
                                                    __half* __restrict__ k) {
    int t = blockIdx.x;
    int b = t >> 11;
    int s = t & 2047;
    const float* row = qkv + (size_t)t * QKV_N;
    const float* f = fc + (size_t)s * HD_;
    const float sc = 0.022097086912079608f;  // 1/sqrt(2048)
    for (int idx = threadIdx.x; idx < NH_ * 64; idx += 256) {
        int h = idx >> 6, i = idx & 63;
        float x0 = row[h * HD_ + 2 * i];
        float x1 = row[h * HD_ + 2 * i + 1];
        float cs = f[2 * i], sn = f[2 * i + 1];
        size_t o = ((size_t)(b * NH_ + h) * S_ + s) * HD_ + 2 * i;
        *(uint32_t*)(q + o) = packh2((x0 * cs - x1 * sn) * sc,
                                     (x1 * cs + x0 * sn) * sc);
    }
    for (int idx = threadIdx.x; idx < NKV_ * 64; idx += 256) {
        int h = idx >> 6, i = idx & 63;
        float x0 = row[NH_ * HD_ + h * HD_ + 2 * i];
        float x1 = row[NH_ * HD_ + h * HD_ + 2 * i + 1];
        float cs = f[2 * i], sn = f[2 * i + 1];
        size_t o = ((size_t)(b * NKV_ + h) * S_ + s) * HD_ + 2 * i;
        *(uint32_t*)(k + o) = packh2(x0 * cs - x1 * sn, x1 * cs + x0 * sn);
    }
}

// ---------------------------------------------------------------------------
// V transpose: qkv f32 [t][...] -> vt half [b][h][d][s], 32x32 smem tiles.
// ---------------------------------------------------------------------------
__global__ void __launch_bounds__(256) vtrans_k(const float* __restrict__ qkv,
                                                __half* __restrict__ vt) {
    __shared__ float tsm[32][33];
    int bh = blockIdx.z, b = bh >> 2, h = bh & 3;
    int s0 = blockIdx.x * 32, d0 = blockIdx.y * 32;
    int tx = threadIdx.x & 31, ty = threadIdx.x >> 5;  // 32 x 8
    #pragma unroll
    for (int i = 0; i < 4; i++) {
        int s = s0 + ty + i * 8;
        tsm[ty + i * 8][tx] =
            qkv[((size_t)(b * S_ + s)) * QKV_N + (NH_ + NKV_) * HD_ + h * HD_ + d0 + tx];
    }
    __syncthreads();
    #pragma unroll
    for (int i = 0; i < 4; i++) {
        int d = d0 + ty + i * 8;
        vt[((size_t)(b * NKV_ + h) * HD_ + d) * S_ + s0 + tx] =
            __float2half(tsm[tx][ty + i * 8]);
    }
}

// ---------------------------------------------------------------------------
// Flash attention on fp16 mma (unchanged from R8). BM=128, BN=64 kv tiles.
// ---------------------------------------------------------------------------
#define AT_BLK 16384
#define AT_STAGE (2 * AT_BLK)
#define ATT_SMEM (3 * AT_STAGE)   // 98304

__global__ void __launch_bounds__(256, 1) attn_k(const __half* __restrict__ Q,
                                                 const __half* __restrict__ K,
                                                 const __half* __restrict__ Vt,
                                                 __half* __restrict__ O) {
    extern __shared__ char smc[];
    const uint32_t smb = smem_u32(smc);
    const int tid = threadIdx.x;
    const int wq = tid >> 5, lane = tid & 31;
    const int gid = lane >> 2, tg = lane & 3;
    const int qt = blockIdx.x, hh = blockIdx.y, b = blockIdx.z;
    const int q0 = qt * 128;

    const __half* Qp = Q  + (size_t)(b * NH_  + hh)        * S_ * HD_;
    const __half* Kp = K  + (size_t)(b * NKV_ + (hh >> 2)) * S_ * HD_;
    const __half* Vp = Vt + (size_t)(b * NKV_ + (hh >> 2)) * HD_ * S_;

    const int ra = q0 + wq * 16 + gid;   // rows ra, ra+8

    uint32_t qa[8][4];
    #pragma unroll
    for (int kc = 0; kc < 8; kc++) {
        const __half* p0 = Qp + (size_t)ra * HD_ + kc * 16 + 2 * tg;
        qa[kc][0] = *(const uint32_t*)(p0);
        qa[kc][1] = *(const uint32_t*)(p0 + 8 * HD_);
        qa[kc][2] = *(const uint32_t*)(p0 + 8);
        qa[kc][3] = *(const uint32_t*)(p0 + 8 * HD_ + 8);
    }

    const int lrow = tid >> 1;
    const int ci0 = (tid & 1) * 4;
    uint32_t dsto[4];
    #pragma unroll
    for (int i = 0; i < 4; i++)
        dsto[i] = (uint32_t)(lrow * 128 + (((ci0 + i) ^ (lrow & 7)) << 4));
    const __half* Kg = Kp + (size_t)(lrow & 63) * HD_ + (lrow >> 6) * 64 + ci0 * 8;
    const __half* Vg = Vp + (size_t)lrow * S_ + ci0 * 8;

    auto load_tile = [&](int st, int kt) {
        int k0 = kt * 64;
        uint32_t kb = smb + st * AT_STAGE;
        uint32_t vb = kb + AT_BLK;
        const __half* kg = Kg + (size_t)k0 * HD_;
        const __half* vg = Vg + k0;
        #pragma unroll
        for (int i = 0; i < 4; i++) {
            cpa16(kb + dsto[i], kg + i * 8);
            cpa16(vb + dsto[i], vg + i * 8);
        }
        CP_COMMIT();
    };

    float o[16][4];
    #pragma unroll
    for (int dt = 0; dt < 16; dt++)
        #pragma unroll
        for (int q = 0; q < 4; q++) o[dt][q] = 0.f;
    float mA = -1e30f, mB = -1e30f, lA = 0.f, lB = 0.f;

    const int nkt = 2 * qt + 2;
    load_tile(0, 0);
    load_tile(1, 1);

    for (int kt = 0; kt < nkt; kt++) {
        if (kt + 1 < nkt) CP_WAIT_1(); else CP_WAIT_0();
        __syncthreads();
        if (kt + 2 < nkt) load_tile((kt + 2) % 3, kt + 2);

        const uint32_t kb = smb + (kt % 3) * AT_STAGE;
        const uint32_t vb = kb + AT_BLK;
        const int k0 = kt * 64;

        float s[8][4];
        #pragma unroll
        for (int nt = 0; nt < 8; nt++)
            #pragma unroll
            for (int q = 0; q < 4; q++) s[nt][q] = 0.f;
        #pragma unroll
        for (int kc = 0; kc < 8; kc++) {
            const int rbase = (kc >> 2) * 64;
            const int ch0 = 2 * (kc & 3);
            #pragma unroll
            for (int nt = 0; nt < 8; nt++) {
                int r = rbase + nt * 8 + gid;
                uint32_t b0 = lds32(kb + coff(r, ch0,     tg));
                uint32_t b1 = lds32(kb + coff(r, ch0 + 1, tg));
                mma_f16(s[nt], qa[kc], b0, b1);
            }
        }

        float mtA = -1e30f, mtB = -1e30f;
        #pragma unroll
        for (int nt = 0; nt < 8; nt++) {
            int c0 = k0 + nt * 8 + tg * 2, c1 = c0 + 1;
            if (c0 > ra)     s[nt][0] = -1e30f;
            if (c1 > ra)     s[nt][1] = -1e30f;
            if (c0 > ra + 8) s[nt][2] = -1e30f;
            if (c1 > ra + 8) s[nt][3] = -1e30f;
            mtA = fmaxf(mtA, fmaxf(s[nt][0], s[nt][1]));
            mtB = fmaxf(mtB, fmaxf(s[nt][2], s[nt][3]));
        }
        mtA = fmaxf(mtA, __shfl_xor_sync(0xffffffffu, mtA, 1));
        mtA = fmaxf(mtA, __shfl_xor_sync(0xffffffffu, mtA, 2));
        mtB = fmaxf(mtB, __shfl_xor_sync(0xffffffffu, mtB, 1));
        mtB = fmaxf(mtB, __shfl_xor_sync(0xffffffffu, mtB, 2));

        float mnA = fmaxf(mA, mtA), mnB = fmaxf(mB, mtB);
        float facA = __expf(mA - mnA), facB = __expf(mB - mnB);
        float lsA = 0.f, lsB = 0.f;
        #pragma unroll
        for (int nt = 0; nt < 8; nt++) {
            s[nt][0] = __expf(s[nt][0] - mnA);
            s[nt][1] = __expf(s[nt][1] - mnA);
            s[nt][2] = __expf(s[nt][2] - mnB);
            s[nt][3] = __expf(s[nt][3] - mnB);
            lsA += s[nt][0] + s[nt][1];
            lsB += s[nt][2] + s[nt][3];
        }
        lsA += __shfl_xor_sync(0xffffffffu, lsA, 1);
        lsA += __shfl_xor_sync(0xffffffffu, lsA, 2);
        lsB += __shfl_xor_sync(0xffffffffu, lsB, 1);
        lsB += __shfl_xor_sync(0xffffffffu, lsB, 2);
        lA = lA * facA + lsA;  mA = mnA;
        lB = lB * facB + lsB;  mB = mnB;

        #pragma unroll
        for (int dt = 0; dt < 16; dt++) {
            o[dt][0] *= facA; o[dt][1] *= facA;
            o[dt][2] *= facB; o[dt][3] *= facB;
        }

        #pragma unroll
        for (int j = 0; j < 4; j++) {
            uint32_t aa[4];
            aa[0] = packh2(s[2 * j][0],     s[2 * j][1]);
            aa[1] = packh2(s[2 * j][2],     s[2 * j][3]);
            aa[2] = packh2(s[2 * j + 1][0], s[2 * j + 1][1]);
            aa[3] = packh2(s[2 * j + 1][2], s[2 * j + 1][3]);
            #pragma unroll
            for (int dt = 0; dt < 16; dt++) {
                int r = dt * 8 + gid;
                uint32_t b0 = lds32(vb + coff(r, 2 * j,     tg));
                uint32_t b1 = lds32(vb + coff(r, 2 * j + 1, tg));
                mma_f16(o[dt], aa, b0, b1);
            }
        }
        __syncthreads();
    }

    float iA = 1.0f / lA, iB = 1.0f / lB;
    __half* OpA = O + (((size_t)b * S_ + ra)     * NH_ + hh) * HD_;
    __half* OpB = O + (((size_t)b * S_ + ra + 8) * NH_ + hh) * HD_;
    #pragma unroll
    for (int dt = 0; dt < 16; dt++) {
        int d = dt * 8 + tg * 2;
        *(uint32_t*)(OpA + d) = packh2(o[dt][0] * iA, o[dt][1] * iA);
        *(uint32_t*)(OpB + d) = packh2(o[dt][2] * iB, o[dt][3] * iB);
    }
}

// ---------------------------------------------------------------------------
// launch
// ---------------------------------------------------------------------------
extern "C" void kernel_launch(void* const* d_in, const int* in_sizes, int n_in,
                              void* d_out, int out_size) {
    const float* x     = (const float*)d_in[0];
    const float* freqs = (const float*)d_in[2];
    const float* w_qkv = (const float*)d_in[4];
    const float* w_fc  = (const float*)d_in[5];
    const float* w1    = (const float*)d_in[6];
    const float* w2    = (const float*)d_in[7];
    const float* w3    = (const float*)d_in[8];
    const float* anw   = (const float*)d_in[9];
    const float* fnw   = (const float*)d_in[10];
    float* out = (float*)d_out;

    float *qkv, *h;
    __half *hnorm, *qh, *kh, *vth, *attnh, *ffh, *wqkvh, *wfch, *w1h, *w2h, *w3h;
    cudaGetSymbolAddress((void**)&qkv,   g_qkv);
    cudaGetSymbolAddress((void**)&h,     g_h);
    cudaGetSymbolAddress((void**)&hnorm, g_hnorm);
    cudaGetSymbolAddress((void**)&qh,    g_qh);
    cudaGetSymbolAddress((void**)&kh,    g_kh);
    cudaGetSymbolAddress((void**)&vth,   g_vth);
    cudaGetSymbolAddress((void**)&attnh, g_attnh);
    cudaGetSymbolAddress((void**)&ffh,   g_ffh);
    cudaGetSymbolAddress((void**)&wqkvh, g_wqkvh);
    cudaGetSymbolAddress((void**)&wfch,  g_wfch);
    cudaGetSymbolAddress((void**)&w1h,   g_w1h);
    cudaGetSymbolAddress((void**)&w2h,   g_w2h);
    cudaGetSymbolAddress((void**)&w3h,   g_w3h);

    static bool attr_done = false;
    if (!attr_done) {
        cudaFuncSetAttribute(tgemm_k<0>, cudaFuncAttributeMaxDynamicSharedMemorySize, GEMM_SMEM);
        cudaFuncSetAttribute(tgemm_k<1>, cudaFuncAttributeMaxDynamicSharedMemorySize, GEMM_SMEM);
        cudaFuncSetAttribute(tgemm_k<2>, cudaFuncAttributeMaxDynamicSharedMemorySize, GEMM_SMEM);
        cudaFuncSetAttribute(attn_k, cudaFuncAttributeMaxDynamicSharedMemorySize, ATT_SMEM);
        attr_done = true;
    }

    // 0. weights -> fp16
    auto cvt = [](const float* s, __half* d, size_t n) {
        int n4 = (int)(n / 4);
        cvt_half_k<<<(n4 + 255) / 256, 256>>>(s, d, n4);
    };
    cvt(w_qkv, wqkvh, (size_t)QKV_N * E_);
    cvt(w_fc,  wfch,  (size_t)E_ * E_);
    cvt(w1,    w1h,   (size_t)FF_ * E_);
    cvt(w2,    w2h,   (size_t)FF_ * E_);
    cvt(w3,    w3h,   (size_t)E_ * FF_);

    // 1. h_norm = half(rmsnorm(x) * attn_norm_w)
    rmsnorm_k<<<T_, 256>>>(x, anw, hnorm);
    // 2. qkv(f32) = h_norm @ w_qkv^T
    tgemm_k<0><<<dim3(QKV_N / 128, T_ / 256), 256, GEMM_SMEM>>>(hnorm, wqkvh, nullptr,
                                                                nullptr, qkv, T_, QKV_N, E_);
    // 3. RoPE + split (half) and V transpose (half, [b][h][d][s])
    rope_split_k<<<T_, 256>>>(qkv, freqs, qh, kh);
    vtrans_k<<<dim3(S_ / 32, HD_ / 32, B_ * NKV_), 256>>>(qkv, vth);
    // 4. causal flash attention (fp16 mma, f32 softmax)
    attn_k<<<dim3(S_ / 128, NH_, B_), 256, ATT_SMEM>>>(qh, kh, vth, attnh);
    // 5. h(f32) = x + attnh @ w_fc^T
    tgemm_k<1><<<dim3(E_ / 128, T_ / 256), 256, GEMM_SMEM>>>(attnh, wfch, nullptr, x,
                                                             h, T_, E_, E_);
    // 6. g = half(rmsnorm(h) * ff_norm_w)
    rmsnorm_k<<<T_, 256>>>(h, fnw, hnorm);
    // 7. ffh(f16) = silu(g @ w1^T) * (g @ w2^T)
    tgemm_k<2><<<dim3(FF_ / 64, T_ / 256), 256, GEMM_SMEM>>>(hnorm, w1h, w2h, nullptr,
                                                             ffh, T_, FF_, E_);
    // 8. out(f32) = h + ffh @ w3^T
    tgemm_k<1><<<dim3(E_ / 128, T_ / 256), 256, GEMM_SMEM>>>(ffh, w3h, nullptr, h,
                                                             out, T_, E_, FF_);
}

// round 14
// speedup vs baseline: 13.8263x; 1.0075x over previous
#include <cuda_runtime.h>
#include <cuda_fp16.h>
#include <math.h>
#include <stdint.h>

// ---------------------------------------------------------------------------
// DecoderLayer: B=2, S=2048, E=2048, NH=16, NKV=4, HD=128, FF=5632
// Round 13: R9 fp16 mma GEMMs (256xBN CTA / 64x64 warp tile) +
//  - attention LPT scheduling (heavy causal tiles first)
//  - qkv GEMM emits half (MODE 3); rope/vtrans read half
//  - single segmented weight-cvt launch
// ---------------------------------------------------------------------------

#define B_    2
#define S_    2048
#define E_    2048
#define NH_   16
#define NKV_  4
#define HD_   128
#define FF_   5632
#define T_    (B_ * S_)
#define QKV_N ((NH_ + 2 * NKV_) * HD_)  // 3072

// scratch (device globals; allocation-free)
__device__ __half g_qkvh [(size_t)T_ * QKV_N];
__device__ float  g_h    [(size_t)T_ * E_];
__device__ __half g_hnorm[(size_t)T_ * E_];
__device__ __half g_qh   [(size_t)B_ * NH_  * S_ * HD_];
__device__ __half g_kh   [(size_t)B_ * NKV_ * S_ * HD_];
__device__ __half g_vth  [(size_t)B_ * NKV_ * HD_ * S_];  // [b][h][d][s]
__device__ __half g_attnh[(size_t)T_ * E_];
__device__ __half g_ffh  [(size_t)T_ * FF_];
__device__ __half g_wqkvh[(size_t)QKV_N * E_];
__device__ __half g_wfch [(size_t)E_ * E_];
__device__ __half g_w1h  [(size_t)FF_ * E_];
__device__ __half g_w2h  [(size_t)FF_ * E_];
__device__ __half g_w3h  [(size_t)E_ * FF_];

// ---------------------------------------------------------------------------
__device__ __forceinline__ uint32_t smem_u32(const void* p) {
    uint32_t a;
    asm("{ .reg .u64 t; cvta.to.shared.u64 t, %1; cvt.u32.u64 %0, t; }"
        : "=r"(a) : "l"(p));
    return a;
}
__device__ __forceinline__ uint32_t lds32(uint32_t addr) {
    uint32_t v;
    asm volatile("ld.shared.b32 %0, [%1];" : "=r"(v) : "r"(addr));
    return v;
}
__device__ __forceinline__ uint32_t packh2(float a, float b) {
    __half2 h = __floats2half2_rn(a, b);
    return *reinterpret_cast<uint32_t*>(&h);
}
__device__ __forceinline__ void cpa16(uint32_t dst, const void* src) {
    asm volatile("cp.async.cg.shared.global [%0], [%1], 16;"
                 :: "r"(dst), "l"(src) : "memory");
}
#define CP_COMMIT() asm volatile("cp.async.commit_group;" ::: "memory")
#define CP_WAIT_0() asm volatile("cp.async.wait_group 0;" ::: "memory")
#define CP_WAIT_1() asm volatile("cp.async.wait_group 1;" ::: "memory")

__device__ __forceinline__ void mma_f16(float* c, const uint32_t* a,
                                        uint32_t b0, uint32_t b1) {
    asm volatile(
        "mma.sync.aligned.m16n8k16.row.col.f32.f16.f16.f32 "
        "{%0,%1,%2,%3}, {%4,%5,%6,%7}, {%8,%9}, {%0,%1,%2,%3};"
        : "+f"(c[0]), "+f"(c[1]), "+f"(c[2]), "+f"(c[3])
        : "r"(a[0]), "r"(a[1]), "r"(a[2]), "r"(a[3]), "r"(b0), "r"(b1));
}

// XOR swizzle: byte offset of 16B chunk ch (+ tg*4) in 64-half row r
__device__ __forceinline__ uint32_t coff(int r, int ch, int tg) {
    return (uint32_t)(r * 128 + ((ch ^ (r & 7)) << 4) + tg * 4);
}

// ---------------------------------------------------------------------------
// Segmented fp32 -> fp16 weight conversion (all 5 weights, one launch).
// Segment block counts (n/4 elems per block of 256):
//   wqkv 1572864->6144 | wfc 1048576->4096 | w1 2883584->11264
//   w2 2883584->11264  | w3 2883584->11264   (total 44032 blocks)
// ---------------------------------------------------------------------------
#define CVT_B0 6144
#define CVT_B1 (CVT_B0 + 4096)     // 10240
#define CVT_B2 (CVT_B1 + 11264)    // 21504
#define CVT_B3 (CVT_B2 + 11264)    // 32768
#define CVT_B4 (CVT_B3 + 11264)    // 44032

__global__ void __launch_bounds__(256) cvt_all_k(const float* __restrict__ wqkv,
                                                 const float* __restrict__ wfc,
                                                 const float* __restrict__ w1,
                                                 const float* __restrict__ w2,
                                                 const float* __restrict__ w3,
                                                 __half* __restrict__ dqkv,
                                                 __half* __restrict__ dfc,
                                                 __half* __restrict__ d1,
                                                 __half* __restrict__ d2,
                                                 __half* __restrict__ d3) {
    int bx = blockIdx.x;
    const float* s; __half* d; int i;
    if (bx < CVT_B0)      { s = wqkv; d = dqkv; i = bx * 256 + threadIdx.x; }
    else if (bx < CVT_B1) { s = wfc;  d = dfc;  i = (bx - CVT_B0) * 256 + threadIdx.x; }
    else if (bx < CVT_B2) { s = w1;   d = d1;   i = (bx - CVT_B1) * 256 + threadIdx.x; }
    else if (bx < CVT_B3) { s = w2;   d = d2;   i = (bx - CVT_B2) * 256 + threadIdx.x; }
    else                  { s = w3;   d = d3;   i = (bx - CVT_B3) * 256 + threadIdx.x; }
    float4 v = ((const float4*)s)[i];
    uint2 o;
    o.x = packh2(v.x, v.y);
    o.y = packh2(v.z, v.w);
    ((uint2*)d)[i] = o;
}

// ---------------------------------------------------------------------------
// RMSNorm: fp32 in, fp16 out
// ---------------------------------------------------------------------------
__global__ void __launch_bounds__(256) rmsnorm_k(const float* __restrict__ x,
                                                 const float* __restrict__ w,
                                                 __half* __restrict__ o) {
    size_t base = (size_t)blockIdx.x * E_;
    int tid = threadIdx.x;
    float4 v0 = *(const float4*)(x + base + tid * 8);
    float4 v1 = *(const float4*)(x + base + tid * 8 + 4);
    float ss = v0.x*v0.x + v0.y*v0.y + v0.z*v0.z + v0.w*v0.w
             + v1.x*v1.x + v1.y*v1.y + v1.z*v1.z + v1.w*v1.w;
    #pragma unroll
    for (int off = 16; off; off >>= 1) ss += __shfl_xor_sync(0xffffffffu, ss, off);
    __shared__ float ws[8];
    if ((tid & 31) == 0) ws[tid >> 5] = ss;
    __syncthreads();
    float tot = ws[0] + ws[1] + ws[2] + ws[3] + ws[4] + ws[5] + ws[6] + ws[7];
    float sc = rsqrtf(tot * (1.0f / E_) + 1e-5f);
    float4 w0 = *(const float4*)(w + tid * 8);
    float4 w1w = *(const float4*)(w + tid * 8 + 4);
    uint4 r;
    r.x = packh2(v0.x*sc*w0.x,  v0.y*sc*w0.y);
    r.y = packh2(v0.z*sc*w0.z,  v0.w*sc*w0.w);
    r.z = packh2(v1.x*sc*w1w.x, v1.y*sc*w1w.y);
    r.w = packh2(v1.z*sc*w1w.z, v1.w*sc*w1w.w);
    *(uint4*)(o + base + tid * 8) = r;
}

// ---------------------------------------------------------------------------
// fp16 GEMM: C[M,N] = A[M,K]*B[N,K]^T. CTA tile 256 x BN, BK=64, 3-stage.
// MODE 0: C(f32) = A·B^T
// MODE 1: C(f32) = R + A·B^T
// MODE 2: C(f16) = silu(A·B^T)*(A·B2^T)   (smem B rows 64..127 = B2, BN=64)
// MODE 3: C(f16) = A·B^T
// 256 threads = 8 warps in 4(M) x 2(N) grid, warp tile 64x64.
// ---------------------------------------------------------------------------
#define GSTAGE 49152                    // (256 A rows + 128 B rows) * 128B
#define GEMM_SMEM (3 * GSTAGE)          // 147456

template <int MODE>
__global__ void __launch_bounds__(256) tgemm_k(const __half* __restrict__ A,
                                               const __half* __restrict__ Bm,
                                               const __half* __restrict__ B2,
                                               const float* __restrict__ R,
                                               void* __restrict__ Cout,
                                               int M, int N, int K) {
    extern __shared__ char sm[];
    constexpr int BN = (MODE == 2) ? 64 : 128;
    constexpr int NT = (MODE == 2) ? 4 : 8;   // n-tiles per warp per B matrix

    const int tid = threadIdx.x;
    const int m0 = blockIdx.y * 256, n0 = blockIdx.x * BN;
    const uint32_t smb = smem_u32(sm);

    // loader tables: 12 x (smem offset, global ptr)
    uint32_t so[12];
    const __half* gp[12];
    #pragma unroll
    for (int j = 0; j < 12; j++) {
        int ci = tid + j * 256;
        int row = ci >> 3, ch = ci & 7;
        so[j] = (uint32_t)(row * 128 + ((ch ^ (row & 7)) << 4));
        if (row < 256) {
            gp[j] = A + (size_t)(m0 + row) * K + ch * 8;
        } else {
            int br = row - 256;
            if (MODE == 2)
                gp[j] = ((br < 64) ? (Bm + (size_t)(n0 + br) * K)
                                   : (B2 + (size_t)(n0 + br - 64) * K)) + ch * 8;
            else
                gp[j] = Bm + (size_t)(n0 + br) * K + ch * 8;
        }
    }

    auto load_chunk = [&](int st, int c) {
        uint32_t base = smb + st * GSTAGE;
        #pragma unroll
        for (int j = 0; j < 12; j++)
            cpa16(base + so[j], gp[j] + c * 64);
        CP_COMMIT();
    };

    const int wid = tid >> 5, lane = tid & 31;
    const int gid = lane >> 2, tg = lane & 3;
    const int wm = wid >> 1, wn = wid & 1;

    float c1[4][NT][4];
    float c2[(MODE == 2) ? 4 : 1][(MODE == 2) ? NT : 1][4];
    #pragma unroll
    for (int mt = 0; mt < 4; mt++)
        #pragma unroll
        for (int nt = 0; nt < NT; nt++)
            #pragma unroll
            for (int q = 0; q < 4; q++) {
                c1[mt][nt][q] = 0.f;
                if (MODE == 2) c2[mt][nt][q] = 0.f;
            }

    const int NC = K >> 6;
    load_chunk(0, 0);
    load_chunk(1, 1);

    for (int c = 0; c < NC; c++) {
        if (c + 1 < NC) CP_WAIT_1(); else CP_WAIT_0();
        __syncthreads();
        if (c + 2 < NC) load_chunk((c + 2) % 3, c + 2);

        const uint32_t ab = smb + (c % 3) * GSTAGE;
        const uint32_t bb = ab + 32768;
        #pragma unroll
        for (int ks = 0; ks < 4; ks++) {
            uint32_t af[4][4];
            #pragma unroll
            for (int mt = 0; mt < 4; mt++) {
                int ra = wm * 64 + mt * 16 + gid;
                af[mt][0] = lds32(ab + coff(ra,     2 * ks,     tg));
                af[mt][1] = lds32(ab + coff(ra + 8, 2 * ks,     tg));
                af[mt][2] = lds32(ab + coff(ra,     2 * ks + 1, tg));
                af[mt][3] = lds32(ab + coff(ra + 8, 2 * ks + 1, tg));
            }
            uint32_t bf[NT][2];
            #pragma unroll
            for (int nt = 0; nt < NT; nt++) {
                int rb = wn * (NT * 8) + nt * 8 + gid;
                bf[nt][0] = lds32(bb + coff(rb, 2 * ks,     tg));
                bf[nt][1] = lds32(bb + coff(rb, 2 * ks + 1, tg));
            }
            #pragma unroll
            for (int mt = 0; mt < 4; mt++)
                #pragma unroll
                for (int nt = 0; nt < NT; nt++)
                    mma_f16(c1[mt][nt], af[mt], bf[nt][0], bf[nt][1]);
            if (MODE == 2) {
                uint32_t bf2[NT][2];
                #pragma unroll
                for (int nt = 0; nt < NT; nt++) {
                    int rb = 64 + wn * 32 + nt * 8 + gid;
                    bf2[nt][0] = lds32(bb + coff(rb, 2 * ks,     tg));
                    bf2[nt][1] = lds32(bb + coff(rb, 2 * ks + 1, tg));
                }
                #pragma unroll
                for (int mt = 0; mt < 4; mt++)
                    #pragma unroll
                    for (int nt = 0; nt < NT; nt++)
                        mma_f16(c2[mt][nt], af[mt], bf2[nt][0], bf2[nt][1]);
            }
        }
    }

    // epilogue
    #pragma unroll
    for (int mt = 0; mt < 4; mt++) {
        #pragma unroll
        for (int half = 0; half < 2; half++) {
            size_t row = (size_t)(m0 + wm * 64 + mt * 16 + gid + half * 8);
            #pragma unroll
            for (int nt = 0; nt < NT; nt++) {
                int col = n0 + wn * (NT * 8) + nt * 8 + tg * 2;
                float v0 = c1[mt][nt][half * 2 + 0];
                float v1 = c1[mt][nt][half * 2 + 1];
                if (MODE == 2) {
                    float u0 = c2[mt][nt][half * 2 + 0];
                    float u1 = c2[mt][nt][half * 2 + 1];
                    v0 = (v0 / (1.0f + __expf(-v0))) * u0;
                    v1 = (v1 / (1.0f + __expf(-v1))) * u1;
                    *(uint32_t*)((__half*)Cout + row * N + col) = packh2(v0, v1);
                } else if (MODE == 3) {
                    *(uint32_t*)((__half*)Cout + row * N + col) = packh2(v0, v1);
                } else {
                    if (MODE == 1) {
                        float2 res = *(const float2*)(R + row * N + col);
                        v0 += res.x; v1 += res.y;
                    }
                    *(float2*)((float*)Cout + row * N + col) = make_float2(v0, v1);
                }
            }
        }
    }
}

// ---------------------------------------------------------------------------
// RoPE + split from HALF qkv: q half pre-scaled by 1/sqrt(2048), k half.
// ---------------------------------------------------------------------------
__global__ void __launch_bounds__(256) rope_split_k(const __half* __restrict__ qkv,
                                                    const float* __restrict__ fc,
                                                    __half* __restrict__ q,
                                                    __half* __restrict__ k) {
    int t = blockIdx.x;
    int b = t >> 11;
    int s = t & 2047;
    const __half* row = qkv + (size_t)t * QKV_N;
    const float* f = fc + (size_t)s * HD_;
    const float sc = 0.022097086912079608f;  // 1/sqrt(2048)
    for (int idx = threadIdx.x; idx < NH_ * 64; idx += 256) {
        int h = idx >> 6, i = idx & 63;
        float x0 = __half2float(row[h * HD_ + 2 * i]);
        float x1 = __half2float(row[h * HD_ + 2 * i + 1]);
        float cs = f[2 * i], sn = f[2 * i + 1];
        size_t o = ((size_t)(b * NH_ + h) * S_ + s) * HD_ + 2 * i;
        *(uint32_t*)(q + o) = packh2((x0 * cs - x1 * sn) * sc,
                                     (x1 * cs + x0 * sn) * sc);
    }
    for (int idx = threadIdx.x; idx < NKV_ * 64; idx += 256) {
        int h = idx >> 6, i = idx & 63;
        float x0 = __half2float(row[NH_ * HD_ + h * HD_ + 2 * i]);
        float x1 = __half2float(row[NH_ * HD_ + h * HD_ + 2 * i + 1]);
        float cs = f[2 * i], sn = f[2 * i + 1];
        size_t o = ((size_t)(b * NKV_ + h) * S_ + s) * HD_ + 2 * i;
        *(uint32_t*)(k + o) = packh2(x0 * cs - x1 * sn, x1 * cs + x0 * sn);
    }
}

// ---------------------------------------------------------------------------
// V transpose: qkv half -> vt half [b][h][d][s], 32x32 smem tiles.
// ---------------------------------------------------------------------------
__global__ void __launch_bounds__(256) vtrans_k(const __half* __restrict__ qkv,
                                                __half* __restrict__ vt) {
    __shared__ __half tsm[32][40];   // 80B row pad: avoids bank conflicts
    int bh = blockIdx.z, b = bh >> 2, h = bh & 3;
    int s0 = blockIdx.x * 32, d0 = blockIdx.y * 32;
    int tx = threadIdx.x & 31, ty = threadIdx.x >> 5;  // 32 x 8
    #pragma unroll
    for (int i = 0; i < 4; i++) {
        int s = s0 + ty + i * 8;
        tsm[ty + i * 8][tx] =
            qkv[((size_t)(b * S_ + s)) * QKV_N + (NH_ + NKV_) * HD_ + h * HD_ + d0 + tx];
    }
    __syncthreads();
    #pragma unroll
    for (int i = 0; i < 4; i++) {
        int d = d0 + ty + i * 8;
        vt[((size_t)(b * NKV_ + h) * HD_ + d) * S_ + s0 + tx] = tsm[tx][ty + i * 8];
    }
}

// ---------------------------------------------------------------------------
// Flash attention on fp16 mma. BM=128, BN=64 kv tiles, 3-stage cp.async.
// LPT: qt reversed so heaviest causal CTAs are scheduled first.
// ---------------------------------------------------------------------------
#define AT_BLK 16384
#define AT_STAGE (2 * AT_BLK)
#define ATT_SMEM (3 * AT_STAGE)   // 98304

__global__ void __launch_bounds__(256, 1) attn_k(const __half* __restrict__ Q,
                                                 const __half* __restrict__ K,
                                                 const __half* __restrict__ Vt,
                                                 __half* __restrict__ O) {
    extern __shared__ char smc[];
    const uint32_t smb = smem_u32(smc);
    const int tid = threadIdx.x;
    const int wq = tid >> 5, lane = tid & 31;
    const int gid = lane >> 2, tg = lane & 3;
    const int qt = gridDim.x - 1 - blockIdx.x;   // LPT: heavy tiles first
    const int hh = blockIdx.y, b = blockIdx.z;
    const int q0 = qt * 128;

    const __half* Qp = Q  + (size_t)(b * NH_  + hh)        * S_ * HD_;
    const __half* Kp = K  + (size_t)(b * NKV_ + (hh >> 2)) * S_ * HD_;
    const __half* Vp = Vt + (size_t)(b * NKV_ + (hh >> 2)) * HD_ * S_;

    const int ra = q0 + wq * 16 + gid;   // rows ra, ra+8

    uint32_t qa[8][4];
    #pragma unroll
    for (int kc = 0; kc < 8; kc++) {
        const __half* p0 = Qp + (size_t)ra * HD_ + kc * 16 + 2 * tg;
        qa[kc][0] = *(const uint32_t*)(p0);
        qa[kc][1] = *(const uint32_t*)(p0 + 8 * HD_);
        qa[kc][2] = *(const uint32_t*)(p0 + 8);
        qa[kc][3] = *(const uint32_t*)(p0 + 8 * HD_ + 8);
    }

    const int lrow = tid >> 1;
    const int ci0 = (tid & 1) * 4;
    uint32_t dsto[4];
    #pragma unroll
    for (int i = 0; i < 4; i++)
        dsto[i] = (uint32_t)(lrow * 128 + (((ci0 + i) ^ (lrow & 7)) << 4));
    const __half* Kg = Kp + (size_t)(lrow & 63) * HD_ + (lrow >> 6) * 64 + ci0 * 8;
    const __half* Vg = Vp + (size_t)lrow * S_ + ci0 * 8;

    auto load_tile = [&](int st, int kt) {
        int k0 = kt * 64;
        uint32_t kb = smb + st * AT_STAGE;
        uint32_t vb = kb + AT_BLK;
        const __half* kg = Kg + (size_t)k0 * HD_;
        const __half* vg = Vg + k0;
        #pragma unroll
        for (int i = 0; i < 4; i++) {
            cpa16(kb + dsto[i], kg + i * 8);
            cpa16(vb + dsto[i], vg + i * 8);
        }
        CP_COMMIT();
    };

    float o[16][4];
    #pragma unroll
    for (int dt = 0; dt < 16; dt++)
        #pragma unroll
        for (int q = 0; q < 4; q++) o[dt][q] = 0.f;
    float mA = -1e30f, mB = -1e30f, lA = 0.f, lB = 0.f;

    const int nkt = 2 * qt + 2;
    load_tile(0, 0);
    load_tile(1, 1);

    for (int kt = 0; kt < nkt; kt++) {
        if (kt + 1 < nkt) CP_WAIT_1(); else CP_WAIT_0();
        __syncthreads();
        if (kt + 2 < nkt) load_tile((kt + 2) % 3, kt + 2);

        const uint32_t kb = smb + (kt % 3) * AT_STAGE;
        const uint32_t vb = kb + AT_BLK;
        const int k0 = kt * 64;

        float s[8][4];
        #pragma unroll
        for (int nt = 0; nt < 8; nt++)
            #pragma unroll
            for (int q = 0; q < 4; q++) s[nt][q] = 0.f;
        #pragma unroll
        for (int kc = 0; kc < 8; kc++) {
            const int rbase = (kc >> 2) * 64;
            const int ch0 = 2 * (kc & 3);
            #pragma unroll
            for (int nt = 0; nt < 8; nt++) {
                int r = rbase + nt * 8 + gid;
                uint32_t b0 = lds32(kb + coff(r, ch0,     tg));
                uint32_t b1 = lds32(kb + coff(r, ch0 + 1, tg));
                mma_f16(s[nt], qa[kc], b0, b1);
            }
        }

        float mtA = -1e30f, mtB = -1e30f;
        #pragma unroll
        for (int nt = 0; nt < 8; nt++) {
            int c0 = k0 + nt * 8 + tg * 2, c1 = c0 + 1;
            if (c0 > ra)     s[nt][0] = -1e30f;
            if (c1 > ra)     s[nt][1] = -1e30f;
            if (c0 > ra + 8) s[nt][2] = -1e30f;
            if (c1 > ra + 8) s[nt][3] = -1e30f;
            mtA = fmaxf(mtA, fmaxf(s[nt][0], s[nt][1]));
            mtB = fmaxf(mtB, fmaxf(s[nt][2], s[nt][3]));
        }
        mtA = fmaxf(mtA, __shfl_xor_sync(0xffffffffu, mtA, 1));
        mtA = fmaxf(mtA, __shfl_xor_sync(0xffffffffu, mtA, 2));
        mtB = fmaxf(mtB, __shfl_xor_sync(0xffffffffu, mtB, 1));
        mtB = fmaxf(mtB, __shfl_xor_sync(0xffffffffu, mtB, 2));

        float mnA = fmaxf(mA, mtA), mnB = fmaxf(mB, mtB);
        float facA = __expf(mA - mnA), facB = __expf(mB - mnB);
        float lsA = 0.f, lsB = 0.f;
        #pragma unroll
        for (int nt = 0; nt < 8; nt++) {
            s[nt][0] = __expf(s[nt][0] - mnA);
            s[nt][1] = __expf(s[nt][1] - mnA);
            s[nt][2] = __expf(s[nt][2] - mnB);
            s[nt][3] = __expf(s[nt][3] - mnB);
            lsA += s[nt][0] + s[nt][1];
            lsB += s[nt][2] + s[nt][3];
        }
        lsA += __shfl_xor_sync(0xffffffffu, lsA, 1);
        lsA += __shfl_xor_sync(0xffffffffu, lsA, 2);
        lsB += __shfl_xor_sync(0xffffffffu, lsB, 1);
        lsB += __shfl_xor_sync(0xffffffffu, lsB, 2);
        lA = lA * facA + lsA;  mA = mnA;
        lB = lB * facB + lsB;  mB = mnB;

        #pragma unroll
        for (int dt = 0; dt < 16; dt++) {
            o[dt][0] *= facA; o[dt][1] *= facA;
            o[dt][2] *= facB; o[dt][3] *= facB;
        }

        #pragma unroll
        for (int j = 0; j < 4; j++) {
            uint32_t aa[4];
            aa[0] = packh2(s[2 * j][0],     s[2 * j][1]);
            aa[1] = packh2(s[2 * j][2],     s[2 * j][3]);
            aa[2] = packh2(s[2 * j + 1][0], s[2 * j + 1][1]);
            aa[3] = packh2(s[2 * j + 1][2], s[2 * j + 1][3]);
            #pragma unroll
            for (int dt = 0; dt < 16; dt++) {
                int r = dt * 8 + gid;
                uint32_t b0 = lds32(vb + coff(r, 2 * j,     tg));
                uint32_t b1 = lds32(vb + coff(r, 2 * j + 1, tg));
                mma_f16(o[dt], aa, b0, b1);
            }
        }
        __syncthreads();
    }

    float iA = 1.0f / lA, iB = 1.0f / lB;
    __half* OpA = O + (((size_t)b * S_ + ra)     * NH_ + hh) * HD_;
    __half* OpB = O + (((size_t)b * S_ + ra + 8) * NH_ + hh) * HD_;
    #pragma unroll
    for (int dt = 0; dt < 16; dt++) {
        int d = dt * 8 + tg * 2;
        *(uint32_t*)(OpA + d) = packh2(o[dt][0] * iA, o[dt][1] * iA);
        *(uint32_t*)(OpB + d) = packh2(o[dt][2] * iB, o[dt][3] * iB);
    }
}

// ---------------------------------------------------------------------------
// launch
// ---------------------------------------------------------------------------
extern "C" void kernel_launch(void* const* d_in, const int* in_sizes, int n_in,
                              void* d_out, int out_size) {
    const float* x     = (const float*)d_in[0];
    const float* freqs = (const float*)d_in[2];
    const float* w_qkv = (const float*)d_in[4];
    const float* w_fc  = (const float*)d_in[5];
    const float* w1    = (const float*)d_in[6];
    const float* w2    = (const float*)d_in[7];
    const float* w3    = (const float*)d_in[8];
    const float* anw   = (const float*)d_in[9];
    const float* fnw   = (const float*)d_in[10];
    float* out = (float*)d_out;

    float *h;
    __half *qkvh, *hnorm, *qh, *kh, *vth, *attnh, *ffh;
    __half *wqkvh, *wfch, *w1h, *w2h, *w3h;
    cudaGetSymbolAddress((void**)&qkvh,  g_qkvh);
    cudaGetSymbolAddress((void**)&h,     g_h);
    cudaGetSymbolAddress((void**)&hnorm, g_hnorm);
    cudaGetSymbolAddress((void**)&qh,    g_qh);
    cudaGetSymbolAddress((void**)&kh,    g_kh);
    cudaGetSymbolAddress((void**)&vth,   g_vth);
    cudaGetSymbolAddress((void**)&attnh, g_attnh);
    cudaGetSymbolAddress((void**)&ffh,   g_ffh);
    cudaGetSymbolAddress((void**)&wqkvh, g_wqkvh);
    cudaGetSymbolAddress((void**)&wfch,  g_wfch);
    cudaGetSymbolAddress((void**)&w1h,   g_w1h);
    cudaGetSymbolAddress((void**)&w2h,   g_w2h);
    cudaGetSymbolAddress((void**)&w3h,   g_w3h);

    static bool attr_done = false;
    if (!attr_done) {
        cudaFuncSetAttribute(tgemm_k<1>, cudaFuncAttributeMaxDynamicSharedMemorySize, GEMM_SMEM);
        cudaFuncSetAttribute(tgemm_k<2>, cudaFuncAttributeMaxDynamicSharedMemorySize, GEMM_SMEM);
        cudaFuncSetAttribute(tgemm_k<3>, cudaFuncAttributeMaxDynamicSharedMemorySize, GEMM_SMEM);
        cudaFuncSetAttribute(attn_k, cudaFuncAttributeMaxDynamicSharedMemorySize, ATT_SMEM);
        attr_done = true;
    }

    // 0. weights -> fp16 (single segmented launch)
    cvt_all_k<<<CVT_B4, 256>>>(w_qkv, w_fc, w1, w2, w3,
                               wqkvh, wfch, w1h, w2h, w3h);

    // 1. h_norm = half(rmsnorm(x) * attn_norm_w)
    rmsnorm_k<<<T_, 256>>>(x, anw, hnorm);
    // 2. qkv(f16) = h_norm @ w_qkv^T
    tgemm_k<3><<<dim3(QKV_N / 128, T_ / 256), 256, GEMM_SMEM>>>(hnorm, wqkvh, nullptr,
                                                                nullptr, qkvh, T_, QKV_N, E_);
    // 3. RoPE + split (half) and V transpose (half, [b][h][d][s])
    rope_split_k<<<T_, 256>>>(qkvh, freqs, qh, kh);
    vtrans_k<<<dim3(S_ / 32, HD_ / 32, B_ * NKV_), 256>>>(qkvh, vth);
    // 4. causal flash attention (fp16 mma, f32 softmax, LPT order)
    attn_k<<<dim3(S_ / 128, NH_, B_), 256, ATT_SMEM>>>(qh, kh, vth, attnh);
    // 5. h(f32) = x + attnh @ w_fc^T
    tgemm_k<1><<<dim3(E_ / 128, T_ / 256), 256, GEMM_SMEM>>>(attnh, wfch, nullptr, x,
                                                             h, T_, E_, E_);
    // 6. g = half(rmsnorm(h) * ff_norm_w)
    rmsnorm_k<<<T_, 256>>>(h, fnw, hnorm);
    // 7. ffh(f16) = silu(g @ w1^T) * (g @ w2^T)
    tgemm_k<2><<<dim3(FF_ / 64, T_ / 256), 256, GEMM_SMEM>>>(hnorm, w1h, w2h, nullptr,
                                                             ffh, T_, FF_, E_);
    // 8. out(f32) = h + ffh @ w3^T
    tgemm_k<1><<<dim3(E_ / 128, T_ / 256), 256, GEMM_SMEM>>>(ffh, w3h, nullptr, h,
                                                             out, T_, E_, FF_);
}

// round 15
// speedup vs baseline: 14.2326x; 1.0294x over previous
#include <cuda_runtime.h>
#include <cuda_fp16.h>
#include <math.h>
#include <stdint.h>

// ---------------------------------------------------------------------------
// DecoderLayer: B=2, S=2048, E=2048, NH=16, NKV=4, HD=128, FF=5632
// Round 14: R13 + ldmatrix.x4 fragment loads in GEMM and attention mainloops
// (32 LDS.32 -> 8 LDSM.x4 per ks-step) + ILP-4 weight conversion.
// ---------------------------------------------------------------------------

#define B_    2
#define S_    2048
#define E_    2048
#define NH_   16
#define NKV_  4
#define HD_   128
#define FF_   5632
#define T_    (B_ * S_)
#define QKV_N ((NH_ + 2 * NKV_) * HD_)  // 3072

// scratch (device globals; allocation-free)
__device__ __half g_qkvh [(size_t)T_ * QKV_N];
__device__ float  g_h    [(size_t)T_ * E_];
__device__ __half g_hnorm[(size_t)T_ * E_];
__device__ __half g_qh   [(size_t)B_ * NH_  * S_ * HD_];
__device__ __half g_kh   [(size_t)B_ * NKV_ * S_ * HD_];
__device__ __half g_vth  [(size_t)B_ * NKV_ * HD_ * S_];  // [b][h][d][s]
__device__ __half g_attnh[(size_t)T_ * E_];
__device__ __half g_ffh  [(size_t)T_ * FF_];
__device__ __half g_wqkvh[(size_t)QKV_N * E_];
__device__ __half g_wfch [(size_t)E_ * E_];
__device__ __half g_w1h  [(size_t)FF_ * E_];
__device__ __half g_w2h  [(size_t)FF_ * E_];
__device__ __half g_w3h  [(size_t)E_ * FF_];

// ---------------------------------------------------------------------------
__device__ __forceinline__ uint32_t smem_u32(const void* p) {
    uint32_t a;
    asm("{ .reg .u64 t; cvta.to.shared.u64 t, %1; cvt.u32.u64 %0, t; }"
        : "=r"(a) : "l"(p));
    return a;
}
__device__ __forceinline__ uint32_t packh2(float a, float b) {
    __half2 h = __floats2half2_rn(a, b);
    return *reinterpret_cast<uint32_t*>(&h);
}
__device__ __forceinline__ void cpa16(uint32_t dst, const void* src) {
    asm volatile("cp.async.cg.shared.global [%0], [%1], 16;"
                 :: "r"(dst), "l"(src) : "memory");
}
#define CP_COMMIT() asm volatile("cp.async.commit_group;" ::: "memory")
#define CP_WAIT_0() asm volatile("cp.async.wait_group 0;" ::: "memory")
#define CP_WAIT_1() asm volatile("cp.async.wait_group 1;" ::: "memory")

__device__ __forceinline__ void mma_f16(float* c, const uint32_t* a,
                                        uint32_t b0, uint32_t b1) {
    asm volatile(
        "mma.sync.aligned.m16n8k16.row.col.f32.f16.f16.f32 "
        "{%0,%1,%2,%3}, {%4,%5,%6,%7}, {%8,%9}, {%0,%1,%2,%3};"
        : "+f"(c[0]), "+f"(c[1]), "+f"(c[2]), "+f"(c[3])
        : "r"(a[0]), "r"(a[1]), "r"(a[2]), "r"(a[3]), "r"(b0), "r"(b1));
}
__device__ __forceinline__ void ldsm_x4(uint32_t& r0, uint32_t& r1,
                                        uint32_t& r2, uint32_t& r3,
                                        uint32_t addr) {
    asm volatile("ldmatrix.sync.aligned.m8n8.x4.shared.b16 {%0,%1,%2,%3}, [%4];"
                 : "=r"(r0), "=r"(r1), "=r"(r2), "=r"(r3) : "r"(addr));
}

// ---------------------------------------------------------------------------
// Segmented fp32 -> fp16 weight conversion, 4 float4 per thread (ILP-4).
// Block = 1024 float4s. wqkv 1536 | wfc 1024 | w1/w2/w3 2816 each.
// ---------------------------------------------------------------------------
#define CVT_B0 1536
#define CVT_B1 (CVT_B0 + 1024)    // 2560
#define CVT_B2 (CVT_B1 + 2816)    // 5376
#define CVT_B3 (CVT_B2 + 2816)    // 8192
#define CVT_B4 (CVT_B3 + 2816)    // 11008

__global__ void __launch_bounds__(256) cvt_all_k(const float* __restrict__ wqkv,
                                                 const float* __restrict__ wfc,
                                                 const float* __restrict__ w1,
                                                 const float* __restrict__ w2,
                                                 const float* __restrict__ w3,
                                                 __half* __restrict__ dqkv,
                                                 __half* __restrict__ dfc,
                                                 __half* __restrict__ d1,
                                                 __half* __restrict__ d2,
                                                 __half* __restrict__ d3) {
    int bx = blockIdx.x;
    const float* s; __half* d; int sb;
    if (bx < CVT_B0)      { s = wqkv; d = dqkv; sb = bx; }
    else if (bx < CVT_B1) { s = wfc;  d = dfc;  sb = bx - CVT_B0; }
    else if (bx < CVT_B2) { s = w1;   d = d1;   sb = bx - CVT_B1; }
    else if (bx < CVT_B3) { s = w2;   d = d2;   sb = bx - CVT_B2; }
    else                  { s = w3;   d = d3;   sb = bx - CVT_B3; }
    int i0 = sb * 1024 + threadIdx.x;
    float4 v[4];
    #pragma unroll
    for (int j = 0; j < 4; j++) v[j] = ((const float4*)s)[i0 + j * 256];
    #pragma unroll
    for (int j = 0; j < 4; j++) {
        uint2 o;
        o.x = packh2(v[j].x, v[j].y);
        o.y = packh2(v[j].z, v[j].w);
        ((uint2*)d)[i0 + j * 256] = o;
    }
}

// ---------------------------------------------------------------------------
// RMSNorm: fp32 in, fp16 out
// ---------------------------------------------------------------------------
__global__ void __launch_bounds__(256) rmsnorm_k(const float* __restrict__ x,
                                                 const float* __restrict__ w,
                                                 __half* __restrict__ o) {
    size_t base = (size_t)blockIdx.x * E_;
    int tid = threadIdx.x;
    float4 v0 = *(const float4*)(x + base + tid * 8);
    float4 v1 = *(const float4*)(x + base + tid * 8 + 4);
    float ss = v0.x*v0.x + v0.y*v0.y + v0.z*v0.z + v0.w*v0.w
             + v1.x*v1.x + v1.y*v1.y + v1.z*v1.z + v1.w*v1.w;
    #pragma unroll
    for (int off = 16; off; off >>= 1) ss += __shfl_xor_sync(0xffffffffu, ss, off);
    __shared__ float ws[8];
    if ((tid & 31) == 0) ws[tid >> 5] = ss;
    __syncthreads();
    float tot = ws[0] + ws[1] + ws[2] + ws[3] + ws[4] + ws[5] + ws[6] + ws[7];
    float sc = rsqrtf(tot * (1.0f / E_) + 1e-5f);
    float4 w0 = *(const float4*)(w + tid * 8);
    float4 w1w = *(const float4*)(w + tid * 8 + 4);
    uint4 r;
    r.x = packh2(v0.x*sc*w0.x,  v0.y*sc*w0.y);
    r.y = packh2(v0.z*sc*w0.z,  v0.w*sc*w0.w);
    r.z = packh2(v1.x*sc*w1w.x, v1.y*sc*w1w.y);
    r.w = packh2(v1.z*sc*w1w.z, v1.w*sc*w1w.w);
    *(uint4*)(o + base + tid * 8) = r;
}

// ---------------------------------------------------------------------------
// fp16 GEMM: C[M,N] = A[M,K]*B[N,K]^T. CTA tile 256 x BN, BK=64, 3-stage.
// MODE 1: C(f32) = R + A·B^T              (BN=128)
// MODE 2: C(f16) = silu(A·B^T)*(A·B2^T)   (BN=64; smem B rows 64..127 = B2)
// MODE 3: C(f16) = A·B^T                  (BN=128)
// 8 warps (4M x 2N), warp tile 64x64. Fragments via ldmatrix.x4.
// Swizzle note: all fragment rows are 8k+(lane&7), so the XOR term is
// ((ch ^ (lane&7))<<4) uniformly -- computed once per ks-step.
// ---------------------------------------------------------------------------
#define GSTAGE 49152                    // (256 A rows + 128 B rows) * 128B
#define GEMM_SMEM (3 * GSTAGE)          // 147456

template <int MODE>
__global__ void __launch_bounds__(256) tgemm_k(const __half* __restrict__ A,
                                               const __half* __restrict__ Bm,
                                               const __half* __restrict__ B2,
                                               const float* __restrict__ R,
                                               void* __restrict__ Cout,
                                               int M, int N, int K) {
    extern __shared__ char sm[];
    constexpr int BN = (MODE == 2) ? 64 : 128;
    constexpr int NT = (MODE == 2) ? 4 : 8;   // n-tiles per warp per B matrix

    const int tid = threadIdx.x;
    const int m0 = blockIdx.y * 256, n0 = blockIdx.x * BN;
    const uint32_t smb = smem_u32(sm);

    // loader tables: 12 x (smem offset, global ptr)
    uint32_t so[12];
    const __half* gp[12];
    #pragma unroll
    for (int j = 0; j < 12; j++) {
        int ci = tid + j * 256;
        int row = ci >> 3, ch = ci & 7;
        so[j] = (uint32_t)(row * 128 + ((ch ^ (row & 7)) << 4));
        if (row < 256) {
            gp[j] = A + (size_t)(m0 + row) * K + ch * 8;
        } else {
            int br = row - 256;
            if (MODE == 2)
                gp[j] = ((br < 64) ? (Bm + (size_t)(n0 + br) * K)
                                   : (B2 + (size_t)(n0 + br - 64) * K)) + ch * 8;
            else
                gp[j] = Bm + (size_t)(n0 + br) * K + ch * 8;
        }
    }

    auto load_chunk = [&](int st, int c) {
        uint32_t base = smb + st * GSTAGE;
        #pragma unroll
        for (int j = 0; j < 12; j++)
            cpa16(base + so[j], gp[j] + c * 64);
        CP_COMMIT();
    };

    const int wid = tid >> 5, lane = tid & 31;
    const int gid = lane >> 2, tg = lane & 3;
    const int wm = wid >> 1, wn = wid & 1;
    const int l7 = lane & 7;
    const int lhi = lane >> 4;            // 0/1
    const int lbit3 = (lane >> 3) & 1;    // 0/1

    // ldmatrix row-byte offsets (swizzle XOR applied separately per ks)
    uint32_t rowA[4], rowB[NT / 2];
    #pragma unroll
    for (int mt = 0; mt < 4; mt++)
        rowA[mt] = (uint32_t)((wm * 64 + mt * 16 + (lane & 15)) * 128);
    #pragma unroll
    for (int p = 0; p < NT / 2; p++)
        rowB[p] = (uint32_t)((wn * (NT * 8) + (2 * p + lhi) * 8 + l7) * 128);
    uint32_t rowB2[(MODE == 2) ? 2 : 1];
    if (MODE == 2) {
        #pragma unroll
        for (int p = 0; p < 2; p++)
            rowB2[p] = (uint32_t)((64 + wn * 32 + (2 * p + lhi) * 8 + l7) * 128);
    }

    float c1[4][NT][4];
    float c2[(MODE == 2) ? 4 : 1][(MODE == 2) ? NT : 1][4];
    #pragma unroll
    for (int mt = 0; mt < 4; mt++)
        #pragma unroll
        for (int nt = 0; nt < NT; nt++)
            #pragma unroll
            for (int q = 0; q < 4; q++) {
                c1[mt][nt][q] = 0.f;
                if (MODE == 2) c2[mt][nt][q] = 0.f;
            }

    const int NC = K >> 6;
    load_chunk(0, 0);
    load_chunk(1, 1);

    for (int c = 0; c < NC; c++) {
        if (c + 1 < NC) CP_WAIT_1(); else CP_WAIT_0();
        __syncthreads();
        if (c + 2 < NC) load_chunk((c + 2) % 3, c + 2);

        const uint32_t ab = smb + (c % 3) * GSTAGE;
        const uint32_t bb = ab + 32768;
        #pragma unroll
        for (int ks = 0; ks < 4; ks++) {
            const uint32_t swA = (uint32_t)(((2 * ks + lhi)   ^ l7) << 4);
            const uint32_t swB = (uint32_t)(((2 * ks + lbit3) ^ l7) << 4);
            uint32_t af[4][4];
            #pragma unroll
            for (int mt = 0; mt < 4; mt++)
                ldsm_x4(af[mt][0], af[mt][1], af[mt][2], af[mt][3],
                        ab + rowA[mt] + swA);
            uint32_t bf[NT][2];
            #pragma unroll
            for (int p = 0; p < NT / 2; p++)
                ldsm_x4(bf[2 * p][0], bf[2 * p][1], bf[2 * p + 1][0],
                        bf[2 * p + 1][1], bb + rowB[p] + swB);
            #pragma unroll
            for (int mt = 0; mt < 4; mt++)
                #pragma unroll
                for (int nt = 0; nt < NT; nt++)
                    mma_f16(c1[mt][nt], af[mt], bf[nt][0], bf[nt][1]);
            if (MODE == 2) {
                uint32_t bf2[NT][2];
                #pragma unroll
                for (int p = 0; p < 2; p++)
                    ldsm_x4(bf2[2 * p][0], bf2[2 * p][1], bf2[2 * p + 1][0],
                            bf2[2 * p + 1][1], bb + rowB2[p] + swB);
                #pragma unroll
                for (int mt = 0; mt < 4; mt++)
                    #pragma unroll
                    for (int nt = 0; nt < NT; nt++)
                        mma_f16(c2[mt][nt], af[mt], bf2[nt][0], bf2[nt][1]);
            }
        }
    }

    // epilogue
    #pragma unroll
    for (int mt = 0; mt < 4; mt++) {
        #pragma unroll
        for (int half = 0; half < 2; half++) {
            size_t row = (size_t)(m0 + wm * 64 + mt * 16 + gid + half * 8);
            #pragma unroll
            for (int nt = 0; nt < NT; nt++) {
                int col = n0 + wn * (NT * 8) + nt * 8 + tg * 2;
                float v0 = c1[mt][nt][half * 2 + 0];
                float v1 = c1[mt][nt][half * 2 + 1];
                if (MODE == 2) {
                    float u0 = c2[mt][nt][half * 2 + 0];
                    float u1 = c2[mt][nt][half * 2 + 1];
                    v0 = (v0 / (1.0f + __expf(-v0))) * u0;
                    v1 = (v1 / (1.0f + __expf(-v1))) * u1;
                    *(uint32_t*)((__half*)Cout + row * N + col) = packh2(v0, v1);
                } else if (MODE == 3) {
                    *(uint32_t*)((__half*)Cout + row * N + col) = packh2(v0, v1);
                } else {
                    float2 res = *(const float2*)(R + row * N + col);
                    v0 += res.x; v1 += res.y;
                    *(float2*)((float*)Cout + row * N + col) = make_float2(v0, v1);
                }
            }
        }
    }
}

// ---------------------------------------------------------------------------
// RoPE + split from half qkv: q half pre-scaled by 1/sqrt(2048), k half.
// ---------------------------------------------------------------------------
__global__ void __launch_bounds__(256) rope_split_k(const __half* __restrict__ qkv,
                                                    const float* __restrict__ fc,
                                                    __half* __restrict__ q,
                                                    __half* __restrict__ k) {
    int t = blockIdx.x;
    int b = t >> 11;
    int s = t & 2047;
    const __half* row = qkv + (size_t)t * QKV_N;
    const float* f = fc + (size_t)s * HD_;
    const float sc = 0.022097086912079608f;  // 1/sqrt(2048)
    for (int idx = threadIdx.x; idx < NH_ * 64; idx += 256) {
        int h = idx >> 6, i = idx & 63;
        float x0 = __half2float(row[h * HD_ + 2 * i]);
        float x1 = __half2float(row[h * HD_ + 2 * i + 1]);
        float cs = f[2 * i], sn = f[2 * i + 1];
        size_t o = ((size_t)(b * NH_ + h) * S_ + s) * HD_ + 2 * i;
        *(uint32_t*)(q + o) = packh2((x0 * cs - x1 * sn) * sc,
                                     (x1 * cs + x0 * sn) * sc);
    }
    for (int idx = threadIdx.x; idx < NKV_ * 64; idx += 256) {
        int h = idx >> 6, i = idx & 63;
        float x0 = __half2float(row[NH_ * HD_ + h * HD_ + 2 * i]);
        float x1 = __half2float(row[NH_ * HD_ + h * HD_ + 2 * i + 1]);
        float cs = f[2 * i], sn = f[2 * i + 1];
        size_t o = ((size_t)(b * NKV_ + h) * S_ + s) * HD_ + 2 * i;
        *(uint32_t*)(k + o) = packh2(x0 * cs - x1 * sn, x1 * cs + x0 * sn);
    }
}

// ---------------------------------------------------------------------------
// V transpose: qkv half -> vt half [b][h][d][s], 32x32 smem tiles.
// ---------------------------------------------------------------------------
__global__ void __launch_bounds__(256) vtrans_k(const __half* __restrict__ qkv,
                                                __half* __restrict__ vt) {
    __shared__ __half tsm[32][40];
    int bh = blockIdx.z, b = bh >> 2, h = bh & 3;
    int s0 = blockIdx.x * 32, d0 = blockIdx.y * 32;
    int tx = threadIdx.x & 31, ty = threadIdx.x >> 5;  // 32 x 8
    #pragma unroll
    for (int i = 0; i < 4; i++) {
        int s = s0 + ty + i * 8;
        tsm[ty + i * 8][tx] =
            qkv[((size_t)(b * S_ + s)) * QKV_N + (NH_ + NKV_) * HD_ + h * HD_ + d0 + tx];
    }
    __syncthreads();
    #pragma unroll
    for (int i = 0; i < 4; i++) {
        int d = d0 + ty + i * 8;
        vt[((size_t)(b * NKV_ + h) * HD_ + d) * S_ + s0 + tx] = tsm[tx][ty + i * 8];
    }
}

// ---------------------------------------------------------------------------
// Flash attention on fp16 mma. BM=128, BN=64 kv tiles, 3-stage cp.async.
// LPT order; K/Vt fragments via ldmatrix.x4.
// ---------------------------------------------------------------------------
#define AT_BLK 16384
#define AT_STAGE (2 * AT_BLK)
#define ATT_SMEM (3 * AT_STAGE)   // 98304

__global__ void __launch_bounds__(256, 1) attn_k(const __half* __restrict__ Q,
                                                 const __half* __restrict__ K,
                                                 const __half* __restrict__ Vt,
                                                 __half* __restrict__ O) {
    extern __shared__ char smc[];
    const uint32_t smb = smem_u32(smc);
    const int tid = threadIdx.x;
    const int wq = tid >> 5, lane = tid & 31;
    const int gid = lane >> 2, tg = lane & 3;
    const int l7 = lane & 7;
    const int lhi = lane >> 4;
    const int lbit3 = (lane >> 3) & 1;
    const int qt = gridDim.x - 1 - blockIdx.x;   // LPT: heavy tiles first
    const int hh = blockIdx.y, b = blockIdx.z;
    const int q0 = qt * 128;

    const __half* Qp = Q  + (size_t)(b * NH_  + hh)        * S_ * HD_;
    const __half* Kp = K  + (size_t)(b * NKV_ + (hh >> 2)) * S_ * HD_;
    const __half* Vp = Vt + (size_t)(b * NKV_ + (hh >> 2)) * HD_ * S_;

    const int ra = q0 + wq * 16 + gid;   // rows ra, ra+8

    uint32_t qa[8][4];
    #pragma unroll
    for (int kc = 0; kc < 8; kc++) {
        const __half* p0 = Qp + (size_t)ra * HD_ + kc * 16 + 2 * tg;
        qa[kc][0] = *(const uint32_t*)(p0);
        qa[kc][1] = *(const uint32_t*)(p0 + 8 * HD_);
        qa[kc][2] = *(const uint32_t*)(p0 + 8);
        qa[kc][3] = *(const uint32_t*)(p0 + 8 * HD_ + 8);
    }

    const int lrow = tid >> 1;
    const int ci0 = (tid & 1) * 4;
    uint32_t dsto[4];
    #pragma unroll
    for (int i = 0; i < 4; i++)
        dsto[i] = (uint32_t)(lrow * 128 + (((ci0 + i) ^ (lrow & 7)) << 4));
    const __half* Kg = Kp + (size_t)(lrow & 63) * HD_ + (lrow >> 6) * 64 + ci0 * 8;
    const __half* Vg = Vp + (size_t)lrow * S_ + ci0 * 8;

    auto load_tile = [&](int st, int kt) {
        int k0 = kt * 64;
        uint32_t kb = smb + st * AT_STAGE;
        uint32_t vb = kb + AT_BLK;
        const __half* kg = Kg + (size_t)k0 * HD_;
        const __half* vg = Vg + k0;
        #pragma unroll
        for (int i = 0; i < 4; i++) {
            cpa16(kb + dsto[i], kg + i * 8);
            cpa16(vb + dsto[i], vg + i * 8);
        }
        CP_COMMIT();
    };

    // ldmatrix row-byte offsets
    uint32_t rowKV[8];
    #pragma unroll
    for (int p = 0; p < 8; p++)
        rowKV[p] = (uint32_t)(((2 * p + lhi) * 8 + l7) * 128);

    float o[16][4];
    #pragma unroll
    for (int dt = 0; dt < 16; dt++)
        #pragma unroll
        for (int q = 0; q < 4; q++) o[dt][q] = 0.f;
    float mA = -1e30f, mB = -1e30f, lA = 0.f, lB = 0.f;

    const int nkt = 2 * qt + 2;
    load_tile(0, 0);
    load_tile(1, 1);

    for (int kt = 0; kt < nkt; kt++) {
        if (kt + 1 < nkt) CP_WAIT_1(); else CP_WAIT_0();
        __syncthreads();
        if (kt + 2 < nkt) load_tile((kt + 2) % 3, kt + 2);

        const uint32_t kb = smb + (kt % 3) * AT_STAGE;
        const uint32_t vb = kb + AT_BLK;
        const int k0 = kt * 64;

        float s[8][4];
        #pragma unroll
        for (int nt = 0; nt < 8; nt++)
            #pragma unroll
            for (int q = 0; q < 4; q++) s[nt][q] = 0.f;
        #pragma unroll
        for (int kc = 0; kc < 8; kc++) {
            const uint32_t kb2 = kb + (uint32_t)((kc >> 2) * 8192);
            const uint32_t swK = (uint32_t)(((2 * (kc & 3) + lbit3) ^ l7) << 4);
            #pragma unroll
            for (int p = 0; p < 4; p++) {
                uint32_t b0, b1, b2, b3;
                ldsm_x4(b0, b1, b2, b3, kb2 + rowKV[p] + swK);
                mma_f16(s[2 * p],     qa[kc], b0, b1);
                mma_f16(s[2 * p + 1], qa[kc], b2, b3);
            }
        }

        float mtA = -1e30f, mtB = -1e30f;
        #pragma unroll
        for (int nt = 0; nt < 8; nt++) {
            int c0 = k0 + nt * 8 + tg * 2, c1 = c0 + 1;
            if (c0 > ra)     s[nt][0] = -1e30f;
            if (c1 > ra)     s[nt][1] = -1e30f;
            if (c0 > ra + 8) s[nt][2] = -1e30f;
            if (c1 > ra + 8) s[nt][3] = -1e30f;
            mtA = fmaxf(mtA, fmaxf(s[nt][0], s[nt][1]));
            mtB = fmaxf(mtB, fmaxf(s[nt][2], s[nt][3]));
        }
        mtA = fmaxf(mtA, __shfl_xor_sync(0xffffffffu, mtA, 1));
        mtA = fmaxf(mtA, __shfl_xor_sync(0xffffffffu, mtA, 2));
        mtB = fmaxf(mtB, __shfl_xor_sync(0xffffffffu, mtB, 1));
        mtB = fmaxf(mtB, __shfl_xor_sync(0xffffffffu, mtB, 2));

        float mnA = fmaxf(mA, mtA), mnB = fmaxf(mB, mtB);
        float facA = __expf(mA - mnA), facB = __expf(mB - mnB);
        float lsA = 0.f, lsB = 0.f;
        #pragma unroll
        for (int nt = 0; nt < 8; nt++) {
            s[nt][0] = __expf(s[nt][0] - mnA);
            s[nt][1] = __expf(s[nt][1] - mnA);
            s[nt][2] = __expf(s[nt][2] - mnB);
            s[nt][3] = __expf(s[nt][3] - mnB);
            lsA += s[nt][0] + s[nt][1];
            lsB += s[nt][2] + s[nt][3];
        }
        lsA += __shfl_xor_sync(0xffffffffu, lsA, 1);
        lsA += __shfl_xor_sync(0xffffffffu, lsA, 2);
        lsB += __shfl_xor_sync(0xffffffffu, lsB, 1);
        lsB += __shfl_xor_sync(0xffffffffu, lsB, 2);
        lA = lA * facA + lsA;  mA = mnA;
        lB = lB * facB + lsB;  mB = mnB;

        #pragma unroll
        for (int dt = 0; dt < 16; dt++) {
            o[dt][0] *= facA; o[dt][1] *= facA;
            o[dt][2] *= facB; o[dt][3] *= facB;
        }

        #pragma unroll
        for (int j = 0; j < 4; j++) {
            uint32_t aa[4];
            aa[0] = packh2(s[2 * j][0],     s[2 * j][1]);
            aa[1] = packh2(s[2 * j][2],     s[2 * j][3]);
            aa[2] = packh2(s[2 * j + 1][0], s[2 * j + 1][1]);
            aa[3] = packh2(s[2 * j + 1][2], s[2 * j + 1][3]);
            const uint32_t swV = (uint32_t)(((2 * j + lbit3) ^ l7) << 4);
            #pragma unroll
            for (int p = 0; p < 8; p++) {
                uint32_t b0, b1, b2, b3;
                ldsm_x4(b0, b1, b2, b3, vb + rowKV[p] + swV);
                mma_f16(o[2 * p],     aa, b0, b1);
                mma_f16(o[2 * p + 1], aa, b2, b3);
            }
        }
        __syncthreads();
    }

    float iA = 1.0f / lA, iB = 1.0f / lB;
    __half* OpA = O + (((size_t)b * S_ + ra)     * NH_ + hh) * HD_;
    __half* OpB = O + (((size_t)b * S_ + ra + 8) * NH_ + hh) * HD_;
    #pragma unroll
    for (int dt = 0; dt < 16; dt++) {
        int d = dt * 8 + tg * 2;
        *(uint32_t*)(OpA + d) = packh2(o[dt][0] * iA, o[dt][1] * iA);
        *(uint32_t*)(OpB + d) = packh2(o[dt][2] * iB, o[dt][3] * iB);
    }
}

// ---------------------------------------------------------------------------
// launch
// ---------------------------------------------------------------------------
extern "C" void kernel_launch(void* const* d_in, const int* in_sizes, int n_in,
                              void* d_out, int out_size) {
    const float* x     = (const float*)d_in[0];
    const float* freqs = (const float*)d_in[2];
    const float* w_qkv = (const float*)d_in[4];
    const float* w_fc  = (const float*)d_in[5];
    const float* w1    = (const float*)d_in[6];
    const float* w2    = (const float*)d_in[7];
    const float* w3    = (const float*)d_in[8];
    const float* anw   = (const float*)d_in[9];
    const float* fnw   = (const float*)d_in[10];
    float* out = (float*)d_out;

    float *h;
    __half *qkvh, *hnorm, *qh, *kh, *vth, *attnh, *ffh;
    __half *wqkvh, *wfch, *w1h, *w2h, *w3h;
    cudaGetSymbolAddress((void**)&qkvh,  g_qkvh);
    cudaGetSymbolAddress((void**)&h,     g_h);
    cudaGetSymbolAddress((void**)&hnorm, g_hnorm);
    cudaGetSymbolAddress((void**)&qh,    g_qh);
    cudaGetSymbolAddress((void**)&kh,    g_kh);
    cudaGetSymbolAddress((void**)&vth,   g_vth);
    cudaGetSymbolAddress((void**)&attnh, g_attnh);
    cudaGetSymbolAddress((void**)&ffh,   g_ffh);
    cudaGetSymbolAddress((void**)&wqkvh, g_wqkvh);
    cudaGetSymbolAddress((void**)&wfch,  g_wfch);
    cudaGetSymbolAddress((void**)&w1h,   g_w1h);
    cudaGetSymbolAddress((void**)&w2h,   g_w2h);
    cudaGetSymbolAddress((void**)&w3h,   g_w3h);

    static bool attr_done = false;
    if (!attr_done) {
        cudaFuncSetAttribute(tgemm_k<1>, cudaFuncAttributeMaxDynamicSharedMemorySize, GEMM_SMEM);
        cudaFuncSetAttribute(tgemm_k<2>, cudaFuncAttributeMaxDynamicSharedMemorySize, GEMM_SMEM);
        cudaFuncSetAttribute(tgemm_k<3>, cudaFuncAttributeMaxDynamicSharedMemorySize, GEMM_SMEM);
        cudaFuncSetAttribute(attn_k, cudaFuncAttributeMaxDynamicSharedMemorySize, ATT_SMEM);
        attr_done = true;
    }

    // 0. weights -> fp16 (single segmented launch, ILP-4)
    cvt_all_k<<<CVT_B4, 256>>>(w_qkv, w_fc, w1, w2, w3,
                               wqkvh, wfch, w1h, w2h, w3h);

    // 1. h_norm = half(rmsnorm(x) * attn_norm_w)
    rmsnorm_k<<<T_, 256>>>(x, anw, hnorm);
    // 2. qkv(f16) = h_norm @ w_qkv^T
    tgemm_k<3><<<dim3(QKV_N / 128, T_ / 256), 256, GEMM_SMEM>>>(hnorm, wqkvh, nullptr,
                                                                nullptr, qkvh, T_, QKV_N, E_);
    // 3. RoPE + split (half) and V transpose (half, [b][h][d][s])
    rope_split_k<<<T_, 256>>>(qkvh, freqs, qh, kh);
    vtrans_k<<<dim3(S_ / 32, HD_ / 32, B_ * NKV_), 256>>>(qkvh, vth);
    // 4. causal flash attention (fp16 mma, f32 softmax, LPT order)
    attn_k<<<dim3(S_ / 128, NH_, B_), 256, ATT_SMEM>>>(qh, kh, vth, attnh);
    // 5. h(f32) = x + attnh @ w_fc^T
    tgemm_k<1><<<dim3(E_ / 128, T_ / 256), 256, GEMM_SMEM>>>(attnh, wfch, nullptr, x,
                                                             h, T_, E_, E_);
    // 6. g = half(rmsnorm(h) * ff_norm_w)
    rmsnorm_k<<<T_, 256>>>(h, fnw, hnorm);
    // 7. ffh(f16) = silu(g @ w1^T) * (g @ w2^T)
    tgemm_k<2><<<dim3(FF_ / 64, T_ / 256), 256, GEMM_SMEM>>>(hnorm, w1h, w2h, nullptr,
                                                             ffh, T_, FF_, E_);
    // 8. out(f32) = h + ffh @ w3^T
    tgemm_k<1><<<dim3(E_ / 128, T_ / 256), 256, GEMM_SMEM>>>(ffh, w3h, nullptr, h,
                                                             out, T_, E_, FF_);
}